// round 1
// baseline (speedup 1.0000x reference)
#include <cuda_runtime.h>
#include <math.h>

// ---------------- problem dims ----------------
#define MB   8
#define SS   1024
#define HH   1536
#define NHh  8
#define HD   96
#define AHd  768
#define KK   7
#define IM   3072
#define MROWS (MB*SS)          // 8192

// ---------------- scratch (static device arrays; no allocation) ----------------
__device__ float g_q   [MROWS*AHd];
__device__ float g_k   [MROWS*AHd];
__device__ float g_v   [MROWS*AHd];
__device__ float g_co  [MROWS*AHd];
__device__ float g_dconv[MROWS*HH];
__device__ float g_sep [MROWS*AHd];       // becomes conv_attn in place
__device__ float g_ck  [MROWS*56];
__device__ float g_scores[(size_t)MB*NHh*SS*SS];   // 268 MB
__device__ float g_ctx [MROWS*HH];        // [attn ctx | conv heads]
__device__ float g_tmp [MROWS*HH];        // pre-LN gemm outputs
__device__ float g_inter[MROWS*IM];
__device__ float g_attn[MROWS*HH];
__device__ float g_layer[MROWS*HH];

// ---------------- generic SGEMM: C = A[M,K] @ W[K,N] + bias, optional exact GELU ----------------
// 128x128 tile, BK=8, 256 threads, 8x8 per thread.
__global__ void sgemm_bias(const float* __restrict__ A, const float* __restrict__ W,
                           const float* __restrict__ bias, float* __restrict__ C,
                           int M, int N, int Kd, int do_gelu) {
    __shared__ float As[8][132];
    __shared__ float Bs[8][128];
    const int tid  = threadIdx.x;
    const int bx   = blockIdx.x, by = blockIdx.y;
    const int trow = tid >> 4, tcol = tid & 15;
    float acc[8][8];
#pragma unroll
    for (int i = 0; i < 8; i++)
#pragma unroll
        for (int j = 0; j < 8; j++) acc[i][j] = 0.f;

    const int aRow = tid >> 1;
    const int aCol = (tid & 1) * 4;
    const int bRow = tid >> 5;
    const int bCol = (tid & 31) * 4;

    const float* Ap = A + (size_t)(by * 128 + aRow) * Kd + aCol;
    const float* Wp = W + (size_t)bRow * N + bx * 128 + bCol;
    const bool nOK = (bx * 128 + bCol + 3) < N;   // N is always a multiple of 4 here

    for (int k0 = 0; k0 < Kd; k0 += 8) {
        float4 av = *(const float4*)Ap;
        As[aCol + 0][aRow] = av.x;
        As[aCol + 1][aRow] = av.y;
        As[aCol + 2][aRow] = av.z;
        As[aCol + 3][aRow] = av.w;
        float4 bv = nOK ? *(const float4*)Wp : make_float4(0.f, 0.f, 0.f, 0.f);
        *(float4*)&Bs[bRow][bCol] = bv;
        __syncthreads();
#pragma unroll
        for (int kk = 0; kk < 8; kk++) {
            float ar[8], br[8];
            *(float4*)(ar)     = *(const float4*)&As[kk][trow * 8];
            *(float4*)(ar + 4) = *(const float4*)&As[kk][trow * 8 + 4];
            *(float4*)(br)     = *(const float4*)&Bs[kk][tcol * 8];
            *(float4*)(br + 4) = *(const float4*)&Bs[kk][tcol * 8 + 4];
#pragma unroll
            for (int i = 0; i < 8; i++)
#pragma unroll
                for (int j = 0; j < 8; j++) acc[i][j] += ar[i] * br[j];
        }
        __syncthreads();
        Ap += 8;
        Wp += (size_t)8 * N;
    }

    const int row0 = by * 128 + trow * 8;
    const int col0 = bx * 128 + tcol * 8;
#pragma unroll
    for (int i = 0; i < 8; i++) {
#pragma unroll
        for (int j = 0; j < 8; j++) {
            int cc = col0 + j;
            if (cc < N) {
                float x = acc[i][j] + bias[cc];
                if (do_gelu) x = 0.5f * x * (1.f + erff(x * 0.70710678118654752f));
                C[(size_t)(row0 + i) * N + cc] = x;
            }
        }
    }
}

// ---------------- depthwise conv over sequence (k=7, same pad) ----------------
__global__ void depthwise_conv(const float* __restrict__ X, const float* __restrict__ dw,
                               float* __restrict__ Y) {
    int idx = blockIdx.x * blockDim.x + threadIdx.x;
    if (idx >= MROWS * HH) return;
    int c = idx % HH;
    int s = (idx / HH) % SS;
    int b = idx / (HH * SS);
    float acc = 0.f;
#pragma unroll
    for (int k = 0; k < KK; k++) {
        int ss = s + k - 3;
        if (ss >= 0 && ss < SS)
            acc += X[((size_t)b * SS + ss) * HH + c] * dw[c * KK + k];
    }
    Y[idx] = acc;
}

// ---------------- elementwise: sep *= q  (conv_attn) ----------------
__global__ void mul_inplace(float* __restrict__ A, const float* __restrict__ B, int n) {
    int i = blockIdx.x * blockDim.x + threadIdx.x;
    if (i < n) A[i] *= B[i];
}

// ---------------- softmax over 7 kernel taps per (row, head) ----------------
__global__ void softmax7(float* __restrict__ ck) {
    int idx = blockIdx.x * blockDim.x + threadIdx.x;
    if (idx >= MROWS * NHh) return;
    int row = idx >> 3, h = idx & 7;
    float* p = ck + (size_t)row * 56 + h * 7;
    float m = p[0];
#pragma unroll
    for (int k = 1; k < 7; k++) m = fmaxf(m, p[k]);
    float e[7], s = 0.f;
#pragma unroll
    for (int k = 0; k < 7; k++) { e[k] = expf(p[k] - m); s += e[k]; }
    float inv = 1.f / s;
#pragma unroll
    for (int k = 0; k < 7; k++) p[k] = e[k] * inv;
}

// ---------------- span dynamic conv: gather co windows weighted by ck ----------------
__global__ void span_conv(const float* __restrict__ co, const float* __restrict__ ck,
                          float* __restrict__ ctx) {
    int idx = blockIdx.x * blockDim.x + threadIdx.x;
    if (idx >= MROWS * AHd) return;
    int d = idx % HD;
    int h = (idx / HD) % NHh;
    int s = (idx / AHd) % SS;
    int b = idx / (AHd * SS);
    size_t row = (size_t)b * SS + s;
    const float* w = ck + row * 56 + h * 7;
    float acc = 0.f;
#pragma unroll
    for (int k = 0; k < KK; k++) {
        int ss = s + k - 3;
        if (ss >= 0 && ss < SS)
            acc += co[((size_t)b * SS + ss) * AHd + h * HD + d] * w[k];
    }
    ctx[row * HH + AHd + h * HD + d] = acc;   // conv heads occupy cols [768,1536)
}

// ---------------- attention scores: S[b,h,q,k] = q·k / sqrt(96) ----------------
// grid (S/64 ktile, S/64 qtile, B*NH), 256 threads, 4x4 per thread, BK=32 over d=96
__global__ void attn_scores(const float* __restrict__ Q, const float* __restrict__ Kb,
                            float* __restrict__ Sc) {
    int bz = blockIdx.z;
    int b = bz >> 3, h = bz & 7;
    int qt = blockIdx.y, kt = blockIdx.x;
    __shared__ float Qs[32][68];
    __shared__ float Ks[32][68];
    int tid = threadIdx.x;
    int trow = tid >> 4, tcol = tid & 15;
    float acc[4][4];
#pragma unroll
    for (int i = 0; i < 4; i++)
#pragma unroll
        for (int j = 0; j < 4; j++) acc[i][j] = 0.f;

    const float* qbase = Q + (size_t)b * SS * AHd + h * HD;
    const float* kbase = Kb + (size_t)b * SS * AHd + h * HD;
    int lr = tid >> 2;
    int lq = (tid & 3) * 8;

    for (int d0 = 0; d0 < HD; d0 += 32) {
        const float* qp = qbase + (size_t)(qt * 64 + lr) * AHd + d0 + lq;
        float4 a0 = *(const float4*)qp;
        float4 a1 = *(const float4*)(qp + 4);
        Qs[lq + 0][lr] = a0.x; Qs[lq + 1][lr] = a0.y; Qs[lq + 2][lr] = a0.z; Qs[lq + 3][lr] = a0.w;
        Qs[lq + 4][lr] = a1.x; Qs[lq + 5][lr] = a1.y; Qs[lq + 6][lr] = a1.z; Qs[lq + 7][lr] = a1.w;
        const float* kp = kbase + (size_t)(kt * 64 + lr) * AHd + d0 + lq;
        float4 b0 = *(const float4*)kp;
        float4 b1 = *(const float4*)(kp + 4);
        Ks[lq + 0][lr] = b0.x; Ks[lq + 1][lr] = b0.y; Ks[lq + 2][lr] = b0.z; Ks[lq + 3][lr] = b0.w;
        Ks[lq + 4][lr] = b1.x; Ks[lq + 5][lr] = b1.y; Ks[lq + 6][lr] = b1.z; Ks[lq + 7][lr] = b1.w;
        __syncthreads();
#pragma unroll
        for (int dd = 0; dd < 32; dd++) {
            float ar[4], br[4];
            *(float4*)ar = *(const float4*)&Qs[dd][trow * 4];
            *(float4*)br = *(const float4*)&Ks[dd][tcol * 4];
#pragma unroll
            for (int i = 0; i < 4; i++)
#pragma unroll
                for (int j = 0; j < 4; j++) acc[i][j] += ar[i] * br[j];
        }
        __syncthreads();
    }
    const float sc = 0.10206207261596576f;  // 1/sqrt(96)
#pragma unroll
    for (int i = 0; i < 4; i++)
#pragma unroll
        for (int j = 0; j < 4; j++)
            Sc[((size_t)bz * SS + qt * 64 + trow * 4 + i) * SS + kt * 64 + tcol * 4 + j] = acc[i][j] * sc;
}

// ---------------- row softmax over 1024 keys ----------------
__global__ void softmax_rows(float* __restrict__ Sc) {
    size_t row = blockIdx.x;
    int tid = threadIdx.x;
    float4* p = (float4*)(Sc + row * SS);
    float4 v = p[tid];
    __shared__ float red[256];
    float m = fmaxf(fmaxf(v.x, v.y), fmaxf(v.z, v.w));
    red[tid] = m;
    __syncthreads();
    for (int o = 128; o > 0; o >>= 1) {
        if (tid < o) red[tid] = fmaxf(red[tid], red[tid + o]);
        __syncthreads();
    }
    m = red[0];
    __syncthreads();
    v.x = expf(v.x - m); v.y = expf(v.y - m); v.z = expf(v.z - m); v.w = expf(v.w - m);
    red[tid] = v.x + v.y + v.z + v.w;
    __syncthreads();
    for (int o = 128; o > 0; o >>= 1) {
        if (tid < o) red[tid] += red[tid + o];
        __syncthreads();
    }
    float inv = 1.f / red[0];
    v.x *= inv; v.y *= inv; v.z *= inv; v.w *= inv;
    p[tid] = v;
}

// ---------------- attention ctx: C[b,q,h,d] = sum_k P[b,h,q,k] V[b,k,h,d] ----------------
// grid (S/64 qtile, B*NH), 256 threads, BM=64 q, BN=96 d, BK=32, 4x6 per thread
__global__ void attn_ctx(const float* __restrict__ P, const float* __restrict__ V,
                         float* __restrict__ C) {
    int bz = blockIdx.y;
    int b = bz >> 3, h = bz & 7;
    int qt = blockIdx.x;
    __shared__ float Ps[32][68];
    __shared__ float Vs[32][100];
    int tid = threadIdx.x;
    int trow = tid >> 4, tcol = tid & 15;
    float acc[4][6];
#pragma unroll
    for (int i = 0; i < 4; i++)
#pragma unroll
        for (int j = 0; j < 6; j++) acc[i][j] = 0.f;

    const float* pbase = P + ((size_t)bz * SS + qt * 64) * SS;
    const float* vbase = V + (size_t)b * SS * AHd + h * HD;
    int lq = tid >> 2, lk = (tid & 3) * 8;
    int lkv = tid >> 3, ld = (tid & 7) * 12;

    for (int k0 = 0; k0 < SS; k0 += 32) {
        const float* pp = pbase + (size_t)lq * SS + k0 + lk;
        float4 p0 = *(const float4*)pp;
        float4 p1 = *(const float4*)(pp + 4);
        Ps[lk + 0][lq] = p0.x; Ps[lk + 1][lq] = p0.y; Ps[lk + 2][lq] = p0.z; Ps[lk + 3][lq] = p0.w;
        Ps[lk + 4][lq] = p1.x; Ps[lk + 5][lq] = p1.y; Ps[lk + 6][lq] = p1.z; Ps[lk + 7][lq] = p1.w;
        const float* vp = vbase + (size_t)(k0 + lkv) * AHd + ld;
        float4 v0 = *(const float4*)vp;
        float4 v1 = *(const float4*)(vp + 4);
        float4 v2 = *(const float4*)(vp + 8);
        *(float4*)&Vs[lkv][ld]     = v0;
        *(float4*)&Vs[lkv][ld + 4] = v1;
        *(float4*)&Vs[lkv][ld + 8] = v2;
        __syncthreads();
#pragma unroll
        for (int kk = 0; kk < 32; kk++) {
            float ar[4], br[6];
            *(float4*)ar = *(const float4*)&Ps[kk][trow * 4];
#pragma unroll
            for (int j = 0; j < 6; j++) br[j] = Vs[kk][tcol * 6 + j];
#pragma unroll
            for (int i = 0; i < 4; i++)
#pragma unroll
                for (int j = 0; j < 6; j++) acc[i][j] += ar[i] * br[j];
        }
        __syncthreads();
    }
#pragma unroll
    for (int i = 0; i < 4; i++)
#pragma unroll
        for (int j = 0; j < 6; j++)
            C[((size_t)b * SS + qt * 64 + trow * 4 + i) * HH + h * HD + tcol * 6 + j] = acc[i][j];
}

// ---------------- fused residual + LayerNorm over H=1536 ----------------
__global__ void ln_residual(const float* __restrict__ X, const float* __restrict__ R,
                            const float* __restrict__ gam, const float* __restrict__ bet,
                            float* __restrict__ O) {
    size_t row = blockIdx.x;
    int tid = threadIdx.x;                 // 256
    const float* x = X + row * HH;
    const float* r = R + row * HH;
    __shared__ float red[256];
    float vals[6];
    float s = 0.f;
#pragma unroll
    for (int t = 0; t < 6; t++) {
        int c = tid + t * 256;
        vals[t] = x[c] + r[c];
        s += vals[t];
    }
    red[tid] = s;
    __syncthreads();
    for (int o = 128; o > 0; o >>= 1) {
        if (tid < o) red[tid] += red[tid + o];
        __syncthreads();
    }
    float mean = red[0] * (1.f / HH);
    __syncthreads();
    float s2 = 0.f;
#pragma unroll
    for (int t = 0; t < 6; t++) {
        float d = vals[t] - mean;
        s2 += d * d;
    }
    red[tid] = s2;
    __syncthreads();
    for (int o = 128; o > 0; o >>= 1) {
        if (tid < o) red[tid] += red[tid + o];
        __syncthreads();
    }
    float rstd = rsqrtf(red[0] * (1.f / HH) + 1e-12f);
#pragma unroll
    for (int t = 0; t < 6; t++) {
        int c = tid + t * 256;
        O[row * HH + c] = (vals[t] - mean) * rstd * gam[c] + bet[c];
    }
}

// ---------------- global max-pool over S + linear decoder ----------------
__global__ void pool_decode(const float* __restrict__ L, const float* __restrict__ wd,
                            const float* __restrict__ bd, float* __restrict__ out) {
    int b = blockIdx.x;
    int tid = threadIdx.x;                 // 512
    __shared__ float red[512];
    float part = 0.f;
    for (int c = tid; c < HH; c += 512) {
        float m = -3.4e38f;
        const float* base = L + (size_t)b * SS * HH + c;
        for (int s = 0; s < SS; s++) m = fmaxf(m, base[(size_t)s * HH]);
        part += m * wd[c];
    }
    red[tid] = part;
    __syncthreads();
    for (int o = 256; o > 0; o >>= 1) {
        if (tid < o) red[tid] += red[tid + o];
        __syncthreads();
    }
    if (tid == 0) out[b] = red[0] + bd[0];
}

// ---------------- host launcher ----------------
extern "C" void kernel_launch(void* const* d_in, const int* in_sizes, int n_in,
                              void* d_out, int out_size) {
    const float* embed = (const float*)d_in[0];
    const float* wq  = (const float*)d_in[1];  const float* bq  = (const float*)d_in[2];
    const float* wk  = (const float*)d_in[3];  const float* bk  = (const float*)d_in[4];
    const float* wv  = (const float*)d_in[5];  const float* bv  = (const float*)d_in[6];
    const float* dw  = (const float*)d_in[7];
    const float* pw  = (const float*)d_in[8];  const float* sep_b = (const float*)d_in[9];
    const float* wck = (const float*)d_in[10]; const float* bck = (const float*)d_in[11];
    const float* wco = (const float*)d_in[12]; const float* bco = (const float*)d_in[13];
    const float* wso = (const float*)d_in[14]; const float* bso = (const float*)d_in[15];
    const float* ln1_g = (const float*)d_in[16]; const float* ln1_b = (const float*)d_in[17];
    const float* wi  = (const float*)d_in[18]; const float* bi  = (const float*)d_in[19];
    const float* wo  = (const float*)d_in[20]; const float* bo  = (const float*)d_in[21];
    const float* ln2_g = (const float*)d_in[22]; const float* ln2_b = (const float*)d_in[23];
    const float* wd  = (const float*)d_in[24]; const float* bd  = (const float*)d_in[25];
    float* out = (float*)d_out;

    float *q, *k, *v, *co, *dconv, *sep, *ck, *scores, *ctx, *tmp, *inter, *attn, *layer;
    cudaGetSymbolAddress((void**)&q, g_q);
    cudaGetSymbolAddress((void**)&k, g_k);
    cudaGetSymbolAddress((void**)&v, g_v);
    cudaGetSymbolAddress((void**)&co, g_co);
    cudaGetSymbolAddress((void**)&dconv, g_dconv);
    cudaGetSymbolAddress((void**)&sep, g_sep);
    cudaGetSymbolAddress((void**)&ck, g_ck);
    cudaGetSymbolAddress((void**)&scores, g_scores);
    cudaGetSymbolAddress((void**)&ctx, g_ctx);
    cudaGetSymbolAddress((void**)&tmp, g_tmp);
    cudaGetSymbolAddress((void**)&inter, g_inter);
    cudaGetSymbolAddress((void**)&attn, g_attn);
    cudaGetSymbolAddress((void**)&layer, g_layer);

    dim3 blk(256);

    // projections: q, k, v, co  (M=8192, N=768, K=1536)
    dim3 gproj(AHd / 128, MROWS / 128);
    sgemm_bias<<<gproj, blk>>>(embed, wq, bq, q, MROWS, AHd, HH, 0);
    sgemm_bias<<<gproj, blk>>>(embed, wk, bk, k, MROWS, AHd, HH, 0);
    sgemm_bias<<<gproj, blk>>>(embed, wv, bv, v, MROWS, AHd, HH, 0);
    sgemm_bias<<<gproj, blk>>>(embed, wco, bco, co, MROWS, AHd, HH, 0);

    // separable conv: depthwise then pointwise
    depthwise_conv<<<(MROWS * HH + 255) / 256, blk>>>(embed, dw, dconv);
    sgemm_bias<<<gproj, blk>>>(dconv, pw, sep_b, sep, MROWS, AHd, HH, 0);

    // conv_attn = sep * q
    mul_inplace<<<(MROWS * AHd + 255) / 256, blk>>>(sep, q, MROWS * AHd);

    // span kernels: ck = softmax(conv_attn @ wck + bck) over 7 taps
    dim3 gck(1, MROWS / 128);
    sgemm_bias<<<gck, blk>>>(sep, wck, bck, ck, MROWS, 56, AHd, 0);
    softmax7<<<(MROWS * NHh + 255) / 256, blk>>>(ck);

    // conv heads -> ctx[:, 768:1536]
    span_conv<<<(MROWS * AHd + 255) / 256, blk>>>(co, ck, ctx);

    // self-attention -> ctx[:, 0:768]
    dim3 gsc(SS / 64, SS / 64, MB * NHh);
    attn_scores<<<gsc, blk>>>(q, k, scores);
    softmax_rows<<<MB * NHh * SS, blk>>>(scores);
    dim3 gcx(SS / 64, MB * NHh);
    attn_ctx<<<gcx, blk>>>(scores, v, ctx);

    // self output + LN1
    dim3 gso(HH / 128, MROWS / 128);
    sgemm_bias<<<gso, blk>>>(ctx, wso, bso, tmp, MROWS, HH, HH, 0);
    ln_residual<<<MROWS, blk>>>(tmp, embed, ln1_g, ln1_b, attn);

    // FFN
    dim3 gin(IM / 128, MROWS / 128);
    sgemm_bias<<<gin, blk>>>(attn, wi, bi, inter, MROWS, IM, HH, 1);
    sgemm_bias<<<gso, blk>>>(inter, wo, bo, tmp, MROWS, HH, IM, 0);
    ln_residual<<<MROWS, blk>>>(tmp, attn, ln2_g, ln2_b, layer);

    // pool + decode
    pool_decode<<<MB, dim3(512)>>>(layer, wd, bd, out);
}

// round 3
// speedup vs baseline: 2.3004x; 2.3004x over previous
#include <cuda_runtime.h>
#include <math.h>
#include <stdint.h>

// ---------------- problem dims ----------------
#define MB   8
#define SS   1024
#define HH   1536
#define NHh  8
#define HD   96
#define AHd  768
#define KK   7
#define IM   3072
#define MROWS (MB*SS)          // 8192

// ---------------- scratch (static device arrays; no allocation) ----------------
__device__ float g_q   [MROWS*AHd];
__device__ float g_k   [MROWS*AHd];
__device__ float g_v   [MROWS*AHd];
__device__ float g_co  [MROWS*AHd];
__device__ float g_dconv[MROWS*HH];
__device__ float g_sep [MROWS*AHd];       // becomes conv_attn in place
__device__ float g_ck  [MROWS*56];
__device__ float g_scores[(size_t)MB*NHh*SS*SS];   // 268 MB
__device__ float g_ctx [MROWS*HH];        // [attn ctx | conv heads]
__device__ float g_tmp [MROWS*HH];        // pre-LN gemm outputs
__device__ float g_inter[MROWS*IM];
__device__ float g_attn[MROWS*HH];
__device__ float g_layer[MROWS*HH];
__device__ float g_pool[MB*HH];

// ============================================================================
// tf32 mma.sync GEMM: C[M,N] = A[M,K] @ W[K,N] + bias, optional exact GELU
// BM=128, BN=128, BK=16, 256 threads (8 warps, 2x4), warp tile 64x32.
// A stored to SMEM transposed [k][m]; B native [k][n]. Row stride 136 words
// makes fragment loads bank-conflict-free (136 mod 32 == 8).
// ============================================================================
__device__ __forceinline__ uint32_t f2tf32(float x) {
    uint32_t u;
    asm("cvt.rna.tf32.f32 %0, %1;" : "=r"(u) : "f"(x));
    return u;
}

__device__ __forceinline__ void mma_tf32(float* d, const uint32_t* a, const uint32_t* b) {
    asm volatile(
        "mma.sync.aligned.m16n8k8.row.col.f32.tf32.tf32.f32 "
        "{%0,%1,%2,%3}, {%4,%5,%6,%7}, {%8,%9}, {%0,%1,%2,%3};"
        : "+f"(d[0]), "+f"(d[1]), "+f"(d[2]), "+f"(d[3])
        : "r"(a[0]), "r"(a[1]), "r"(a[2]), "r"(a[3]), "r"(b[0]), "r"(b[1]));
}

#define SROW 136

__global__ void __launch_bounds__(256) mma_gemm(
    const float* __restrict__ A, const float* __restrict__ W,
    const float* __restrict__ bias, float* __restrict__ C,
    int M, int N, int Kd, int do_gelu)
{
    __shared__ uint32_t As[2][16][SROW];
    __shared__ uint32_t Bs[2][16][SROW];

    const int tid  = threadIdx.x;
    const int wid  = tid >> 5, lane = tid & 31;
    const int wr   = wid >> 2, wc = wid & 3;        // warp grid 2 x 4
    const int g    = lane >> 2, tg = lane & 3;      // groupID, thread-in-group
    const int m0   = blockIdx.y * 128, n0 = blockIdx.x * 128;

    // loader mapping
    const int aRow = tid >> 1;             // 0..127
    const int aK   = (tid & 1) * 8;        // 0 or 8
    const int bK   = tid >> 4;             // 0..15
    const int bN   = (tid & 15) * 8;       // 0..120

    const float* Ap = A + (size_t)(m0 + aRow) * Kd + aK;
    const float* Wp = W + (size_t)bK * N + n0 + bN;

    float acc[4][4][4];
#pragma unroll
    for (int i = 0; i < 4; i++)
#pragma unroll
        for (int j = 0; j < 4; j++)
#pragma unroll
            for (int c = 0; c < 4; c++) acc[i][j][c] = 0.f;

    const int nkb = Kd >> 4;

    // prefetch tile 0
    float4 pa0 = *(const float4*)(Ap);
    float4 pa1 = *(const float4*)(Ap + 4);
    float4 pb0 = *(const float4*)(Wp);
    float4 pb1 = *(const float4*)(Wp + 4);

    for (int kb = 0; kb < nkb; kb++) {
        const int buf = kb & 1;
        // store prefetched tile (with tf32 conversion)
        As[buf][aK + 0][aRow] = f2tf32(pa0.x);
        As[buf][aK + 1][aRow] = f2tf32(pa0.y);
        As[buf][aK + 2][aRow] = f2tf32(pa0.z);
        As[buf][aK + 3][aRow] = f2tf32(pa0.w);
        As[buf][aK + 4][aRow] = f2tf32(pa1.x);
        As[buf][aK + 5][aRow] = f2tf32(pa1.y);
        As[buf][aK + 6][aRow] = f2tf32(pa1.z);
        As[buf][aK + 7][aRow] = f2tf32(pa1.w);
        Bs[buf][bK][bN + 0] = f2tf32(pb0.x);
        Bs[buf][bK][bN + 1] = f2tf32(pb0.y);
        Bs[buf][bK][bN + 2] = f2tf32(pb0.z);
        Bs[buf][bK][bN + 3] = f2tf32(pb0.w);
        Bs[buf][bK][bN + 4] = f2tf32(pb1.x);
        Bs[buf][bK][bN + 5] = f2tf32(pb1.y);
        Bs[buf][bK][bN + 6] = f2tf32(pb1.z);
        Bs[buf][bK][bN + 7] = f2tf32(pb1.w);
        __syncthreads();

        // prefetch next tile
        if (kb + 1 < nkb) {
            const float* Ap2 = Ap + (kb + 1) * 16;
            const float* Wp2 = Wp + (size_t)(kb + 1) * 16 * N;
            pa0 = *(const float4*)(Ap2);
            pa1 = *(const float4*)(Ap2 + 4);
            pb0 = *(const float4*)(Wp2);
            pb1 = *(const float4*)(Wp2 + 4);
        }

        // compute: two k=8 slices
#pragma unroll
        for (int kk = 0; kk < 16; kk += 8) {
            uint32_t af[4][4];
#pragma unroll
            for (int mt = 0; mt < 4; mt++) {
                int mb = wr * 64 + mt * 16 + g;
                af[mt][0] = As[buf][kk + tg][mb];
                af[mt][1] = As[buf][kk + tg][mb + 8];
                af[mt][2] = As[buf][kk + tg + 4][mb];
                af[mt][3] = As[buf][kk + tg + 4][mb + 8];
            }
            uint32_t bf[4][2];
#pragma unroll
            for (int nt = 0; nt < 4; nt++) {
                int nb = wc * 32 + nt * 8 + g;
                bf[nt][0] = Bs[buf][kk + tg][nb];
                bf[nt][1] = Bs[buf][kk + tg + 4][nb];
            }
#pragma unroll
            for (int mt = 0; mt < 4; mt++)
#pragma unroll
                for (int nt = 0; nt < 4; nt++)
                    mma_tf32(acc[mt][nt], af[mt], bf[nt]);
        }
    }

    // epilogue
#pragma unroll
    for (int mt = 0; mt < 4; mt++) {
#pragma unroll
        for (int nt = 0; nt < 4; nt++) {
            int row = m0 + wr * 64 + mt * 16 + g;
            int col = n0 + wc * 32 + nt * 8 + 2 * tg;
            float b0 = bias[col], b1 = bias[col + 1];
            float v0 = acc[mt][nt][0] + b0;
            float v1 = acc[mt][nt][1] + b1;
            float v2 = acc[mt][nt][2] + b0;
            float v3 = acc[mt][nt][3] + b1;
            if (do_gelu) {
                v0 = 0.5f * v0 * (1.f + erff(v0 * 0.70710678118654752f));
                v1 = 0.5f * v1 * (1.f + erff(v1 * 0.70710678118654752f));
                v2 = 0.5f * v2 * (1.f + erff(v2 * 0.70710678118654752f));
                v3 = 0.5f * v3 * (1.f + erff(v3 * 0.70710678118654752f));
            }
            *(float2*)(C + (size_t)row * N + col)       = make_float2(v0, v1);
            *(float2*)(C + (size_t)(row + 8) * N + col) = make_float2(v2, v3);
        }
    }
}

// ---------------- small SIMT SGEMM (only for ck: N=56) ----------------
__global__ void sgemm_bias(const float* __restrict__ A, const float* __restrict__ W,
                           const float* __restrict__ bias, float* __restrict__ C,
                           int M, int N, int Kd, int do_gelu) {
    __shared__ float As[8][132];
    __shared__ float Bs[8][128];
    const int tid  = threadIdx.x;
    const int bx   = blockIdx.x, by = blockIdx.y;
    const int trow = tid >> 4, tcol = tid & 15;
    float acc[8][8];
#pragma unroll
    for (int i = 0; i < 8; i++)
#pragma unroll
        for (int j = 0; j < 8; j++) acc[i][j] = 0.f;

    const int aRow = tid >> 1;
    const int aCol = (tid & 1) * 4;
    const int bRow = tid >> 5;
    const int bCol = (tid & 31) * 4;

    const float* Ap = A + (size_t)(by * 128 + aRow) * Kd + aCol;
    const float* Wp = W + (size_t)bRow * N + bx * 128 + bCol;
    const bool nOK = (bx * 128 + bCol + 3) < N;

    for (int k0 = 0; k0 < Kd; k0 += 8) {
        float4 av = *(const float4*)Ap;
        As[aCol + 0][aRow] = av.x;
        As[aCol + 1][aRow] = av.y;
        As[aCol + 2][aRow] = av.z;
        As[aCol + 3][aRow] = av.w;
        float4 bv = nOK ? *(const float4*)Wp : make_float4(0.f, 0.f, 0.f, 0.f);
        *(float4*)&Bs[bRow][bCol] = bv;
        __syncthreads();
#pragma unroll
        for (int kk = 0; kk < 8; kk++) {
            float ar[8], br[8];
            *(float4*)(ar)     = *(const float4*)&As[kk][trow * 8];
            *(float4*)(ar + 4) = *(const float4*)&As[kk][trow * 8 + 4];
            *(float4*)(br)     = *(const float4*)&Bs[kk][tcol * 8];
            *(float4*)(br + 4) = *(const float4*)&Bs[kk][tcol * 8 + 4];
#pragma unroll
            for (int i = 0; i < 8; i++)
#pragma unroll
                for (int j = 0; j < 8; j++) acc[i][j] += ar[i] * br[j];
        }
        __syncthreads();
        Ap += 8;
        Wp += (size_t)8 * N;
    }

    const int row0 = by * 128 + trow * 8;
    const int col0 = bx * 128 + tcol * 8;
#pragma unroll
    for (int i = 0; i < 8; i++) {
#pragma unroll
        for (int j = 0; j < 8; j++) {
            int cc = col0 + j;
            if (cc < N) {
                float x = acc[i][j] + bias[cc];
                if (do_gelu) x = 0.5f * x * (1.f + erff(x * 0.70710678118654752f));
                C[(size_t)(row0 + i) * N + cc] = x;
            }
        }
    }
}

// ---------------- depthwise conv over sequence (k=7, same pad) ----------------
__global__ void depthwise_conv(const float* __restrict__ X, const float* __restrict__ dw,
                               float* __restrict__ Y) {
    int idx = blockIdx.x * blockDim.x + threadIdx.x;
    if (idx >= MROWS * HH) return;
    int c = idx % HH;
    int s = (idx / HH) % SS;
    int b = idx / (HH * SS);
    float acc = 0.f;
#pragma unroll
    for (int k = 0; k < KK; k++) {
        int ss = s + k - 3;
        if (ss >= 0 && ss < SS)
            acc += X[((size_t)b * SS + ss) * HH + c] * dw[c * KK + k];
    }
    Y[idx] = acc;
}

__global__ void mul_inplace(float* __restrict__ A, const float* __restrict__ B, int n) {
    int i = blockIdx.x * blockDim.x + threadIdx.x;
    if (i < n) A[i] *= B[i];
}

__global__ void softmax7(float* __restrict__ ck) {
    int idx = blockIdx.x * blockDim.x + threadIdx.x;
    if (idx >= MROWS * NHh) return;
    int row = idx >> 3, h = idx & 7;
    float* p = ck + (size_t)row * 56 + h * 7;
    float m = p[0];
#pragma unroll
    for (int k = 1; k < 7; k++) m = fmaxf(m, p[k]);
    float e[7], s = 0.f;
#pragma unroll
    for (int k = 0; k < 7; k++) { e[k] = expf(p[k] - m); s += e[k]; }
    float inv = 1.f / s;
#pragma unroll
    for (int k = 0; k < 7; k++) p[k] = e[k] * inv;
}

__global__ void span_conv(const float* __restrict__ co, const float* __restrict__ ck,
                          float* __restrict__ ctx) {
    int idx = blockIdx.x * blockDim.x + threadIdx.x;
    if (idx >= MROWS * AHd) return;
    int d = idx % HD;
    int h = (idx / HD) % NHh;
    int s = (idx / AHd) % SS;
    int b = idx / (AHd * SS);
    size_t row = (size_t)b * SS + s;
    const float* w = ck + row * 56 + h * 7;
    float acc = 0.f;
#pragma unroll
    for (int k = 0; k < KK; k++) {
        int ss = s + k - 3;
        if (ss >= 0 && ss < SS)
            acc += co[((size_t)b * SS + ss) * AHd + h * HD + d] * w[k];
    }
    ctx[row * HH + AHd + h * HD + d] = acc;
}

// ---------------- attention scores ----------------
__global__ void attn_scores(const float* __restrict__ Q, const float* __restrict__ Kb,
                            float* __restrict__ Sc) {
    int bz = blockIdx.z;
    int b = bz >> 3, h = bz & 7;
    int qt = blockIdx.y, kt = blockIdx.x;
    __shared__ float Qs[32][68];
    __shared__ float Ks[32][68];
    int tid = threadIdx.x;
    int trow = tid >> 4, tcol = tid & 15;
    float acc[4][4];
#pragma unroll
    for (int i = 0; i < 4; i++)
#pragma unroll
        for (int j = 0; j < 4; j++) acc[i][j] = 0.f;

    const float* qbase = Q + (size_t)b * SS * AHd + h * HD;
    const float* kbase = Kb + (size_t)b * SS * AHd + h * HD;
    int lr = tid >> 2;
    int lq = (tid & 3) * 8;

    for (int d0 = 0; d0 < HD; d0 += 32) {
        const float* qp = qbase + (size_t)(qt * 64 + lr) * AHd + d0 + lq;
        float4 a0 = *(const float4*)qp;
        float4 a1 = *(const float4*)(qp + 4);
        Qs[lq + 0][lr] = a0.x; Qs[lq + 1][lr] = a0.y; Qs[lq + 2][lr] = a0.z; Qs[lq + 3][lr] = a0.w;
        Qs[lq + 4][lr] = a1.x; Qs[lq + 5][lr] = a1.y; Qs[lq + 6][lr] = a1.z; Qs[lq + 7][lr] = a1.w;
        const float* kp = kbase + (size_t)(kt * 64 + lr) * AHd + d0 + lq;
        float4 b0 = *(const float4*)kp;
        float4 b1 = *(const float4*)(kp + 4);
        Ks[lq + 0][lr] = b0.x; Ks[lq + 1][lr] = b0.y; Ks[lq + 2][lr] = b0.z; Ks[lq + 3][lr] = b0.w;
        Ks[lq + 4][lr] = b1.x; Ks[lq + 5][lr] = b1.y; Ks[lq + 6][lr] = b1.z; Ks[lq + 7][lr] = b1.w;
        __syncthreads();
#pragma unroll
        for (int dd = 0; dd < 32; dd++) {
            float ar[4], br[4];
            *(float4*)ar = *(const float4*)&Qs[dd][trow * 4];
            *(float4*)br = *(const float4*)&Ks[dd][tcol * 4];
#pragma unroll
            for (int i = 0; i < 4; i++)
#pragma unroll
                for (int j = 0; j < 4; j++) acc[i][j] += ar[i] * br[j];
        }
        __syncthreads();
    }
    const float sc = 0.10206207261596576f;
#pragma unroll
    for (int i = 0; i < 4; i++)
#pragma unroll
        for (int j = 0; j < 4; j++)
            Sc[((size_t)bz * SS + qt * 64 + trow * 4 + i) * SS + kt * 64 + tcol * 4 + j] = acc[i][j] * sc;
}

__global__ void softmax_rows(float* __restrict__ Sc) {
    size_t row = blockIdx.x;
    int tid = threadIdx.x;
    float4* p = (float4*)(Sc + row * SS);
    float4 v = p[tid];
    __shared__ float red[256];
    float m = fmaxf(fmaxf(v.x, v.y), fmaxf(v.z, v.w));
    red[tid] = m;
    __syncthreads();
    for (int o = 128; o > 0; o >>= 1) {
        if (tid < o) red[tid] = fmaxf(red[tid], red[tid + o]);
        __syncthreads();
    }
    m = red[0];
    __syncthreads();
    v.x = expf(v.x - m); v.y = expf(v.y - m); v.z = expf(v.z - m); v.w = expf(v.w - m);
    red[tid] = v.x + v.y + v.z + v.w;
    __syncthreads();
    for (int o = 128; o > 0; o >>= 1) {
        if (tid < o) red[tid] += red[tid + o];
        __syncthreads();
    }
    float inv = 1.f / red[0];
    v.x *= inv; v.y *= inv; v.z *= inv; v.w *= inv;
    p[tid] = v;
}

__global__ void attn_ctx(const float* __restrict__ P, const float* __restrict__ V,
                         float* __restrict__ C) {
    int bz = blockIdx.y;
    int b = bz >> 3, h = bz & 7;
    int qt = blockIdx.x;
    __shared__ float Ps[32][68];
    __shared__ float Vs[32][100];
    int tid = threadIdx.x;
    int trow = tid >> 4, tcol = tid & 15;
    float acc[4][6];
#pragma unroll
    for (int i = 0; i < 4; i++)
#pragma unroll
        for (int j = 0; j < 6; j++) acc[i][j] = 0.f;

    const float* pbase = P + ((size_t)bz * SS + qt * 64) * SS;
    const float* vbase = V + (size_t)b * SS * AHd + h * HD;
    int lq = tid >> 2, lk = (tid & 3) * 8;
    int lkv = tid >> 3, ld = (tid & 7) * 12;

    for (int k0 = 0; k0 < SS; k0 += 32) {
        const float* pp = pbase + (size_t)lq * SS + k0 + lk;
        float4 p0 = *(const float4*)pp;
        float4 p1 = *(const float4*)(pp + 4);
        Ps[lk + 0][lq] = p0.x; Ps[lk + 1][lq] = p0.y; Ps[lk + 2][lq] = p0.z; Ps[lk + 3][lq] = p0.w;
        Ps[lk + 4][lq] = p1.x; Ps[lk + 5][lq] = p1.y; Ps[lk + 6][lq] = p1.z; Ps[lk + 7][lq] = p1.w;
        const float* vp = vbase + (size_t)(k0 + lkv) * AHd + ld;
        float4 v0 = *(const float4*)vp;
        float4 v1 = *(const float4*)(vp + 4);
        float4 v2 = *(const float4*)(vp + 8);
        *(float4*)&Vs[lkv][ld]     = v0;
        *(float4*)&Vs[lkv][ld + 4] = v1;
        *(float4*)&Vs[lkv][ld + 8] = v2;
        __syncthreads();
#pragma unroll
        for (int kk = 0; kk < 32; kk++) {
            float ar[4], br[6];
            *(float4*)ar = *(const float4*)&Ps[kk][trow * 4];
#pragma unroll
            for (int j = 0; j < 6; j++) br[j] = Vs[kk][tcol * 6 + j];
#pragma unroll
            for (int i = 0; i < 4; i++)
#pragma unroll
                for (int j = 0; j < 6; j++) acc[i][j] += ar[i] * br[j];
        }
        __syncthreads();
    }
#pragma unroll
    for (int i = 0; i < 4; i++)
#pragma unroll
        for (int j = 0; j < 6; j++)
            C[((size_t)b * SS + qt * 64 + trow * 4 + i) * HH + h * HD + tcol * 6 + j] = acc[i][j];
}

// ---------------- fused residual + LayerNorm over H=1536 ----------------
__global__ void ln_residual(const float* __restrict__ X, const float* __restrict__ R,
                            const float* __restrict__ gam, const float* __restrict__ bet,
                            float* __restrict__ O) {
    size_t row = blockIdx.x;
    int tid = threadIdx.x;
    const float* x = X + row * HH;
    const float* r = R + row * HH;
    __shared__ float red[256];
    float vals[6];
    float s = 0.f;
#pragma unroll
    for (int t = 0; t < 6; t++) {
        int c = tid + t * 256;
        vals[t] = x[c] + r[c];
        s += vals[t];
    }
    red[tid] = s;
    __syncthreads();
    for (int o = 128; o > 0; o >>= 1) {
        if (tid < o) red[tid] += red[tid + o];
        __syncthreads();
    }
    float mean = red[0] * (1.f / HH);
    __syncthreads();
    float s2 = 0.f;
#pragma unroll
    for (int t = 0; t < 6; t++) {
        float d = vals[t] - mean;
        s2 += d * d;
    }
    red[tid] = s2;
    __syncthreads();
    for (int o = 128; o > 0; o >>= 1) {
        if (tid < o) red[tid] += red[tid + o];
        __syncthreads();
    }
    float rstd = rsqrtf(red[0] * (1.f / HH) + 1e-12f);
#pragma unroll
    for (int t = 0; t < 6; t++) {
        int c = tid + t * 256;
        O[row * HH + c] = (vals[t] - mean) * rstd * gam[c] + bet[c];
    }
}

// ---------------- global max-pool (parallel over channels) + decoder ----------------
__global__ void maxpool_seq(const float* __restrict__ L, float* __restrict__ pooled) {
    int idx = blockIdx.x * blockDim.x + threadIdx.x;   // b*HH + c
    if (idx >= MB * HH) return;
    int c = idx % HH, b = idx / HH;
    const float* base = L + (size_t)b * SS * HH + c;
    float m = -3.4e38f;
    for (int s = 0; s < SS; s++) m = fmaxf(m, base[(size_t)s * HH]);
    pooled[idx] = m;
}

__global__ void decode(const float* __restrict__ pooled, const float* __restrict__ wd,
                       const float* __restrict__ bd, float* __restrict__ out) {
    int b = blockIdx.x;
    int tid = threadIdx.x;   // 256
    __shared__ float red[256];
    float part = 0.f;
    for (int c = tid; c < HH; c += 256) part += pooled[b * HH + c] * wd[c];
    red[tid] = part;
    __syncthreads();
    for (int o = 128; o > 0; o >>= 1) {
        if (tid < o) red[tid] += red[tid + o];
        __syncthreads();
    }
    if (tid == 0) out[b] = red[0] + bd[0];
}

// ============================================================================
// Host launcher
// ============================================================================
extern "C" void kernel_launch(void* const* d_in, const int* in_sizes, int n_in,
                              void* d_out, int out_size) {
    const float* embed = (const float*)d_in[0];
    const float* wq  = (const float*)d_in[1];  const float* bq  = (const float*)d_in[2];
    const float* wk  = (const float*)d_in[3];  const float* bk  = (const float*)d_in[4];
    const float* wv  = (const float*)d_in[5];  const float* bv  = (const float*)d_in[6];
    const float* dw  = (const float*)d_in[7];
    const float* pw  = (const float*)d_in[8];  const float* sep_b = (const float*)d_in[9];
    const float* wck = (const float*)d_in[10]; const float* bck = (const float*)d_in[11];
    const float* wco = (const float*)d_in[12]; const float* bco = (const float*)d_in[13];
    const float* wso = (const float*)d_in[14]; const float* bso = (const float*)d_in[15];
    const float* ln1_g = (const float*)d_in[16]; const float* ln1_b = (const float*)d_in[17];
    const float* wi  = (const float*)d_in[18]; const float* bi  = (const float*)d_in[19];
    const float* wo  = (const float*)d_in[20]; const float* bo  = (const float*)d_in[21];
    const float* ln2_g = (const float*)d_in[22]; const float* ln2_b = (const float*)d_in[23];
    const float* wd  = (const float*)d_in[24]; const float* bd  = (const float*)d_in[25];
    float* out = (float*)d_out;

    float *q, *k, *v, *co, *dconv, *sep, *ck, *scores, *ctx, *tmp, *inter, *attn, *layer, *pool;
    cudaGetSymbolAddress((void**)&q, g_q);
    cudaGetSymbolAddress((void**)&k, g_k);
    cudaGetSymbolAddress((void**)&v, g_v);
    cudaGetSymbolAddress((void**)&co, g_co);
    cudaGetSymbolAddress((void**)&dconv, g_dconv);
    cudaGetSymbolAddress((void**)&sep, g_sep);
    cudaGetSymbolAddress((void**)&ck, g_ck);
    cudaGetSymbolAddress((void**)&scores, g_scores);
    cudaGetSymbolAddress((void**)&ctx, g_ctx);
    cudaGetSymbolAddress((void**)&tmp, g_tmp);
    cudaGetSymbolAddress((void**)&inter, g_inter);
    cudaGetSymbolAddress((void**)&attn, g_attn);
    cudaGetSymbolAddress((void**)&layer, g_layer);
    cudaGetSymbolAddress((void**)&pool, g_pool);

    dim3 blk(256);

    // ---- projections on mma.sync tensor path ----
    dim3 gproj(AHd / 128, MROWS / 128);
    mma_gemm<<<gproj, blk>>>(embed, wq,  bq,  q,  MROWS, AHd, HH, 0);
    mma_gemm<<<gproj, blk>>>(embed, wk,  bk,  k,  MROWS, AHd, HH, 0);
    mma_gemm<<<gproj, blk>>>(embed, wv,  bv,  v,  MROWS, AHd, HH, 0);
    mma_gemm<<<gproj, blk>>>(embed, wco, bco, co, MROWS, AHd, HH, 0);

    // ---- separable conv ----
    depthwise_conv<<<(MROWS * HH + 255) / 256, blk>>>(embed, dw, dconv);
    mma_gemm<<<gproj, blk>>>(dconv, pw, sep_b, sep, MROWS, AHd, HH, 0);

    // conv_attn = sep * q
    mul_inplace<<<(MROWS * AHd + 255) / 256, blk>>>(sep, q, MROWS * AHd);

    // span kernels (N=56 -> SIMT gemm)
    dim3 gck(1, MROWS / 128);
    sgemm_bias<<<gck, blk>>>(sep, wck, bck, ck, MROWS, 56, AHd, 0);
    softmax7<<<(MROWS * NHh + 255) / 256, blk>>>(ck);
    span_conv<<<(MROWS * AHd + 255) / 256, blk>>>(co, ck, ctx);

    // ---- self-attention ----
    dim3 gsc(SS / 64, SS / 64, MB * NHh);
    attn_scores<<<gsc, blk>>>(q, k, scores);
    softmax_rows<<<MB * NHh * SS, blk>>>(scores);
    dim3 gcx(SS / 64, MB * NHh);
    attn_ctx<<<gcx, blk>>>(scores, v, ctx);

    // ---- self output + LN1 ----
    dim3 gso(HH / 128, MROWS / 128);
    mma_gemm<<<gso, blk>>>(ctx, wso, bso, tmp, MROWS, HH, HH, 0);
    ln_residual<<<MROWS, blk>>>(tmp, embed, ln1_g, ln1_b, attn);

    // ---- FFN ----
    dim3 gin(IM / 128, MROWS / 128);
    mma_gemm<<<gin, blk>>>(attn, wi, bi, inter, MROWS, IM, HH, 1);
    mma_gemm<<<gso, blk>>>(inter, wo, bo, tmp, MROWS, HH, IM, 0);
    ln_residual<<<MROWS, blk>>>(tmp, attn, ln2_g, ln2_b, layer);

    // ---- pool + decode ----
    maxpool_seq<<<(MB * HH + 255) / 256, blk>>>(layer, pool);
    decode<<<MB, blk>>>(pool, wd, bd, out);
}

// round 4
// speedup vs baseline: 3.2507x; 1.4131x over previous
#include <cuda_runtime.h>
#include <math.h>
#include <stdint.h>

// ---------------- problem dims ----------------
#define MB   8
#define SS   1024
#define HH   1536
#define NHh  8
#define HD   96
#define AHd  768
#define KK   7
#define IM   3072
#define MROWS (MB*SS)          // 8192

// ---------------- scratch (static device arrays; no allocation) ----------------
__device__ float g_q   [MROWS*AHd];
__device__ float g_k   [MROWS*AHd];
__device__ float g_v   [MROWS*AHd];
__device__ float g_co  [MROWS*AHd];
__device__ float g_dconv[MROWS*HH];
__device__ float g_sep [MROWS*AHd];
__device__ float g_ck  [MROWS*56];
__device__ float g_scores[(size_t)MB*NHh*SS*SS];   // 268 MB
__device__ float g_ctx [MROWS*HH];
__device__ float g_tmp [MROWS*HH];
__device__ float g_inter[MROWS*IM];
__device__ float g_attn[MROWS*HH];
__device__ float g_layer[MROWS*HH];
__device__ float g_pool[MB*HH];

// ---------------- PTX helpers ----------------
__device__ __forceinline__ uint32_t sptr(const void* p) {
    return (uint32_t)__cvta_generic_to_shared(p);
}
#define CP16(dst, src) \
    asm volatile("cp.async.cg.shared.global [%0], [%1], 16;" :: "r"(dst), "l"(src))
#define CP_COMMIT() asm volatile("cp.async.commit_group;" ::: "memory")
#define CP_WAIT(n)  asm volatile("cp.async.wait_group %0;" :: "n"(n) : "memory")

__device__ __forceinline__ void mma_tf32(float* d, const uint32_t* a, const uint32_t* b) {
    asm volatile(
        "mma.sync.aligned.m16n8k8.row.col.f32.tf32.tf32.f32 "
        "{%0,%1,%2,%3}, {%4,%5,%6,%7}, {%8,%9}, {%0,%1,%2,%3};"
        : "+f"(d[0]), "+f"(d[1]), "+f"(d[2]), "+f"(d[3])
        : "r"(a[0]), "r"(a[1]), "r"(a[2]), "r"(a[3]), "r"(b[0]), "r"(b[1]));
}

// ============================================================================
// tf32 mma GEMM with cp.async pipeline.
// C[M,N] = A[M,K] @ W[K,N] + bias, optional exact GELU.
// BM=128, BN=128, BK=32, 3 stages, 256 threads (8 warps 2x4, warp 64x32).
// A tile [m][k] pitch 36 (banks 4g+tg distinct); B tile [k][n] pitch 136
// (banks 8tg+g distinct).
// ============================================================================
#define PA   36
#define PB   136
#define ASZ  (128*PA)
#define BSZ  (32*PB)
#define NSTG 3
#define GEMM_SMEM (NSTG*(ASZ+BSZ)*4)

__global__ void __launch_bounds__(256) mma_gemm(
    const float* __restrict__ A, const float* __restrict__ W,
    const float* __restrict__ bias, float* __restrict__ C,
    int N, int Kd, int do_gelu)
{
    extern __shared__ float sm[];
    float* Abase = sm;
    float* Bbase = sm + NSTG * ASZ;

    const int tid = threadIdx.x;
    const int wid = tid >> 5, lane = tid & 31;
    const int wr = wid >> 2, wc = wid & 3;
    const int g = lane >> 2, tg = lane & 3;
    const int m0 = blockIdx.y * 128, n0 = blockIdx.x * 128;
    const int nkb = Kd >> 5;

    float acc[4][4][4];
#pragma unroll
    for (int i = 0; i < 4; i++)
#pragma unroll
        for (int j = 0; j < 4; j++)
#pragma unroll
            for (int c = 0; c < 4; c++) acc[i][j][c] = 0.f;

    auto issue = [&](int kb) {
        int s = kb % NSTG;
        float* As = Abase + s * ASZ;
        float* Bs = Bbase + s * BSZ;
        const float* ag = A + (size_t)m0 * Kd + kb * 32;
        const float* bg = W + (size_t)(kb * 32) * N + n0;
#pragma unroll
        for (int t = 0; t < 4; t++) {
            int sA = tid + t * 256;
            int r  = sA >> 3,  c  = (sA & 7) << 2;
            CP16(sptr(As + r * PA + c), ag + (size_t)r * Kd + c);
            int rb = sA >> 5,  cb = (sA & 31) << 2;
            CP16(sptr(Bs + rb * PB + cb), bg + (size_t)rb * N + cb);
        }
    };

    issue(0); CP_COMMIT();
    issue(1); CP_COMMIT();

    for (int kb = 0; kb < nkb; kb++) {
        CP_WAIT(1);
        __syncthreads();
        int s = kb % NSTG;
        const uint32_t* As = (const uint32_t*)(Abase + s * ASZ);
        const uint32_t* Bs = (const uint32_t*)(Bbase + s * BSZ);
#pragma unroll
        for (int kk = 0; kk < 32; kk += 8) {
            uint32_t af[4][4], bf[4][2];
#pragma unroll
            for (int mt = 0; mt < 4; mt++) {
                int mb = wr * 64 + mt * 16 + g;
                af[mt][0] = As[mb * PA + kk + tg];
                af[mt][1] = As[(mb + 8) * PA + kk + tg];
                af[mt][2] = As[mb * PA + kk + tg + 4];
                af[mt][3] = As[(mb + 8) * PA + kk + tg + 4];
            }
#pragma unroll
            for (int nt = 0; nt < 4; nt++) {
                int nb = wc * 32 + nt * 8 + g;
                bf[nt][0] = Bs[(kk + tg) * PB + nb];
                bf[nt][1] = Bs[(kk + tg + 4) * PB + nb];
            }
#pragma unroll
            for (int mt = 0; mt < 4; mt++)
#pragma unroll
                for (int nt = 0; nt < 4; nt++)
                    mma_tf32(acc[mt][nt], af[mt], bf[nt]);
        }
        __syncthreads();
        if (kb + 2 < nkb) issue(kb + 2);
        CP_COMMIT();
    }

    // epilogue
#pragma unroll
    for (int mt = 0; mt < 4; mt++) {
#pragma unroll
        for (int nt = 0; nt < 4; nt++) {
            int row = m0 + wr * 64 + mt * 16 + g;
            int col = n0 + wc * 32 + nt * 8 + 2 * tg;
            float b0 = bias[col], b1 = bias[col + 1];
            float v0 = acc[mt][nt][0] + b0;
            float v1 = acc[mt][nt][1] + b1;
            float v2 = acc[mt][nt][2] + b0;
            float v3 = acc[mt][nt][3] + b1;
            if (do_gelu) {
                v0 = 0.5f * v0 * (1.f + erff(v0 * 0.70710678118654752f));
                v1 = 0.5f * v1 * (1.f + erff(v1 * 0.70710678118654752f));
                v2 = 0.5f * v2 * (1.f + erff(v2 * 0.70710678118654752f));
                v3 = 0.5f * v3 * (1.f + erff(v3 * 0.70710678118654752f));
            }
            *(float2*)(C + (size_t)row * N + col)       = make_float2(v0, v1);
            *(float2*)(C + (size_t)(row + 8) * N + col) = make_float2(v2, v3);
        }
    }
}

// ============================================================================
// Attention scores on mma: S[bz][q][k] = Q·K^T / sqrt(96).
// One-shot K=96 in smem. 128x128 tile per CTA, grid (8,8,64).
// Q,K tiles [pos][d] pitch 100 (banks 4g+tg distinct for both fragments).
// ============================================================================
#define QP 100
#define SC_SMEM (2*128*QP*4)

__global__ void __launch_bounds__(256) attn_scores_mma(
    const float* __restrict__ Q, const float* __restrict__ Kb,
    float* __restrict__ Sc)
{
    extern __shared__ float sm[];
    float* Qs = sm;
    float* Ks = sm + 128 * QP;

    const int tid = threadIdx.x;
    const int wid = tid >> 5, lane = tid & 31;
    const int wr = wid >> 2, wc = wid & 3;
    const int g = lane >> 2, tg = lane & 3;
    const int bz = blockIdx.z, b = bz >> 3, h = bz & 7;
    const int m0 = blockIdx.y * 128, n0 = blockIdx.x * 128;

    const float* qg = Q + (size_t)b * SS * AHd + h * HD;
    const float* kg = Kb + (size_t)b * SS * AHd + h * HD;
#pragma unroll
    for (int t = 0; t < 12; t++) {
        int s = tid + t * 256;               // 0..3071
        int r = s / 24, c = (s % 24) * 4;
        CP16(sptr(Qs + r * QP + c), qg + (size_t)(m0 + r) * AHd + c);
    }
#pragma unroll
    for (int t = 0; t < 12; t++) {
        int s = tid + t * 256;
        int r = s / 24, c = (s % 24) * 4;
        CP16(sptr(Ks + r * QP + c), kg + (size_t)(n0 + r) * AHd + c);
    }
    CP_COMMIT();
    CP_WAIT(0);
    __syncthreads();

    float acc[4][4][4];
#pragma unroll
    for (int i = 0; i < 4; i++)
#pragma unroll
        for (int j = 0; j < 4; j++)
#pragma unroll
            for (int c = 0; c < 4; c++) acc[i][j][c] = 0.f;

    const uint32_t* Qu = (const uint32_t*)Qs;
    const uint32_t* Ku = (const uint32_t*)Ks;
#pragma unroll
    for (int kk = 0; kk < 96; kk += 8) {
        uint32_t af[4][4], bf[4][2];
#pragma unroll
        for (int mt = 0; mt < 4; mt++) {
            int mb = wr * 64 + mt * 16 + g;
            af[mt][0] = Qu[mb * QP + kk + tg];
            af[mt][1] = Qu[(mb + 8) * QP + kk + tg];
            af[mt][2] = Qu[mb * QP + kk + tg + 4];
            af[mt][3] = Qu[(mb + 8) * QP + kk + tg + 4];
        }
#pragma unroll
        for (int nt = 0; nt < 4; nt++) {
            int nb = wc * 32 + nt * 8 + g;
            bf[nt][0] = Ku[nb * QP + kk + tg];
            bf[nt][1] = Ku[nb * QP + kk + tg + 4];
        }
#pragma unroll
        for (int mt = 0; mt < 4; mt++)
#pragma unroll
            for (int nt = 0; nt < 4; nt++)
                mma_tf32(acc[mt][nt], af[mt], bf[nt]);
    }

    const float sc = 0.10206207261596576f;   // 1/sqrt(96)
#pragma unroll
    for (int mt = 0; mt < 4; mt++) {
#pragma unroll
        for (int nt = 0; nt < 4; nt++) {
            int row = m0 + wr * 64 + mt * 16 + g;
            int col = n0 + wc * 32 + nt * 8 + 2 * tg;
            float* p0 = Sc + ((size_t)bz * SS + row) * SS + col;
            float* p1 = Sc + ((size_t)bz * SS + row + 8) * SS + col;
            *(float2*)p0 = make_float2(acc[mt][nt][0] * sc, acc[mt][nt][1] * sc);
            *(float2*)p1 = make_float2(acc[mt][nt][2] * sc, acc[mt][nt][3] * sc);
        }
    }
}

// ============================================================================
// Attention ctx on mma: C[b,q,h,:] = P[bz] @ V_h.  M=1024,N=96,K=1024 per bz.
// BM=128, BN=96, BK=32, 3 stages, 256 threads (warps 2x4, warp 64x24, nt=3).
// P tile [q][k] pitch 36; V tile [k][d] pitch 104 (banks 8tg+g distinct).
// ============================================================================
#define CPV   104
#define CASZ  (128*PA)
#define CVSZ  (32*CPV)
#define CTX_SMEM (NSTG*(CASZ+CVSZ)*4)

__global__ void __launch_bounds__(256) attn_ctx_mma(
    const float* __restrict__ P, const float* __restrict__ V,
    float* __restrict__ C)
{
    extern __shared__ float sm[];
    float* Abase = sm;
    float* Vbase = sm + NSTG * CASZ;

    const int tid = threadIdx.x;
    const int wid = tid >> 5, lane = tid & 31;
    const int wr = wid >> 2, wc = wid & 3;
    const int g = lane >> 2, tg = lane & 3;
    const int bz = blockIdx.y, b = bz >> 3, h = bz & 7;
    const int m0 = blockIdx.x * 128;
    const int nkb = SS / 32;   // 32

    const float* pg = P + ((size_t)bz * SS + m0) * SS;
    const float* vg = V + (size_t)b * SS * AHd + h * HD;

    float acc[4][3][4];
#pragma unroll
    for (int i = 0; i < 4; i++)
#pragma unroll
        for (int j = 0; j < 3; j++)
#pragma unroll
            for (int c = 0; c < 4; c++) acc[i][j][c] = 0.f;

    auto issue = [&](int kb) {
        int s = kb % NSTG;
        float* As = Abase + s * CASZ;
        float* Vs = Vbase + s * CVSZ;
#pragma unroll
        for (int t = 0; t < 4; t++) {
            int sA = tid + t * 256;
            int r = sA >> 3, c = (sA & 7) << 2;
            CP16(sptr(As + r * PA + c), pg + (size_t)r * SS + kb * 32 + c);
        }
#pragma unroll
        for (int t = 0; t < 3; t++) {
            int sV = tid + t * 256;          // 0..767
            int r = sV / 24, c = (sV % 24) * 4;
            CP16(sptr(Vs + r * CPV + c), vg + (size_t)(kb * 32 + r) * AHd + c);
        }
    };

    issue(0); CP_COMMIT();
    issue(1); CP_COMMIT();

    for (int kb = 0; kb < nkb; kb++) {
        CP_WAIT(1);
        __syncthreads();
        int s = kb % NSTG;
        const uint32_t* As = (const uint32_t*)(Abase + s * CASZ);
        const uint32_t* Vs = (const uint32_t*)(Vbase + s * CVSZ);
#pragma unroll
        for (int kk = 0; kk < 32; kk += 8) {
            uint32_t af[4][4], bf[3][2];
#pragma unroll
            for (int mt = 0; mt < 4; mt++) {
                int mb = wr * 64 + mt * 16 + g;
                af[mt][0] = As[mb * PA + kk + tg];
                af[mt][1] = As[(mb + 8) * PA + kk + tg];
                af[mt][2] = As[mb * PA + kk + tg + 4];
                af[mt][3] = As[(mb + 8) * PA + kk + tg + 4];
            }
#pragma unroll
            for (int nt = 0; nt < 3; nt++) {
                int nb = wc * 24 + nt * 8 + g;
                bf[nt][0] = Vs[(kk + tg) * CPV + nb];
                bf[nt][1] = Vs[(kk + tg + 4) * CPV + nb];
            }
#pragma unroll
            for (int mt = 0; mt < 4; mt++)
#pragma unroll
                for (int nt = 0; nt < 3; nt++)
                    mma_tf32(acc[mt][nt], af[mt], bf[nt]);
        }
        __syncthreads();
        if (kb + 2 < nkb) issue(kb + 2);
        CP_COMMIT();
    }

#pragma unroll
    for (int mt = 0; mt < 4; mt++) {
#pragma unroll
        for (int nt = 0; nt < 3; nt++) {
            int row = m0 + wr * 64 + mt * 16 + g;
            int col = h * HD + wc * 24 + nt * 8 + 2 * tg;
            float* p0 = C + ((size_t)b * SS + row) * HH + col;
            float* p1 = C + ((size_t)b * SS + row + 8) * HH + col;
            *(float2*)p0 = make_float2(acc[mt][nt][0], acc[mt][nt][1]);
            *(float2*)p1 = make_float2(acc[mt][nt][2], acc[mt][nt][3]);
        }
    }
}

// ---------------- small SIMT SGEMM (only for ck: N=56) ----------------
__global__ void sgemm_bias(const float* __restrict__ A, const float* __restrict__ W,
                           const float* __restrict__ bias, float* __restrict__ C,
                           int M, int N, int Kd, int do_gelu) {
    __shared__ float As[8][132];
    __shared__ float Bs[8][128];
    const int tid  = threadIdx.x;
    const int bx   = blockIdx.x, by = blockIdx.y;
    const int trow = tid >> 4, tcol = tid & 15;
    float acc[8][8];
#pragma unroll
    for (int i = 0; i < 8; i++)
#pragma unroll
        for (int j = 0; j < 8; j++) acc[i][j] = 0.f;

    const int aRow = tid >> 1;
    const int aCol = (tid & 1) * 4;
    const int bRow = tid >> 5;
    const int bCol = (tid & 31) * 4;

    const float* Ap = A + (size_t)(by * 128 + aRow) * Kd + aCol;
    const float* Wp = W + (size_t)bRow * N + bx * 128 + bCol;
    const bool nOK = (bx * 128 + bCol + 3) < N;

    for (int k0 = 0; k0 < Kd; k0 += 8) {
        float4 av = *(const float4*)Ap;
        As[aCol + 0][aRow] = av.x;
        As[aCol + 1][aRow] = av.y;
        As[aCol + 2][aRow] = av.z;
        As[aCol + 3][aRow] = av.w;
        float4 bv = nOK ? *(const float4*)Wp : make_float4(0.f, 0.f, 0.f, 0.f);
        *(float4*)&Bs[bRow][bCol] = bv;
        __syncthreads();
#pragma unroll
        for (int kk = 0; kk < 8; kk++) {
            float ar[8], br[8];
            *(float4*)(ar)     = *(const float4*)&As[kk][trow * 8];
            *(float4*)(ar + 4) = *(const float4*)&As[kk][trow * 8 + 4];
            *(float4*)(br)     = *(const float4*)&Bs[kk][tcol * 8];
            *(float4*)(br + 4) = *(const float4*)&Bs[kk][tcol * 8 + 4];
#pragma unroll
            for (int i = 0; i < 8; i++)
#pragma unroll
                for (int j = 0; j < 8; j++) acc[i][j] += ar[i] * br[j];
        }
        __syncthreads();
        Ap += 8;
        Wp += (size_t)8 * N;
    }

    const int row0 = by * 128 + trow * 8;
    const int col0 = bx * 128 + tcol * 8;
#pragma unroll
    for (int i = 0; i < 8; i++) {
#pragma unroll
        for (int j = 0; j < 8; j++) {
            int cc = col0 + j;
            if (cc < N) {
                float x = acc[i][j] + bias[cc];
                if (do_gelu) x = 0.5f * x * (1.f + erff(x * 0.70710678118654752f));
                C[(size_t)(row0 + i) * N + cc] = x;
            }
        }
    }
}

// ---------------- depthwise conv over sequence (k=7, same pad) ----------------
__global__ void depthwise_conv(const float* __restrict__ X, const float* __restrict__ dw,
                               float* __restrict__ Y) {
    int idx = blockIdx.x * blockDim.x + threadIdx.x;
    if (idx >= MROWS * HH) return;
    int c = idx % HH;
    int s = (idx / HH) % SS;
    int b = idx / (HH * SS);
    float acc = 0.f;
#pragma unroll
    for (int k = 0; k < KK; k++) {
        int ss = s + k - 3;
        if (ss >= 0 && ss < SS)
            acc += X[((size_t)b * SS + ss) * HH + c] * dw[c * KK + k];
    }
    Y[idx] = acc;
}

__global__ void mul_inplace(float* __restrict__ A, const float* __restrict__ B, int n) {
    int i = blockIdx.x * blockDim.x + threadIdx.x;
    if (i < n) A[i] *= B[i];
}

__global__ void softmax7(float* __restrict__ ck) {
    int idx = blockIdx.x * blockDim.x + threadIdx.x;
    if (idx >= MROWS * NHh) return;
    int row = idx >> 3, h = idx & 7;
    float* p = ck + (size_t)row * 56 + h * 7;
    float m = p[0];
#pragma unroll
    for (int k = 1; k < 7; k++) m = fmaxf(m, p[k]);
    float e[7], s = 0.f;
#pragma unroll
    for (int k = 0; k < 7; k++) { e[k] = expf(p[k] - m); s += e[k]; }
    float inv = 1.f / s;
#pragma unroll
    for (int k = 0; k < 7; k++) p[k] = e[k] * inv;
}

__global__ void span_conv(const float* __restrict__ co, const float* __restrict__ ck,
                          float* __restrict__ ctx) {
    int idx = blockIdx.x * blockDim.x + threadIdx.x;
    if (idx >= MROWS * AHd) return;
    int d = idx % HD;
    int h = (idx / HD) % NHh;
    int s = (idx / AHd) % SS;
    int b = idx / (AHd * SS);
    size_t row = (size_t)b * SS + s;
    const float* w = ck + row * 56 + h * 7;
    float acc = 0.f;
#pragma unroll
    for (int k = 0; k < KK; k++) {
        int ss = s + k - 3;
        if (ss >= 0 && ss < SS)
            acc += co[((size_t)b * SS + ss) * AHd + h * HD + d] * w[k];
    }
    ctx[row * HH + AHd + h * HD + d] = acc;
}

__global__ void softmax_rows(float* __restrict__ Sc) {
    size_t row = blockIdx.x;
    int tid = threadIdx.x;
    float4* p = (float4*)(Sc + row * SS);
    float4 v = p[tid];
    __shared__ float red[256];
    float m = fmaxf(fmaxf(v.x, v.y), fmaxf(v.z, v.w));
    red[tid] = m;
    __syncthreads();
    for (int o = 128; o > 0; o >>= 1) {
        if (tid < o) red[tid] = fmaxf(red[tid], red[tid + o]);
        __syncthreads();
    }
    m = red[0];
    __syncthreads();
    v.x = expf(v.x - m); v.y = expf(v.y - m); v.z = expf(v.z - m); v.w = expf(v.w - m);
    red[tid] = v.x + v.y + v.z + v.w;
    __syncthreads();
    for (int o = 128; o > 0; o >>= 1) {
        if (tid < o) red[tid] += red[tid + o];
        __syncthreads();
    }
    float inv = 1.f / red[0];
    v.x *= inv; v.y *= inv; v.z *= inv; v.w *= inv;
    p[tid] = v;
}

// ---------------- fused residual + LayerNorm over H=1536 ----------------
__global__ void ln_residual(const float* __restrict__ X, const float* __restrict__ R,
                            const float* __restrict__ gam, const float* __restrict__ bet,
                            float* __restrict__ O) {
    size_t row = blockIdx.x;
    int tid = threadIdx.x;
    const float* x = X + row * HH;
    const float* r = R + row * HH;
    __shared__ float red[256];
    float vals[6];
    float s = 0.f;
#pragma unroll
    for (int t = 0; t < 6; t++) {
        int c = tid + t * 256;
        vals[t] = x[c] + r[c];
        s += vals[t];
    }
    red[tid] = s;
    __syncthreads();
    for (int o = 128; o > 0; o >>= 1) {
        if (tid < o) red[tid] += red[tid + o];
        __syncthreads();
    }
    float mean = red[0] * (1.f / HH);
    __syncthreads();
    float s2 = 0.f;
#pragma unroll
    for (int t = 0; t < 6; t++) {
        float d = vals[t] - mean;
        s2 += d * d;
    }
    red[tid] = s2;
    __syncthreads();
    for (int o = 128; o > 0; o >>= 1) {
        if (tid < o) red[tid] += red[tid + o];
        __syncthreads();
    }
    float rstd = rsqrtf(red[0] * (1.f / HH) + 1e-12f);
#pragma unroll
    for (int t = 0; t < 6; t++) {
        int c = tid + t * 256;
        O[row * HH + c] = (vals[t] - mean) * rstd * gam[c] + bet[c];
    }
}

// ---------------- global max-pool + decoder ----------------
__global__ void maxpool_seq(const float* __restrict__ L, float* __restrict__ pooled) {
    int idx = blockIdx.x * blockDim.x + threadIdx.x;
    if (idx >= MB * HH) return;
    int c = idx % HH, b = idx / HH;
    const float* base = L + (size_t)b * SS * HH + c;
    float m = -3.4e38f;
    for (int s = 0; s < SS; s++) m = fmaxf(m, base[(size_t)s * HH]);
    pooled[idx] = m;
}

__global__ void decode(const float* __restrict__ pooled, const float* __restrict__ wd,
                       const float* __restrict__ bd, float* __restrict__ out) {
    int b = blockIdx.x;
    int tid = threadIdx.x;
    __shared__ float red[256];
    float part = 0.f;
    for (int c = tid; c < HH; c += 256) part += pooled[b * HH + c] * wd[c];
    red[tid] = part;
    __syncthreads();
    for (int o = 128; o > 0; o >>= 1) {
        if (tid < o) red[tid] += red[tid + o];
        __syncthreads();
    }
    if (tid == 0) out[b] = red[0] + bd[0];
}

// ============================================================================
// Host launcher
// ============================================================================
extern "C" void kernel_launch(void* const* d_in, const int* in_sizes, int n_in,
                              void* d_out, int out_size) {
    const float* embed = (const float*)d_in[0];
    const float* wq  = (const float*)d_in[1];  const float* bq  = (const float*)d_in[2];
    const float* wk  = (const float*)d_in[3];  const float* bk  = (const float*)d_in[4];
    const float* wv  = (const float*)d_in[5];  const float* bv  = (const float*)d_in[6];
    const float* dw  = (const float*)d_in[7];
    const float* pw  = (const float*)d_in[8];  const float* sep_b = (const float*)d_in[9];
    const float* wck = (const float*)d_in[10]; const float* bck = (const float*)d_in[11];
    const float* wco = (const float*)d_in[12]; const float* bco = (const float*)d_in[13];
    const float* wso = (const float*)d_in[14]; const float* bso = (const float*)d_in[15];
    const float* ln1_g = (const float*)d_in[16]; const float* ln1_b = (const float*)d_in[17];
    const float* wi  = (const float*)d_in[18]; const float* bi  = (const float*)d_in[19];
    const float* wo  = (const float*)d_in[20]; const float* bo  = (const float*)d_in[21];
    const float* ln2_g = (const float*)d_in[22]; const float* ln2_b = (const float*)d_in[23];
    const float* wd  = (const float*)d_in[24]; const float* bd  = (const float*)d_in[25];
    float* out = (float*)d_out;

    cudaFuncSetAttribute(mma_gemm, cudaFuncAttributeMaxDynamicSharedMemorySize, GEMM_SMEM);
    cudaFuncSetAttribute(attn_scores_mma, cudaFuncAttributeMaxDynamicSharedMemorySize, SC_SMEM);
    cudaFuncSetAttribute(attn_ctx_mma, cudaFuncAttributeMaxDynamicSharedMemorySize, CTX_SMEM);

    float *q, *k, *v, *co, *dconv, *sep, *ck, *scores, *ctx, *tmp, *inter, *attn, *layer, *pool;
    cudaGetSymbolAddress((void**)&q, g_q);
    cudaGetSymbolAddress((void**)&k, g_k);
    cudaGetSymbolAddress((void**)&v, g_v);
    cudaGetSymbolAddress((void**)&co, g_co);
    cudaGetSymbolAddress((void**)&dconv, g_dconv);
    cudaGetSymbolAddress((void**)&sep, g_sep);
    cudaGetSymbolAddress((void**)&ck, g_ck);
    cudaGetSymbolAddress((void**)&scores, g_scores);
    cudaGetSymbolAddress((void**)&ctx, g_ctx);
    cudaGetSymbolAddress((void**)&tmp, g_tmp);
    cudaGetSymbolAddress((void**)&inter, g_inter);
    cudaGetSymbolAddress((void**)&attn, g_attn);
    cudaGetSymbolAddress((void**)&layer, g_layer);
    cudaGetSymbolAddress((void**)&pool, g_pool);

    dim3 blk(256);

    // ---- projections ----
    dim3 gproj(AHd / 128, MROWS / 128);
    mma_gemm<<<gproj, blk, GEMM_SMEM>>>(embed, wq,  bq,  q,  AHd, HH, 0);
    mma_gemm<<<gproj, blk, GEMM_SMEM>>>(embed, wk,  bk,  k,  AHd, HH, 0);
    mma_gemm<<<gproj, blk, GEMM_SMEM>>>(embed, wv,  bv,  v,  AHd, HH, 0);
    mma_gemm<<<gproj, blk, GEMM_SMEM>>>(embed, wco, bco, co, AHd, HH, 0);

    // ---- separable conv ----
    depthwise_conv<<<(MROWS * HH + 255) / 256, blk>>>(embed, dw, dconv);
    mma_gemm<<<gproj, blk, GEMM_SMEM>>>(dconv, pw, sep_b, sep, AHd, HH, 0);

    // conv_attn = sep * q
    mul_inplace<<<(MROWS * AHd + 255) / 256, blk>>>(sep, q, MROWS * AHd);

    // span kernels (N=56 -> SIMT gemm)
    dim3 gck(1, MROWS / 128);
    sgemm_bias<<<gck, blk>>>(sep, wck, bck, ck, MROWS, 56, AHd, 0);
    softmax7<<<(MROWS * NHh + 255) / 256, blk>>>(ck);
    span_conv<<<(MROWS * AHd + 255) / 256, blk>>>(co, ck, ctx);

    // ---- self-attention (tensor path) ----
    dim3 gsc(SS / 128, SS / 128, MB * NHh);
    attn_scores_mma<<<gsc, blk, SC_SMEM>>>(q, k, scores);
    softmax_rows<<<MB * NHh * SS, blk>>>(scores);
    dim3 gcx(SS / 128, MB * NHh);
    attn_ctx_mma<<<gcx, blk, CTX_SMEM>>>(scores, v, ctx);

    // ---- self output + LN1 ----
    dim3 gso(HH / 128, MROWS / 128);
    mma_gemm<<<gso, blk, GEMM_SMEM>>>(ctx, wso, bso, tmp, HH, HH, 0);
    ln_residual<<<MROWS, blk>>>(tmp, embed, ln1_g, ln1_b, attn);

    // ---- FFN ----
    dim3 gin(IM / 128, MROWS / 128);
    mma_gemm<<<gin, blk, GEMM_SMEM>>>(attn, wi, bi, inter, IM, HH, 1);
    mma_gemm<<<gso, blk, GEMM_SMEM>>>(inter, wo, bo, tmp, HH, IM, 0);
    ln_residual<<<MROWS, blk>>>(tmp, attn, ln2_g, ln2_b, layer);

    // ---- pool + decode ----
    maxpool_seq<<<(MB * HH + 255) / 256, blk>>>(layer, pool);
    decode<<<MB, blk>>>(pool, wd, bd, out);
}

// round 5
// speedup vs baseline: 3.7975x; 1.1682x over previous
#include <cuda_runtime.h>
#include <math.h>
#include <stdint.h>

// ---------------- problem dims ----------------
#define MB   8
#define SS   1024
#define HH   1536
#define NHh  8
#define HD   96
#define AHd  768
#define KK   7
#define IM   3072
#define MROWS (MB*SS)          // 8192

// ---------------- scratch ----------------
__device__ float g_q   [MROWS*AHd];
__device__ float g_k   [MROWS*AHd];
__device__ float g_v   [MROWS*AHd];
__device__ float g_co  [MROWS*AHd];
__device__ float g_dconv[MROWS*HH];
__device__ float g_sep [MROWS*AHd];
__device__ float g_ck  [MROWS*56];
__device__ float g_scores[(size_t)MB*NHh*SS*SS];   // 268 MB
__device__ float g_ctx [MROWS*HH];
__device__ float g_tmp [MROWS*HH];
__device__ float g_inter[MROWS*IM];
__device__ float g_attn[MROWS*HH];
__device__ float g_layer[MROWS*HH];
__device__ float g_pool[MB*HH];

// ---------------- PTX helpers ----------------
__device__ __forceinline__ uint32_t sptr(const void* p) {
    return (uint32_t)__cvta_generic_to_shared(p);
}
#define CP16(dst, src) \
    asm volatile("cp.async.cg.shared.global [%0], [%1], 16;" :: "r"(dst), "l"(src))
#define CP_COMMIT() asm volatile("cp.async.commit_group;" ::: "memory")
#define CP_WAIT(n)  asm volatile("cp.async.wait_group %0;" :: "n"(n) : "memory")

__device__ __forceinline__ void mma_tf32(float* d, const uint32_t* a, const uint32_t* b) {
    asm volatile(
        "mma.sync.aligned.m16n8k8.row.col.f32.tf32.tf32.f32 "
        "{%0,%1,%2,%3}, {%4,%5,%6,%7}, {%8,%9}, {%0,%1,%2,%3};"
        : "+f"(d[0]), "+f"(d[1]), "+f"(d[2]), "+f"(d[3])
        : "r"(a[0]), "r"(a[1]), "r"(a[2]), "r"(a[3]), "r"(b[0]), "r"(b[1]));
}

// ============================================================================
// tf32 mma GEMM, 2-stage cp.async pipeline, 2 CTAs/SM.
// op: 0 = bias, 1 = bias+gelu, 2 = (x+bias)*aux
// ============================================================================
#define PA   36
#define PB   136
#define ASZ  (128*PA)
#define BSZ  (32*PB)
#define NSTG 2
#define GEMM_SMEM (NSTG*(ASZ+BSZ)*4)

struct GemmSet { const float* W; const float* bias; float* C; };

__device__ __forceinline__ void gemm_body(
    const float* __restrict__ A, const float* __restrict__ W,
    const float* __restrict__ bias, float* __restrict__ C,
    const float* __restrict__ aux,
    int N, int Kd, int op, int m0, int n0, float* sm)
{
    float* Abase = sm;
    float* Bbase = sm + NSTG * ASZ;

    const int tid = threadIdx.x;
    const int wid = tid >> 5, lane = tid & 31;
    const int wr = wid >> 2, wc = wid & 3;
    const int g = lane >> 2, tg = lane & 3;
    const int nkb = Kd >> 5;

    float acc[4][4][4];
#pragma unroll
    for (int i = 0; i < 4; i++)
#pragma unroll
        for (int j = 0; j < 4; j++)
#pragma unroll
            for (int c = 0; c < 4; c++) acc[i][j][c] = 0.f;

    auto issue = [&](int kb) {
        int s = kb % NSTG;
        float* As = Abase + s * ASZ;
        float* Bs = Bbase + s * BSZ;
        const float* ag = A + (size_t)m0 * Kd + kb * 32;
        const float* bg = W + (size_t)(kb * 32) * N + n0;
#pragma unroll
        for (int t = 0; t < 4; t++) {
            int sA = tid + t * 256;
            int r  = sA >> 3,  c  = (sA & 7) << 2;
            CP16(sptr(As + r * PA + c), ag + (size_t)r * Kd + c);
            int rb = sA >> 5,  cb = (sA & 31) << 2;
            CP16(sptr(Bs + rb * PB + cb), bg + (size_t)rb * N + cb);
        }
    };

    issue(0); CP_COMMIT();
    issue(1); CP_COMMIT();

    for (int kb = 0; kb < nkb; kb++) {
        CP_WAIT(1);
        __syncthreads();
        int s = kb % NSTG;
        const uint32_t* As = (const uint32_t*)(Abase + s * ASZ);
        const uint32_t* Bs = (const uint32_t*)(Bbase + s * BSZ);
#pragma unroll
        for (int kk = 0; kk < 32; kk += 8) {
            uint32_t af[4][4], bf[4][2];
#pragma unroll
            for (int mt = 0; mt < 4; mt++) {
                int mb = wr * 64 + mt * 16 + g;
                af[mt][0] = As[mb * PA + kk + tg];
                af[mt][1] = As[(mb + 8) * PA + kk + tg];
                af[mt][2] = As[mb * PA + kk + tg + 4];
                af[mt][3] = As[(mb + 8) * PA + kk + tg + 4];
            }
#pragma unroll
            for (int nt = 0; nt < 4; nt++) {
                int nb = wc * 32 + nt * 8 + g;
                bf[nt][0] = Bs[(kk + tg) * PB + nb];
                bf[nt][1] = Bs[(kk + tg + 4) * PB + nb];
            }
#pragma unroll
            for (int mt = 0; mt < 4; mt++)
#pragma unroll
                for (int nt = 0; nt < 4; nt++)
                    mma_tf32(acc[mt][nt], af[mt], bf[nt]);
        }
        __syncthreads();
        if (kb + 2 < nkb) issue(kb + 2);
        CP_COMMIT();
    }

#pragma unroll
    for (int mt = 0; mt < 4; mt++) {
#pragma unroll
        for (int nt = 0; nt < 4; nt++) {
            int row = m0 + wr * 64 + mt * 16 + g;
            int col = n0 + wc * 32 + nt * 8 + 2 * tg;
            float b0 = bias[col], b1 = bias[col + 1];
            float v0 = acc[mt][nt][0] + b0;
            float v1 = acc[mt][nt][1] + b1;
            float v2 = acc[mt][nt][2] + b0;
            float v3 = acc[mt][nt][3] + b1;
            if (op == 1) {
                v0 = 0.5f * v0 * (1.f + erff(v0 * 0.70710678118654752f));
                v1 = 0.5f * v1 * (1.f + erff(v1 * 0.70710678118654752f));
                v2 = 0.5f * v2 * (1.f + erff(v2 * 0.70710678118654752f));
                v3 = 0.5f * v3 * (1.f + erff(v3 * 0.70710678118654752f));
            } else if (op == 2) {
                const float* a0 = aux + (size_t)row * N + col;
                const float* a1 = aux + (size_t)(row + 8) * N + col;
                v0 *= a0[0]; v1 *= a0[1]; v2 *= a1[0]; v3 *= a1[1];
            }
            *(float2*)(C + (size_t)row * N + col)       = make_float2(v0, v1);
            *(float2*)(C + (size_t)(row + 8) * N + col) = make_float2(v2, v3);
        }
    }
}

__global__ void __launch_bounds__(256, 2) mma_gemm(
    const float* __restrict__ A, const float* __restrict__ W,
    const float* __restrict__ bias, float* __restrict__ C,
    const float* __restrict__ aux, int N, int Kd, int op)
{
    extern __shared__ float sm[];
    gemm_body(A, W, bias, C, aux, N, Kd, op, blockIdx.y * 128, blockIdx.x * 128, sm);
}

// fused q/k/v/co: same A, blockIdx.z selects {W, bias, C}
__global__ void __launch_bounds__(256, 2) mma_gemm_multi(
    const float* __restrict__ A, GemmSet s0, GemmSet s1, GemmSet s2, GemmSet s3,
    int N, int Kd)
{
    extern __shared__ float sm[];
    GemmSet s = (blockIdx.z == 0) ? s0 : (blockIdx.z == 1) ? s1 : (blockIdx.z == 2) ? s2 : s3;
    gemm_body(A, s.W, s.bias, s.C, nullptr, N, Kd, 0, blockIdx.y * 128, blockIdx.x * 128, sm);
}

// ============================================================================
// Attention scores: S = Q·K^T / sqrt(96). One-shot K=96. 128x128/CTA.
// ============================================================================
#define QP 100
#define SC_SMEM (2*128*QP*4)

__global__ void __launch_bounds__(256) attn_scores_mma(
    const float* __restrict__ Q, const float* __restrict__ Kb,
    float* __restrict__ Sc)
{
    extern __shared__ float sm[];
    float* Qs = sm;
    float* Ks = sm + 128 * QP;

    const int tid = threadIdx.x;
    const int wid = tid >> 5, lane = tid & 31;
    const int wr = wid >> 2, wc = wid & 3;
    const int g = lane >> 2, tg = lane & 3;
    const int bz = blockIdx.z, b = bz >> 3, h = bz & 7;
    const int m0 = blockIdx.y * 128, n0 = blockIdx.x * 128;

    const float* qg = Q + (size_t)b * SS * AHd + h * HD;
    const float* kg = Kb + (size_t)b * SS * AHd + h * HD;
#pragma unroll
    for (int t = 0; t < 12; t++) {
        int s = tid + t * 256;
        int r = s / 24, c = (s % 24) * 4;
        CP16(sptr(Qs + r * QP + c), qg + (size_t)(m0 + r) * AHd + c);
    }
#pragma unroll
    for (int t = 0; t < 12; t++) {
        int s = tid + t * 256;
        int r = s / 24, c = (s % 24) * 4;
        CP16(sptr(Ks + r * QP + c), kg + (size_t)(n0 + r) * AHd + c);
    }
    CP_COMMIT();
    CP_WAIT(0);
    __syncthreads();

    float acc[4][4][4];
#pragma unroll
    for (int i = 0; i < 4; i++)
#pragma unroll
        for (int j = 0; j < 4; j++)
#pragma unroll
            for (int c = 0; c < 4; c++) acc[i][j][c] = 0.f;

    const uint32_t* Qu = (const uint32_t*)Qs;
    const uint32_t* Ku = (const uint32_t*)Ks;
#pragma unroll
    for (int kk = 0; kk < 96; kk += 8) {
        uint32_t af[4][4], bf[4][2];
#pragma unroll
        for (int mt = 0; mt < 4; mt++) {
            int mb = wr * 64 + mt * 16 + g;
            af[mt][0] = Qu[mb * QP + kk + tg];
            af[mt][1] = Qu[(mb + 8) * QP + kk + tg];
            af[mt][2] = Qu[mb * QP + kk + tg + 4];
            af[mt][3] = Qu[(mb + 8) * QP + kk + tg + 4];
        }
#pragma unroll
        for (int nt = 0; nt < 4; nt++) {
            int nb = wc * 32 + nt * 8 + g;
            bf[nt][0] = Ku[nb * QP + kk + tg];
            bf[nt][1] = Ku[nb * QP + kk + tg + 4];
        }
#pragma unroll
        for (int mt = 0; mt < 4; mt++)
#pragma unroll
            for (int nt = 0; nt < 4; nt++)
                mma_tf32(acc[mt][nt], af[mt], bf[nt]);
    }

    const float sc = 0.10206207261596576f;
#pragma unroll
    for (int mt = 0; mt < 4; mt++) {
#pragma unroll
        for (int nt = 0; nt < 4; nt++) {
            int row = m0 + wr * 64 + mt * 16 + g;
            int col = n0 + wc * 32 + nt * 8 + 2 * tg;
            float* p0 = Sc + ((size_t)bz * SS + row) * SS + col;
            float* p1 = Sc + ((size_t)bz * SS + row + 8) * SS + col;
            *(float2*)p0 = make_float2(acc[mt][nt][0] * sc, acc[mt][nt][1] * sc);
            *(float2*)p1 = make_float2(acc[mt][nt][2] * sc, acc[mt][nt][3] * sc);
        }
    }
}

// ============================================================================
// Attention ctx: C = P @ V.  2-stage, 2 CTAs/SM.
// ============================================================================
#define CPV   104
#define CASZ  (128*PA)
#define CVSZ  (32*CPV)
#define CTX_SMEM (NSTG*(CASZ+CVSZ)*4)

__global__ void __launch_bounds__(256, 2) attn_ctx_mma(
    const float* __restrict__ P, const float* __restrict__ V,
    float* __restrict__ C)
{
    extern __shared__ float sm[];
    float* Abase = sm;
    float* Vbase = sm + NSTG * CASZ;

    const int tid = threadIdx.x;
    const int wid = tid >> 5, lane = tid & 31;
    const int wr = wid >> 2, wc = wid & 3;
    const int g = lane >> 2, tg = lane & 3;
    const int bz = blockIdx.y, b = bz >> 3, h = bz & 7;
    const int m0 = blockIdx.x * 128;
    const int nkb = SS / 32;

    const float* pg = P + ((size_t)bz * SS + m0) * SS;
    const float* vg = V + (size_t)b * SS * AHd + h * HD;

    float acc[4][3][4];
#pragma unroll
    for (int i = 0; i < 4; i++)
#pragma unroll
        for (int j = 0; j < 3; j++)
#pragma unroll
            for (int c = 0; c < 4; c++) acc[i][j][c] = 0.f;

    auto issue = [&](int kb) {
        int s = kb % NSTG;
        float* As = Abase + s * CASZ;
        float* Vs = Vbase + s * CVSZ;
#pragma unroll
        for (int t = 0; t < 4; t++) {
            int sA = tid + t * 256;
            int r = sA >> 3, c = (sA & 7) << 2;
            CP16(sptr(As + r * PA + c), pg + (size_t)r * SS + kb * 32 + c);
        }
#pragma unroll
        for (int t = 0; t < 3; t++) {
            int sV = tid + t * 256;
            int r = sV / 24, c = (sV % 24) * 4;
            CP16(sptr(Vs + r * CPV + c), vg + (size_t)(kb * 32 + r) * AHd + c);
        }
    };

    issue(0); CP_COMMIT();
    issue(1); CP_COMMIT();

    for (int kb = 0; kb < nkb; kb++) {
        CP_WAIT(1);
        __syncthreads();
        int s = kb % NSTG;
        const uint32_t* As = (const uint32_t*)(Abase + s * CASZ);
        const uint32_t* Vs = (const uint32_t*)(Vbase + s * CVSZ);
#pragma unroll
        for (int kk = 0; kk < 32; kk += 8) {
            uint32_t af[4][4], bf[3][2];
#pragma unroll
            for (int mt = 0; mt < 4; mt++) {
                int mb = wr * 64 + mt * 16 + g;
                af[mt][0] = As[mb * PA + kk + tg];
                af[mt][1] = As[(mb + 8) * PA + kk + tg];
                af[mt][2] = As[mb * PA + kk + tg + 4];
                af[mt][3] = As[(mb + 8) * PA + kk + tg + 4];
            }
#pragma unroll
            for (int nt = 0; nt < 3; nt++) {
                int nb = wc * 24 + nt * 8 + g;
                bf[nt][0] = Vs[(kk + tg) * CPV + nb];
                bf[nt][1] = Vs[(kk + tg + 4) * CPV + nb];
            }
#pragma unroll
            for (int mt = 0; mt < 4; mt++)
#pragma unroll
                for (int nt = 0; nt < 3; nt++)
                    mma_tf32(acc[mt][nt], af[mt], bf[nt]);
        }
        __syncthreads();
        if (kb + 2 < nkb) issue(kb + 2);
        CP_COMMIT();
    }

#pragma unroll
    for (int mt = 0; mt < 4; mt++) {
#pragma unroll
        for (int nt = 0; nt < 3; nt++) {
            int row = m0 + wr * 64 + mt * 16 + g;
            int col = h * HD + wc * 24 + nt * 8 + 2 * tg;
            float* p0 = C + ((size_t)b * SS + row) * HH + col;
            float* p1 = C + ((size_t)b * SS + row + 8) * HH + col;
            *(float2*)p0 = make_float2(acc[mt][nt][0], acc[mt][nt][1]);
            *(float2*)p1 = make_float2(acc[mt][nt][2], acc[mt][nt][3]);
        }
    }
}

// ---------------- small SIMT SGEMM (only for ck: N=56) ----------------
__global__ void sgemm_bias(const float* __restrict__ A, const float* __restrict__ W,
                           const float* __restrict__ bias, float* __restrict__ C,
                           int M, int N, int Kd) {
    __shared__ float As[8][132];
    __shared__ float Bs[8][128];
    const int tid  = threadIdx.x;
    const int bx   = blockIdx.x, by = blockIdx.y;
    const int trow = tid >> 4, tcol = tid & 15;
    float acc[8][8];
#pragma unroll
    for (int i = 0; i < 8; i++)
#pragma unroll
        for (int j = 0; j < 8; j++) acc[i][j] = 0.f;

    const int aRow = tid >> 1;
    const int aCol = (tid & 1) * 4;
    const int bRow = tid >> 5;
    const int bCol = (tid & 31) * 4;

    const float* Ap = A + (size_t)(by * 128 + aRow) * Kd + aCol;
    const float* Wp = W + (size_t)bRow * N + bx * 128 + bCol;
    const bool nOK = (bx * 128 + bCol + 3) < N;

    for (int k0 = 0; k0 < Kd; k0 += 8) {
        float4 av = *(const float4*)Ap;
        As[aCol + 0][aRow] = av.x;
        As[aCol + 1][aRow] = av.y;
        As[aCol + 2][aRow] = av.z;
        As[aCol + 3][aRow] = av.w;
        float4 bv = nOK ? *(const float4*)Wp : make_float4(0.f, 0.f, 0.f, 0.f);
        *(float4*)&Bs[bRow][bCol] = bv;
        __syncthreads();
#pragma unroll
        for (int kk = 0; kk < 8; kk++) {
            float ar[8], br[8];
            *(float4*)(ar)     = *(const float4*)&As[kk][trow * 8];
            *(float4*)(ar + 4) = *(const float4*)&As[kk][trow * 8 + 4];
            *(float4*)(br)     = *(const float4*)&Bs[kk][tcol * 8];
            *(float4*)(br + 4) = *(const float4*)&Bs[kk][tcol * 8 + 4];
#pragma unroll
            for (int i = 0; i < 8; i++)
#pragma unroll
                for (int j = 0; j < 8; j++) acc[i][j] += ar[i] * br[j];
        }
        __syncthreads();
        Ap += 8;
        Wp += (size_t)8 * N;
    }

    const int row0 = by * 128 + trow * 8;
    const int col0 = bx * 128 + tcol * 8;
#pragma unroll
    for (int i = 0; i < 8; i++) {
#pragma unroll
        for (int j = 0; j < 8; j++) {
            int cc = col0 + j;
            if (cc < N)
                C[(size_t)(row0 + i) * N + cc] = acc[i][j] + bias[cc];
        }
    }
}

// ---------------- depthwise conv ----------------
__global__ void depthwise_conv(const float* __restrict__ X, const float* __restrict__ dw,
                               float* __restrict__ Y) {
    int idx = blockIdx.x * blockDim.x + threadIdx.x;
    if (idx >= MROWS * HH) return;
    int c = idx % HH;
    int s = (idx / HH) % SS;
    int b = idx / (HH * SS);
    float acc = 0.f;
#pragma unroll
    for (int k = 0; k < KK; k++) {
        int ss = s + k - 3;
        if (ss >= 0 && ss < SS)
            acc += X[((size_t)b * SS + ss) * HH + c] * dw[c * KK + k];
    }
    Y[idx] = acc;
}

__global__ void softmax7(float* __restrict__ ck) {
    int idx = blockIdx.x * blockDim.x + threadIdx.x;
    if (idx >= MROWS * NHh) return;
    int row = idx >> 3, h = idx & 7;
    float* p = ck + (size_t)row * 56 + h * 7;
    float m = p[0];
#pragma unroll
    for (int k = 1; k < 7; k++) m = fmaxf(m, p[k]);
    float e[7], s = 0.f;
#pragma unroll
    for (int k = 0; k < 7; k++) { e[k] = expf(p[k] - m); s += e[k]; }
    float inv = 1.f / s;
#pragma unroll
    for (int k = 0; k < 7; k++) p[k] = e[k] * inv;
}

__global__ void span_conv(const float* __restrict__ co, const float* __restrict__ ck,
                          float* __restrict__ ctx) {
    int idx = blockIdx.x * blockDim.x + threadIdx.x;
    if (idx >= MROWS * AHd) return;
    int d = idx % HD;
    int h = (idx / HD) % NHh;
    int s = (idx / AHd) % SS;
    int b = idx / (AHd * SS);
    size_t row = (size_t)b * SS + s;
    const float* w = ck + row * 56 + h * 7;
    float acc = 0.f;
#pragma unroll
    for (int k = 0; k < KK; k++) {
        int ss = s + k - 3;
        if (ss >= 0 && ss < SS)
            acc += co[((size_t)b * SS + ss) * AHd + h * HD + d] * w[k];
    }
    ctx[row * HH + AHd + h * HD + d] = acc;
}

// ---------------- row softmax (warp-shuffle reduce) ----------------
__global__ void softmax_rows(float* __restrict__ Sc) {
    size_t row = blockIdx.x;
    int tid = threadIdx.x;
    int lane = tid & 31, wrp = tid >> 5;
    float4* p = (float4*)(Sc + row * SS);
    float4 v = p[tid];
    __shared__ float red[8];

    float m = fmaxf(fmaxf(v.x, v.y), fmaxf(v.z, v.w));
#pragma unroll
    for (int o = 16; o > 0; o >>= 1) m = fmaxf(m, __shfl_xor_sync(0xffffffffu, m, o));
    if (lane == 0) red[wrp] = m;
    __syncthreads();
    m = red[lane & 7];
#pragma unroll
    for (int o = 4; o > 0; o >>= 1) m = fmaxf(m, __shfl_xor_sync(0xffffffffu, m, o));

    v.x = expf(v.x - m); v.y = expf(v.y - m); v.z = expf(v.z - m); v.w = expf(v.w - m);
    float s = v.x + v.y + v.z + v.w;
#pragma unroll
    for (int o = 16; o > 0; o >>= 1) s += __shfl_xor_sync(0xffffffffu, s, o);
    __syncthreads();
    if (lane == 0) red[wrp] = s;
    __syncthreads();
    s = red[lane & 7];
#pragma unroll
    for (int o = 4; o > 0; o >>= 1) s += __shfl_xor_sync(0xffffffffu, s, o);

    float inv = 1.f / s;
    v.x *= inv; v.y *= inv; v.z *= inv; v.w *= inv;
    p[tid] = v;
}

// ---------------- fused residual + LayerNorm ----------------
__global__ void ln_residual(const float* __restrict__ X, const float* __restrict__ R,
                            const float* __restrict__ gam, const float* __restrict__ bet,
                            float* __restrict__ O) {
    size_t row = blockIdx.x;
    int tid = threadIdx.x;
    const float* x = X + row * HH;
    const float* r = R + row * HH;
    __shared__ float red[256];
    float vals[6];
    float s = 0.f;
#pragma unroll
    for (int t = 0; t < 6; t++) {
        int c = tid + t * 256;
        vals[t] = x[c] + r[c];
        s += vals[t];
    }
    red[tid] = s;
    __syncthreads();
    for (int o = 128; o > 0; o >>= 1) {
        if (tid < o) red[tid] += red[tid + o];
        __syncthreads();
    }
    float mean = red[0] * (1.f / HH);
    __syncthreads();
    float s2 = 0.f;
#pragma unroll
    for (int t = 0; t < 6; t++) {
        float d = vals[t] - mean;
        s2 += d * d;
    }
    red[tid] = s2;
    __syncthreads();
    for (int o = 128; o > 0; o >>= 1) {
        if (tid < o) red[tid] += red[tid + o];
        __syncthreads();
    }
    float rstd = rsqrtf(red[0] * (1.f / HH) + 1e-12f);
#pragma unroll
    for (int t = 0; t < 6; t++) {
        int c = tid + t * 256;
        O[row * HH + c] = (vals[t] - mean) * rstd * gam[c] + bet[c];
    }
}

// ---------------- global max-pool + decoder ----------------
__global__ void maxpool_seq(const float* __restrict__ L, float* __restrict__ pooled) {
    int idx = blockIdx.x * blockDim.x + threadIdx.x;
    if (idx >= MB * HH) return;
    int c = idx % HH, b = idx / HH;
    const float* base = L + (size_t)b * SS * HH + c;
    float m = -3.4e38f;
    for (int s = 0; s < SS; s++) m = fmaxf(m, base[(size_t)s * HH]);
    pooled[idx] = m;
}

__global__ void decode(const float* __restrict__ pooled, const float* __restrict__ wd,
                       const float* __restrict__ bd, float* __restrict__ out) {
    int b = blockIdx.x;
    int tid = threadIdx.x;
    __shared__ float red[256];
    float part = 0.f;
    for (int c = tid; c < HH; c += 256) part += pooled[b * HH + c] * wd[c];
    red[tid] = part;
    __syncthreads();
    for (int o = 128; o > 0; o >>= 1) {
        if (tid < o) red[tid] += red[tid + o];
        __syncthreads();
    }
    if (tid == 0) out[b] = red[0] + bd[0];
}

// ============================================================================
// Host launcher
// ============================================================================
extern "C" void kernel_launch(void* const* d_in, const int* in_sizes, int n_in,
                              void* d_out, int out_size) {
    const float* embed = (const float*)d_in[0];
    const float* wq  = (const float*)d_in[1];  const float* bq  = (const float*)d_in[2];
    const float* wk  = (const float*)d_in[3];  const float* bk  = (const float*)d_in[4];
    const float* wv  = (const float*)d_in[5];  const float* bv  = (const float*)d_in[6];
    const float* dw  = (const float*)d_in[7];
    const float* pw  = (const float*)d_in[8];  const float* sep_b = (const float*)d_in[9];
    const float* wck = (const float*)d_in[10]; const float* bck = (const float*)d_in[11];
    const float* wco = (const float*)d_in[12]; const float* bco = (const float*)d_in[13];
    const float* wso = (const float*)d_in[14]; const float* bso = (const float*)d_in[15];
    const float* ln1_g = (const float*)d_in[16]; const float* ln1_b = (const float*)d_in[17];
    const float* wi  = (const float*)d_in[18]; const float* bi  = (const float*)d_in[19];
    const float* wo  = (const float*)d_in[20]; const float* bo  = (const float*)d_in[21];
    const float* ln2_g = (const float*)d_in[22]; const float* ln2_b = (const float*)d_in[23];
    const float* wd  = (const float*)d_in[24]; const float* bd  = (const float*)d_in[25];
    float* out = (float*)d_out;

    cudaFuncSetAttribute(mma_gemm, cudaFuncAttributeMaxDynamicSharedMemorySize, GEMM_SMEM);
    cudaFuncSetAttribute(mma_gemm_multi, cudaFuncAttributeMaxDynamicSharedMemorySize, GEMM_SMEM);
    cudaFuncSetAttribute(attn_scores_mma, cudaFuncAttributeMaxDynamicSharedMemorySize, SC_SMEM);
    cudaFuncSetAttribute(attn_ctx_mma, cudaFuncAttributeMaxDynamicSharedMemorySize, CTX_SMEM);

    float *q, *k, *v, *co, *dconv, *sep, *ck, *scores, *ctx, *tmp, *inter, *attn, *layer, *pool;
    cudaGetSymbolAddress((void**)&q, g_q);
    cudaGetSymbolAddress((void**)&k, g_k);
    cudaGetSymbolAddress((void**)&v, g_v);
    cudaGetSymbolAddress((void**)&co, g_co);
    cudaGetSymbolAddress((void**)&dconv, g_dconv);
    cudaGetSymbolAddress((void**)&sep, g_sep);
    cudaGetSymbolAddress((void**)&ck, g_ck);
    cudaGetSymbolAddress((void**)&scores, g_scores);
    cudaGetSymbolAddress((void**)&ctx, g_ctx);
    cudaGetSymbolAddress((void**)&tmp, g_tmp);
    cudaGetSymbolAddress((void**)&inter, g_inter);
    cudaGetSymbolAddress((void**)&attn, g_attn);
    cudaGetSymbolAddress((void**)&layer, g_layer);
    cudaGetSymbolAddress((void**)&pool, g_pool);

    dim3 blk(256);

    // ---- fused q/k/v/co projections (one launch, grid.z picks weights) ----
    GemmSet sq = {wq, bq, q}, sk = {wk, bk, k}, sv = {wv, bv, v}, sc = {wco, bco, co};
    dim3 gm(AHd / 128, MROWS / 128, 4);
    mma_gemm_multi<<<gm, blk, GEMM_SMEM>>>(embed, sq, sk, sv, sc, AHd, HH);

    // ---- separable conv; pointwise gemm fuses conv_attn = sep*q (op=2) ----
    depthwise_conv<<<(MROWS * HH + 255) / 256, blk>>>(embed, dw, dconv);
    dim3 gproj(AHd / 128, MROWS / 128);
    mma_gemm<<<gproj, blk, GEMM_SMEM>>>(dconv, pw, sep_b, sep, q, AHd, HH, 2);

    // span kernels (N=56 -> SIMT gemm)
    dim3 gck(1, MROWS / 128);
    sgemm_bias<<<gck, blk>>>(sep, wck, bck, ck, MROWS, 56, AHd);
    softmax7<<<(MROWS * NHh + 255) / 256, blk>>>(ck);
    span_conv<<<(MROWS * AHd + 255) / 256, blk>>>(co, ck, ctx);

    // ---- self-attention (tensor path) ----
    dim3 gsc(SS / 128, SS / 128, MB * NHh);
    attn_scores_mma<<<gsc, blk, SC_SMEM>>>(q, k, scores);
    softmax_rows<<<MB * NHh * SS, blk>>>(scores);
    dim3 gcx(SS / 128, MB * NHh);
    attn_ctx_mma<<<gcx, blk, CTX_SMEM>>>(scores, v, ctx);

    // ---- self output + LN1 ----
    dim3 gso(HH / 128, MROWS / 128);
    mma_gemm<<<gso, blk, GEMM_SMEM>>>(ctx, wso, bso, tmp, nullptr, HH, HH, 0);
    ln_residual<<<MROWS, blk>>>(tmp, embed, ln1_g, ln1_b, attn);

    // ---- FFN ----
    dim3 gin(IM / 128, MROWS / 128);
    mma_gemm<<<gin, blk, GEMM_SMEM>>>(attn, wi, bi, inter, nullptr, IM, HH, 1);
    mma_gemm<<<gso, blk, GEMM_SMEM>>>(inter, wo, bo, tmp, nullptr, HH, IM, 0);
    ln_residual<<<MROWS, blk>>>(tmp, attn, ln2_g, ln2_b, layer);

    // ---- pool + decode ----
    maxpool_seq<<<(MB * HH + 255) / 256, blk>>>(layer, pool);
    decode<<<MB, blk>>>(pool, wd, bd, out);
}

// round 6
// speedup vs baseline: 4.1457x; 1.0917x over previous
#include <cuda_runtime.h>
#include <math.h>
#include <stdint.h>

// ---------------- problem dims ----------------
#define MB   8
#define SS   1024
#define HH   1536
#define NHh  8
#define HD   96
#define AHd  768
#define KK   7
#define IM   3072
#define MROWS (MB*SS)          // 8192

// ---------------- scratch ----------------
__device__ float g_q   [MROWS*AHd];
__device__ float g_k   [MROWS*AHd];
__device__ float g_v   [MROWS*AHd];
__device__ float g_co  [MROWS*AHd];
__device__ float g_dconv[MROWS*HH];
__device__ float g_sep [MROWS*AHd];
__device__ float g_ck  [MROWS*56];
__device__ float g_ctx [MROWS*HH];
__device__ float g_tmp [MROWS*HH];
__device__ float g_inter[MROWS*IM];
__device__ float g_attn[MROWS*HH];
__device__ float g_layer[MROWS*HH];
__device__ float g_poolp[MB*8*HH];

// ---------------- PTX helpers ----------------
__device__ __forceinline__ uint32_t sptr(const void* p) {
    return (uint32_t)__cvta_generic_to_shared(p);
}
#define CP16(dst, src) \
    asm volatile("cp.async.cg.shared.global [%0], [%1], 16;" :: "r"(dst), "l"(src))
#define CP_COMMIT() asm volatile("cp.async.commit_group;" ::: "memory")
#define CP_WAIT(n)  asm volatile("cp.async.wait_group %0;" :: "n"(n) : "memory")

__device__ __forceinline__ void mma_tf32(float* d, const uint32_t* a, const uint32_t* b) {
    asm volatile(
        "mma.sync.aligned.m16n8k8.row.col.f32.tf32.tf32.f32 "
        "{%0,%1,%2,%3}, {%4,%5,%6,%7}, {%8,%9}, {%0,%1,%2,%3};"
        : "+f"(d[0]), "+f"(d[1]), "+f"(d[2]), "+f"(d[3])
        : "r"(a[0]), "r"(a[1]), "r"(a[2]), "r"(a[3]), "r"(b[0]), "r"(b[1]));
}

// ============================================================================
// tf32 mma GEMM, 2-stage cp.async pipeline, 2 CTAs/SM.
// op: 0 = bias, 1 = bias+gelu, 2 = (x+bias)*aux
// ============================================================================
#define PA   36
#define PB   136
#define ASZ  (128*PA)
#define BSZ  (32*PB)
#define NSTG 2
#define GEMM_SMEM (NSTG*(ASZ+BSZ)*4)

struct GemmSet { const float* W; const float* bias; float* C; };

__device__ __forceinline__ void gemm_body(
    const float* __restrict__ A, const float* __restrict__ W,
    const float* __restrict__ bias, float* __restrict__ C,
    const float* __restrict__ aux,
    int N, int Kd, int op, int m0, int n0, float* sm)
{
    float* Abase = sm;
    float* Bbase = sm + NSTG * ASZ;

    const int tid = threadIdx.x;
    const int wid = tid >> 5, lane = tid & 31;
    const int wr = wid >> 2, wc = wid & 3;
    const int g = lane >> 2, tg = lane & 3;
    const int nkb = Kd >> 5;

    float acc[4][4][4];
#pragma unroll
    for (int i = 0; i < 4; i++)
#pragma unroll
        for (int j = 0; j < 4; j++)
#pragma unroll
            for (int c = 0; c < 4; c++) acc[i][j][c] = 0.f;

    auto issue = [&](int kb) {
        int s = kb % NSTG;
        float* As = Abase + s * ASZ;
        float* Bs = Bbase + s * BSZ;
        const float* ag = A + (size_t)m0 * Kd + kb * 32;
        const float* bg = W + (size_t)(kb * 32) * N + n0;
#pragma unroll
        for (int t = 0; t < 4; t++) {
            int sA = tid + t * 256;
            int r  = sA >> 3,  c  = (sA & 7) << 2;
            CP16(sptr(As + r * PA + c), ag + (size_t)r * Kd + c);
            int rb = sA >> 5,  cb = (sA & 31) << 2;
            CP16(sptr(Bs + rb * PB + cb), bg + (size_t)rb * N + cb);
        }
    };

    issue(0); CP_COMMIT();
    issue(1); CP_COMMIT();

    for (int kb = 0; kb < nkb; kb++) {
        CP_WAIT(1);
        __syncthreads();
        int s = kb % NSTG;
        const uint32_t* As = (const uint32_t*)(Abase + s * ASZ);
        const uint32_t* Bs = (const uint32_t*)(Bbase + s * BSZ);
#pragma unroll
        for (int kk = 0; kk < 32; kk += 8) {
            uint32_t af[4][4], bf[4][2];
#pragma unroll
            for (int mt = 0; mt < 4; mt++) {
                int mb = wr * 64 + mt * 16 + g;
                af[mt][0] = As[mb * PA + kk + tg];
                af[mt][1] = As[(mb + 8) * PA + kk + tg];
                af[mt][2] = As[mb * PA + kk + tg + 4];
                af[mt][3] = As[(mb + 8) * PA + kk + tg + 4];
            }
#pragma unroll
            for (int nt = 0; nt < 4; nt++) {
                int nb = wc * 32 + nt * 8 + g;
                bf[nt][0] = Bs[(kk + tg) * PB + nb];
                bf[nt][1] = Bs[(kk + tg + 4) * PB + nb];
            }
#pragma unroll
            for (int mt = 0; mt < 4; mt++)
#pragma unroll
                for (int nt = 0; nt < 4; nt++)
                    mma_tf32(acc[mt][nt], af[mt], bf[nt]);
        }
        __syncthreads();
        if (kb + 2 < nkb) issue(kb + 2);
        CP_COMMIT();
    }

#pragma unroll
    for (int mt = 0; mt < 4; mt++) {
#pragma unroll
        for (int nt = 0; nt < 4; nt++) {
            int row = m0 + wr * 64 + mt * 16 + g;
            int col = n0 + wc * 32 + nt * 8 + 2 * tg;
            float b0 = bias[col], b1 = bias[col + 1];
            float v0 = acc[mt][nt][0] + b0;
            float v1 = acc[mt][nt][1] + b1;
            float v2 = acc[mt][nt][2] + b0;
            float v3 = acc[mt][nt][3] + b1;
            if (op == 1) {
                v0 = 0.5f * v0 * (1.f + erff(v0 * 0.70710678118654752f));
                v1 = 0.5f * v1 * (1.f + erff(v1 * 0.70710678118654752f));
                v2 = 0.5f * v2 * (1.f + erff(v2 * 0.70710678118654752f));
                v3 = 0.5f * v3 * (1.f + erff(v3 * 0.70710678118654752f));
            } else if (op == 2) {
                const float* a0 = aux + (size_t)row * N + col;
                const float* a1 = aux + (size_t)(row + 8) * N + col;
                v0 *= a0[0]; v1 *= a0[1]; v2 *= a1[0]; v3 *= a1[1];
            }
            *(float2*)(C + (size_t)row * N + col)       = make_float2(v0, v1);
            *(float2*)(C + (size_t)(row + 8) * N + col) = make_float2(v2, v3);
        }
    }
}

__global__ void __launch_bounds__(256, 2) mma_gemm(
    const float* __restrict__ A, const float* __restrict__ W,
    const float* __restrict__ bias, float* __restrict__ C,
    const float* __restrict__ aux, int N, int Kd, int op)
{
    extern __shared__ float sm[];
    gemm_body(A, W, bias, C, aux, N, Kd, op, blockIdx.y * 128, blockIdx.x * 128, sm);
}

__global__ void __launch_bounds__(256, 2) mma_gemm_multi(
    const float* __restrict__ A, GemmSet s0, GemmSet s1, GemmSet s2, GemmSet s3,
    int N, int Kd)
{
    extern __shared__ float sm[];
    GemmSet s = (blockIdx.z == 0) ? s0 : (blockIdx.z == 1) ? s1 : (blockIdx.z == 2) ? s2 : s3;
    gemm_body(A, s.W, s.bias, s.C, nullptr, N, Kd, 0, blockIdx.y * 128, blockIdx.x * 128, sm);
}

// ============================================================================
// Fused flash attention: per (q-tile, bz) CTA.
// Q tile resident; loop 8 K/V tiles; S-mma in regs; online softmax;
// P stored into K's smem (K dead); P@V mma accumulates O.
// ============================================================================
#define FQP 100
#define FKP 132
#define FVP 104
#define FL_SMEM ((128*FQP + 128*FKP + 128*FVP + 2*128*4)*4)

__global__ void __launch_bounds__(256) flash_attn(
    const float* __restrict__ Q, const float* __restrict__ K,
    const float* __restrict__ V, float* __restrict__ C)
{
    extern __shared__ float sm[];
    float* Qs   = sm;
    float* Ks   = Qs + 128 * FQP;
    float* Vs   = Ks + 128 * FKP;
    float* redm = Vs + 128 * FVP;      // [128][4]
    float* reds = redm + 128 * 4;      // [128][4]

    const int tid = threadIdx.x;
    const int wid = tid >> 5, lane = tid & 31;
    const int wr = wid >> 2, wc = wid & 3;
    const int g = lane >> 2, tg = lane & 3;
    const int bz = blockIdx.y, b = bz >> 3, h = bz & 7;
    const int m0 = blockIdx.x * 128;

    const float* qg = Q + (size_t)b * SS * AHd + h * HD;
    const float* kg = K + (size_t)b * SS * AHd + h * HD;
    const float* vg = V + (size_t)b * SS * AHd + h * HD;

    // load Q tile
#pragma unroll
    for (int t = 0; t < 12; t++) {
        int s = tid + t * 256;
        int r = s / 24, cc = (s % 24) * 4;
        CP16(sptr(Qs + r * FQP + cc), qg + (size_t)(m0 + r) * AHd + cc);
    }
    CP_COMMIT();

    float m_i[4][2], l_i[4][2];
    float acc_o[4][3][4];
#pragma unroll
    for (int i = 0; i < 4; i++) {
        m_i[i][0] = m_i[i][1] = -1e30f;
        l_i[i][0] = l_i[i][1] = 0.f;
#pragma unroll
        for (int j = 0; j < 3; j++)
#pragma unroll
            for (int c = 0; c < 4; c++) acc_o[i][j][c] = 0.f;
    }

    for (int kt = 0; kt < 8; kt++) {
        // load K tile (group), then V tile (group)
#pragma unroll
        for (int t = 0; t < 12; t++) {
            int s = tid + t * 256;
            int r = s / 24, cc = (s % 24) * 4;
            CP16(sptr(Ks + r * FKP + cc), kg + (size_t)(kt * 128 + r) * AHd + cc);
        }
        CP_COMMIT();
#pragma unroll
        for (int t = 0; t < 12; t++) {
            int s = tid + t * 256;
            int r = s / 24, cc = (s % 24) * 4;
            CP16(sptr(Vs + r * FVP + cc), vg + (size_t)(kt * 128 + r) * AHd + cc);
        }
        CP_COMMIT();
        CP_WAIT(1);                 // K (and Q on first iter) arrived
        __syncthreads();

        // ---- S = Q K^T ----
        float sa[4][4][4];
#pragma unroll
        for (int i = 0; i < 4; i++)
#pragma unroll
            for (int j = 0; j < 4; j++)
#pragma unroll
                for (int c = 0; c < 4; c++) sa[i][j][c] = 0.f;

        const uint32_t* Qu = (const uint32_t*)Qs;
        const uint32_t* Ku = (const uint32_t*)Ks;
#pragma unroll
        for (int kk = 0; kk < 96; kk += 8) {
            uint32_t af[4][4], bf[4][2];
#pragma unroll
            for (int mt = 0; mt < 4; mt++) {
                int mb = wr * 64 + mt * 16 + g;
                af[mt][0] = Qu[mb * FQP + kk + tg];
                af[mt][1] = Qu[(mb + 8) * FQP + kk + tg];
                af[mt][2] = Qu[mb * FQP + kk + tg + 4];
                af[mt][3] = Qu[(mb + 8) * FQP + kk + tg + 4];
            }
#pragma unroll
            for (int nt = 0; nt < 4; nt++) {
                int nb = wc * 32 + nt * 8 + g;
                bf[nt][0] = Ku[nb * FKP + kk + tg];
                bf[nt][1] = Ku[nb * FKP + kk + tg + 4];
            }
#pragma unroll
            for (int mt = 0; mt < 4; mt++)
#pragma unroll
                for (int nt = 0; nt < 4; nt++)
                    mma_tf32(sa[mt][nt], af[mt], bf[nt]);
        }
        const float scale = 0.10206207261596576f;
#pragma unroll
        for (int mt = 0; mt < 4; mt++)
#pragma unroll
            for (int nt = 0; nt < 4; nt++)
#pragma unroll
                for (int c = 0; c < 4; c++) sa[mt][nt][c] *= scale;

        // ---- row max: warp-local (nt, tg) then cross-wc via smem ----
        float rmax[4][2];
#pragma unroll
        for (int mt = 0; mt < 4; mt++) {
            float m0v = fmaxf(sa[mt][0][0], sa[mt][0][1]);
            float m1v = fmaxf(sa[mt][0][2], sa[mt][0][3]);
#pragma unroll
            for (int nt = 1; nt < 4; nt++) {
                m0v = fmaxf(m0v, fmaxf(sa[mt][nt][0], sa[mt][nt][1]));
                m1v = fmaxf(m1v, fmaxf(sa[mt][nt][2], sa[mt][nt][3]));
            }
            m0v = fmaxf(m0v, __shfl_xor_sync(0xffffffffu, m0v, 1));
            m0v = fmaxf(m0v, __shfl_xor_sync(0xffffffffu, m0v, 2));
            m1v = fmaxf(m1v, __shfl_xor_sync(0xffffffffu, m1v, 1));
            m1v = fmaxf(m1v, __shfl_xor_sync(0xffffffffu, m1v, 2));
            rmax[mt][0] = m0v; rmax[mt][1] = m1v;
        }
        if (tg == 0) {
#pragma unroll
            for (int mt = 0; mt < 4; mt++) {
                int r0 = wr * 64 + mt * 16 + g;
                redm[r0 * 4 + wc] = rmax[mt][0];
                redm[(r0 + 8) * 4 + wc] = rmax[mt][1];
            }
        }
        __syncthreads();   // also: all warps done reading Ks (safe to overwrite later)

        float alpha[4][2], mnew[4][2];
#pragma unroll
        for (int mt = 0; mt < 4; mt++) {
#pragma unroll
            for (int hf = 0; hf < 2; hf++) {
                int row = wr * 64 + mt * 16 + g + hf * 8;
                float4 r4 = *(float4*)&redm[row * 4];
                float gm = fmaxf(fmaxf(r4.x, r4.y), fmaxf(r4.z, r4.w));
                float mn = fmaxf(m_i[mt][hf], gm);
                alpha[mt][hf] = __expf(m_i[mt][hf] - mn);
                mnew[mt][hf] = mn;
                m_i[mt][hf] = mn;
            }
        }

        // ---- P = exp(S - m), rowsum ----
        float rsum[4][2];
#pragma unroll
        for (int mt = 0; mt < 4; mt++) { rsum[mt][0] = 0.f; rsum[mt][1] = 0.f; }
#pragma unroll
        for (int mt = 0; mt < 4; mt++)
#pragma unroll
            for (int nt = 0; nt < 4; nt++) {
                sa[mt][nt][0] = __expf(sa[mt][nt][0] - mnew[mt][0]);
                sa[mt][nt][1] = __expf(sa[mt][nt][1] - mnew[mt][0]);
                sa[mt][nt][2] = __expf(sa[mt][nt][2] - mnew[mt][1]);
                sa[mt][nt][3] = __expf(sa[mt][nt][3] - mnew[mt][1]);
                rsum[mt][0] += sa[mt][nt][0] + sa[mt][nt][1];
                rsum[mt][1] += sa[mt][nt][2] + sa[mt][nt][3];
            }
#pragma unroll
        for (int mt = 0; mt < 4; mt++) {
            rsum[mt][0] += __shfl_xor_sync(0xffffffffu, rsum[mt][0], 1);
            rsum[mt][0] += __shfl_xor_sync(0xffffffffu, rsum[mt][0], 2);
            rsum[mt][1] += __shfl_xor_sync(0xffffffffu, rsum[mt][1], 1);
            rsum[mt][1] += __shfl_xor_sync(0xffffffffu, rsum[mt][1], 2);
        }
        if (tg == 0) {
#pragma unroll
            for (int mt = 0; mt < 4; mt++) {
                int r0 = wr * 64 + mt * 16 + g;
                reds[r0 * 4 + wc] = rsum[mt][0];
                reds[(r0 + 8) * 4 + wc] = rsum[mt][1];
            }
        }
        __syncthreads();
#pragma unroll
        for (int mt = 0; mt < 4; mt++) {
#pragma unroll
            for (int hf = 0; hf < 2; hf++) {
                int row = wr * 64 + mt * 16 + g + hf * 8;
                float4 r4 = *(float4*)&reds[row * 4];
                float rs = r4.x + r4.y + r4.z + r4.w;
                l_i[mt][hf] = l_i[mt][hf] * alpha[mt][hf] + rs;
            }
#pragma unroll
            for (int nt = 0; nt < 3; nt++) {
                acc_o[mt][nt][0] *= alpha[mt][0];
                acc_o[mt][nt][1] *= alpha[mt][0];
                acc_o[mt][nt][2] *= alpha[mt][1];
                acc_o[mt][nt][3] *= alpha[mt][1];
            }
        }

        // ---- store P into Ks region ----
#pragma unroll
        for (int mt = 0; mt < 4; mt++)
#pragma unroll
            for (int nt = 0; nt < 4; nt++) {
                int row = wr * 64 + mt * 16 + g;
                int col = wc * 32 + nt * 8 + 2 * tg;
                *(float2*)&Ks[row * FKP + col] = make_float2(sa[mt][nt][0], sa[mt][nt][1]);
                *(float2*)&Ks[(row + 8) * FKP + col] = make_float2(sa[mt][nt][2], sa[mt][nt][3]);
            }
        CP_WAIT(0);        // V tile arrived
        __syncthreads();   // P complete + V visible

        // ---- O += P @ V ----
        const uint32_t* Pu = (const uint32_t*)Ks;
        const uint32_t* Vu = (const uint32_t*)Vs;
#pragma unroll
        for (int kk = 0; kk < 128; kk += 8) {
            uint32_t af[4][4], bf[3][2];
#pragma unroll
            for (int mt = 0; mt < 4; mt++) {
                int mb = wr * 64 + mt * 16 + g;
                af[mt][0] = Pu[mb * FKP + kk + tg];
                af[mt][1] = Pu[(mb + 8) * FKP + kk + tg];
                af[mt][2] = Pu[mb * FKP + kk + tg + 4];
                af[mt][3] = Pu[(mb + 8) * FKP + kk + tg + 4];
            }
#pragma unroll
            for (int nt = 0; nt < 3; nt++) {
                int nb = wc * 24 + nt * 8 + g;
                bf[nt][0] = Vu[(kk + tg) * FVP + nb];
                bf[nt][1] = Vu[(kk + tg + 4) * FVP + nb];
            }
#pragma unroll
            for (int mt = 0; mt < 4; mt++)
#pragma unroll
                for (int nt = 0; nt < 3; nt++)
                    mma_tf32(acc_o[mt][nt], af[mt], bf[nt]);
        }
        __syncthreads();   // done with Ks/Vs before next tile's loads
    }

    // ---- write O / l ----
#pragma unroll
    for (int mt = 0; mt < 4; mt++) {
        float inv0 = 1.f / l_i[mt][0];
        float inv1 = 1.f / l_i[mt][1];
#pragma unroll
        for (int nt = 0; nt < 3; nt++) {
            int row = m0 + wr * 64 + mt * 16 + g;
            int col = h * HD + wc * 24 + nt * 8 + 2 * tg;
            float* p0 = C + ((size_t)b * SS + row) * HH + col;
            float* p1 = C + ((size_t)b * SS + row + 8) * HH + col;
            *(float2*)p0 = make_float2(acc_o[mt][nt][0] * inv0, acc_o[mt][nt][1] * inv0);
            *(float2*)p1 = make_float2(acc_o[mt][nt][2] * inv1, acc_o[mt][nt][3] * inv1);
        }
    }
}

// ============================================================================
// ck GEMM: C[8192,56] = A[8192,768] @ W[768,56] + bias.  BM=32 -> 256 CTAs.
// ============================================================================
__global__ void __launch_bounds__(256) ck_gemm(
    const float* __restrict__ A, const float* __restrict__ W,
    const float* __restrict__ bias, float* __restrict__ C)
{
    __shared__ float As[32 * 68];
    __shared__ float Ws[64 * 60];
    const int tid = threadIdx.x;
    const int m0 = blockIdx.x * 32;
    const int rg = tid / 56, c = tid % 56;   // rg<4 active for compute
    float acc[8];
#pragma unroll
    for (int r = 0; r < 8; r++) acc[r] = 0.f;

    for (int k0 = 0; k0 < AHd; k0 += 64) {
#pragma unroll
        for (int t = 0; t < 2; t++) {
            int f = tid + t * 256;               // 0..511
            int r = f >> 4, cc = (f & 15) << 2;
            *(float4*)&As[r * 68 + cc] = *(const float4*)(A + (size_t)(m0 + r) * AHd + k0 + cc);
        }
#pragma unroll
        for (int t = 0; t < 4; t++) {
            int f = tid + t * 256;
            if (f < 896) {
                int r = f / 14, cc = (f % 14) << 2;
                *(float4*)&Ws[r * 60 + cc] = *(const float4*)(W + (size_t)(k0 + r) * 56 + cc);
            }
        }
        __syncthreads();
        if (rg < 4) {
#pragma unroll
            for (int kk = 0; kk < 64; kk += 4) {
                float w0 = Ws[kk * 60 + c], w1 = Ws[(kk + 1) * 60 + c];
                float w2 = Ws[(kk + 2) * 60 + c], w3 = Ws[(kk + 3) * 60 + c];
#pragma unroll
                for (int r = 0; r < 8; r++) {
                    float4 a4 = *(const float4*)&As[(rg * 8 + r) * 68 + kk];
                    acc[r] += a4.x * w0 + a4.y * w1 + a4.z * w2 + a4.w * w3;
                }
            }
        }
        __syncthreads();
    }
    if (rg < 4) {
        float bb = bias[c];
#pragma unroll
        for (int r = 0; r < 8; r++)
            C[(size_t)(m0 + rg * 8 + r) * 56 + c] = acc[r] + bb;
    }
}

// ---------------- depthwise conv ----------------
__global__ void depthwise_conv(const float* __restrict__ X, const float* __restrict__ dw,
                               float* __restrict__ Y) {
    int idx = blockIdx.x * blockDim.x + threadIdx.x;
    if (idx >= MROWS * HH) return;
    int c = idx % HH;
    int s = (idx / HH) % SS;
    int b = idx / (HH * SS);
    float acc = 0.f;
#pragma unroll
    for (int k = 0; k < KK; k++) {
        int ss = s + k - 3;
        if (ss >= 0 && ss < SS)
            acc += X[((size_t)b * SS + ss) * HH + c] * dw[c * KK + k];
    }
    Y[idx] = acc;
}

__global__ void softmax7(float* __restrict__ ck) {
    int idx = blockIdx.x * blockDim.x + threadIdx.x;
    if (idx >= MROWS * NHh) return;
    int row = idx >> 3, h = idx & 7;
    float* p = ck + (size_t)row * 56 + h * 7;
    float m = p[0];
#pragma unroll
    for (int k = 1; k < 7; k++) m = fmaxf(m, p[k]);
    float e[7], s = 0.f;
#pragma unroll
    for (int k = 0; k < 7; k++) { e[k] = __expf(p[k] - m); s += e[k]; }
    float inv = 1.f / s;
#pragma unroll
    for (int k = 0; k < 7; k++) p[k] = e[k] * inv;
}

__global__ void span_conv(const float* __restrict__ co, const float* __restrict__ ck,
                          float* __restrict__ ctx) {
    int idx = blockIdx.x * blockDim.x + threadIdx.x;
    if (idx >= MROWS * AHd) return;
    int d = idx % HD;
    int h = (idx / HD) % NHh;
    int s = (idx / AHd) % SS;
    int b = idx / (AHd * SS);
    size_t row = (size_t)b * SS + s;
    const float* w = ck + row * 56 + h * 7;
    float acc = 0.f;
#pragma unroll
    for (int k = 0; k < KK; k++) {
        int ss = s + k - 3;
        if (ss >= 0 && ss < SS)
            acc += co[((size_t)b * SS + ss) * AHd + h * HD + d] * w[k];
    }
    ctx[row * HH + AHd + h * HD + d] = acc;
}

// ---------------- fused residual + LayerNorm ----------------
__global__ void ln_residual(const float* __restrict__ X, const float* __restrict__ R,
                            const float* __restrict__ gam, const float* __restrict__ bet,
                            float* __restrict__ O) {
    size_t row = blockIdx.x;
    int tid = threadIdx.x;
    const float* x = X + row * HH;
    const float* r = R + row * HH;
    __shared__ float red[256];
    float vals[6];
    float s = 0.f;
#pragma unroll
    for (int t = 0; t < 6; t++) {
        int c = tid + t * 256;
        vals[t] = x[c] + r[c];
        s += vals[t];
    }
    red[tid] = s;
    __syncthreads();
    for (int o = 128; o > 0; o >>= 1) {
        if (tid < o) red[tid] += red[tid + o];
        __syncthreads();
    }
    float mean = red[0] * (1.f / HH);
    __syncthreads();
    float s2 = 0.f;
#pragma unroll
    for (int t = 0; t < 6; t++) {
        float d = vals[t] - mean;
        s2 += d * d;
    }
    red[tid] = s2;
    __syncthreads();
    for (int o = 128; o > 0; o >>= 1) {
        if (tid < o) red[tid] += red[tid + o];
        __syncthreads();
    }
    float rstd = rsqrtf(red[0] * (1.f / HH) + 1e-12f);
#pragma unroll
    for (int t = 0; t < 6; t++) {
        int c = tid + t * 256;
        O[row * HH + c] = (vals[t] - mean) * rstd * gam[c] + bet[c];
    }
}

// ---------------- split max-pool + decoder ----------------
__global__ void maxpool_part(const float* __restrict__ L, float* __restrict__ pp) {
    int idx = blockIdx.x * blockDim.x + threadIdx.x;
    if (idx >= MB * 8 * HH) return;
    int c = idx % HH;
    int ch = (idx / HH) & 7;
    int b = idx / (HH * 8);
    const float* base = L + ((size_t)b * SS + ch * 128) * HH + c;
    float m = -3.4e38f;
    for (int s = 0; s < 128; s++) m = fmaxf(m, base[(size_t)s * HH]);
    pp[idx] = m;
}

__global__ void decode2(const float* __restrict__ pp, const float* __restrict__ wd,
                        const float* __restrict__ bd, float* __restrict__ out) {
    int b = blockIdx.x;
    int tid = threadIdx.x;
    __shared__ float red[256];
    float part = 0.f;
    for (int c = tid; c < HH; c += 256) {
        float m = pp[((size_t)b * 8) * HH + c];
#pragma unroll
        for (int ch = 1; ch < 8; ch++)
            m = fmaxf(m, pp[((size_t)b * 8 + ch) * HH + c]);
        part += m * wd[c];
    }
    red[tid] = part;
    __syncthreads();
    for (int o = 128; o > 0; o >>= 1) {
        if (tid < o) red[tid] += red[tid + o];
        __syncthreads();
    }
    if (tid == 0) out[b] = red[0] + bd[0];
}

// ============================================================================
// Host launcher
// ============================================================================
extern "C" void kernel_launch(void* const* d_in, const int* in_sizes, int n_in,
                              void* d_out, int out_size) {
    const float* embed = (const float*)d_in[0];
    const float* wq  = (const float*)d_in[1];  const float* bq  = (const float*)d_in[2];
    const float* wk  = (const float*)d_in[3];  const float* bk  = (const float*)d_in[4];
    const float* wv  = (const float*)d_in[5];  const float* bv  = (const float*)d_in[6];
    const float* dw  = (const float*)d_in[7];
    const float* pw  = (const float*)d_in[8];  const float* sep_b = (const float*)d_in[9];
    const float* wck = (const float*)d_in[10]; const float* bck = (const float*)d_in[11];
    const float* wco = (const float*)d_in[12]; const float* bco = (const float*)d_in[13];
    const float* wso = (const float*)d_in[14]; const float* bso = (const float*)d_in[15];
    const float* ln1_g = (const float*)d_in[16]; const float* ln1_b = (const float*)d_in[17];
    const float* wi  = (const float*)d_in[18]; const float* bi  = (const float*)d_in[19];
    const float* wo  = (const float*)d_in[20]; const float* bo  = (const float*)d_in[21];
    const float* ln2_g = (const float*)d_in[22]; const float* ln2_b = (const float*)d_in[23];
    const float* wd  = (const float*)d_in[24]; const float* bd  = (const float*)d_in[25];
    float* out = (float*)d_out;

    cudaFuncSetAttribute(mma_gemm, cudaFuncAttributeMaxDynamicSharedMemorySize, GEMM_SMEM);
    cudaFuncSetAttribute(mma_gemm_multi, cudaFuncAttributeMaxDynamicSharedMemorySize, GEMM_SMEM);
    cudaFuncSetAttribute(flash_attn, cudaFuncAttributeMaxDynamicSharedMemorySize, FL_SMEM);

    float *q, *k, *v, *co, *dconv, *sep, *ck, *ctx, *tmp, *inter, *attn, *layer, *poolp;
    cudaGetSymbolAddress((void**)&q, g_q);
    cudaGetSymbolAddress((void**)&k, g_k);
    cudaGetSymbolAddress((void**)&v, g_v);
    cudaGetSymbolAddress((void**)&co, g_co);
    cudaGetSymbolAddress((void**)&dconv, g_dconv);
    cudaGetSymbolAddress((void**)&sep, g_sep);
    cudaGetSymbolAddress((void**)&ck, g_ck);
    cudaGetSymbolAddress((void**)&ctx, g_ctx);
    cudaGetSymbolAddress((void**)&tmp, g_tmp);
    cudaGetSymbolAddress((void**)&inter, g_inter);
    cudaGetSymbolAddress((void**)&attn, g_attn);
    cudaGetSymbolAddress((void**)&layer, g_layer);
    cudaGetSymbolAddress((void**)&poolp, g_poolp);

    dim3 blk(256);

    // ---- fused q/k/v/co projections ----
    GemmSet sq = {wq, bq, q}, sk = {wk, bk, k}, sv = {wv, bv, v}, sc = {wco, bco, co};
    dim3 gm(AHd / 128, MROWS / 128, 4);
    mma_gemm_multi<<<gm, blk, GEMM_SMEM>>>(embed, sq, sk, sv, sc, AHd, HH);

    // ---- separable conv; pointwise gemm fuses conv_attn = sep*q ----
    depthwise_conv<<<(MROWS * HH + 255) / 256, blk>>>(embed, dw, dconv);
    dim3 gproj(AHd / 128, MROWS / 128);
    mma_gemm<<<gproj, blk, GEMM_SMEM>>>(dconv, pw, sep_b, sep, q, AHd, HH, 2);

    // ---- span kernels ----
    ck_gemm<<<MROWS / 32, blk>>>(sep, wck, bck, ck);
    softmax7<<<(MROWS * NHh + 255) / 256, blk>>>(ck);
    span_conv<<<(MROWS * AHd + 255) / 256, blk>>>(co, ck, ctx);

    // ---- fused flash attention -> ctx[:, 0:768] ----
    dim3 gfl(SS / 128, MB * NHh);
    flash_attn<<<gfl, blk, FL_SMEM>>>(q, k, v, ctx);

    // ---- self output + LN1 ----
    dim3 gso(HH / 128, MROWS / 128);
    mma_gemm<<<gso, blk, GEMM_SMEM>>>(ctx, wso, bso, tmp, nullptr, HH, HH, 0);
    ln_residual<<<MROWS, blk>>>(tmp, embed, ln1_g, ln1_b, attn);

    // ---- FFN ----
    dim3 gin(IM / 128, MROWS / 128);
    mma_gemm<<<gin, blk, GEMM_SMEM>>>(attn, wi, bi, inter, nullptr, IM, HH, 1);
    mma_gemm<<<gso, blk, GEMM_SMEM>>>(inter, wo, bo, tmp, nullptr, HH, IM, 0);
    ln_residual<<<MROWS, blk>>>(tmp, attn, ln2_g, ln2_b, layer);

    // ---- pool + decode ----
    maxpool_part<<<(MB * 8 * HH + 255) / 256, blk>>>(layer, poolp);
    decode2<<<MB, blk>>>(poolp, wd, bd, out);
}

// round 7
// speedup vs baseline: 4.3282x; 1.0440x over previous
#include <cuda_runtime.h>
#include <math.h>
#include <stdint.h>

// ---------------- problem dims ----------------
#define MB   8
#define SS   1024
#define HH   1536
#define NHh  8
#define HD   96
#define AHd  768
#define KK   7
#define IM   3072
#define MROWS (MB*SS)          // 8192

// ---------------- scratch ----------------
__device__ float g_q   [MROWS*AHd];
__device__ float g_k   [MROWS*AHd];
__device__ float g_v   [MROWS*AHd];
__device__ float g_co  [MROWS*AHd];
__device__ float g_dconv[MROWS*HH];
__device__ float g_sep [MROWS*AHd];
__device__ float g_ck  [MROWS*56];
__device__ float g_ctx [MROWS*HH];
__device__ float g_tmp [MROWS*HH];
__device__ float g_inter[MROWS*IM];
__device__ float g_attn[MROWS*HH];
__device__ float g_layer[MROWS*HH];
__device__ float g_poolp[MB*8*HH];

// ---------------- PTX helpers ----------------
__device__ __forceinline__ uint32_t sptr(const void* p) {
    return (uint32_t)__cvta_generic_to_shared(p);
}
#define CP16(dst, src) \
    asm volatile("cp.async.cg.shared.global [%0], [%1], 16;" :: "r"(dst), "l"(src))
#define CP_COMMIT() asm volatile("cp.async.commit_group;" ::: "memory")
#define CP_WAIT(n)  asm volatile("cp.async.wait_group %0;" :: "n"(n) : "memory")

__device__ __forceinline__ void mma_tf32(float* d, const uint32_t* a, const uint32_t* b) {
    asm volatile(
        "mma.sync.aligned.m16n8k8.row.col.f32.tf32.tf32.f32 "
        "{%0,%1,%2,%3}, {%4,%5,%6,%7}, {%8,%9}, {%0,%1,%2,%3};"
        : "+f"(d[0]), "+f"(d[1]), "+f"(d[2]), "+f"(d[3])
        : "r"(a[0]), "r"(a[1]), "r"(a[2]), "r"(a[3]), "r"(b[0]), "r"(b[1]));
}

// ============================================================================
// tf32 mma GEMM, 3-stage cp.async pipeline (2 loads in flight), 2 CTAs/SM.
// op: 0 = bias, 1 = bias+gelu, 2 = (x+bias)*aux
// ============================================================================
#define PA   36
#define PB   136
#define ASZ  (128*PA)
#define BSZ  (32*PB)
#define NSTG 3
#define GEMM_SMEM (NSTG*(ASZ+BSZ)*4)

struct GemmSet { const float* W; const float* bias; float* C; };

__device__ __forceinline__ void gemm_body(
    const float* __restrict__ A, const float* __restrict__ W,
    const float* __restrict__ bias, float* __restrict__ C,
    const float* __restrict__ aux,
    int N, int Kd, int op, int m0, int n0, float* sm)
{
    float* Abase = sm;
    float* Bbase = sm + NSTG * ASZ;

    const int tid = threadIdx.x;
    const int wid = tid >> 5, lane = tid & 31;
    const int wr = wid >> 2, wc = wid & 3;
    const int g = lane >> 2, tg = lane & 3;
    const int nkb = Kd >> 5;

    float acc[4][4][4];
#pragma unroll
    for (int i = 0; i < 4; i++)
#pragma unroll
        for (int j = 0; j < 4; j++)
#pragma unroll
            for (int c = 0; c < 4; c++) acc[i][j][c] = 0.f;

    auto issue = [&](int kb) {
        int s = kb % NSTG;
        float* As = Abase + s * ASZ;
        float* Bs = Bbase + s * BSZ;
        const float* ag = A + (size_t)m0 * Kd + kb * 32;
        const float* bg = W + (size_t)(kb * 32) * N + n0;
#pragma unroll
        for (int t = 0; t < 4; t++) {
            int sA = tid + t * 256;
            int r  = sA >> 3,  c  = (sA & 7) << 2;
            CP16(sptr(As + r * PA + c), ag + (size_t)r * Kd + c);
            int rb = sA >> 5,  cb = (sA & 31) << 2;
            CP16(sptr(Bs + rb * PB + cb), bg + (size_t)rb * N + cb);
        }
    };

    issue(0); CP_COMMIT();
    issue(1); CP_COMMIT();
    issue(2); CP_COMMIT();

    for (int kb = 0; kb < nkb; kb++) {
        CP_WAIT(2);
        __syncthreads();
        int s = kb % NSTG;
        const uint32_t* As = (const uint32_t*)(Abase + s * ASZ);
        const uint32_t* Bs = (const uint32_t*)(Bbase + s * BSZ);
#pragma unroll
        for (int kk = 0; kk < 32; kk += 8) {
            uint32_t af[4][4], bf[4][2];
#pragma unroll
            for (int mt = 0; mt < 4; mt++) {
                int mb = wr * 64 + mt * 16 + g;
                af[mt][0] = As[mb * PA + kk + tg];
                af[mt][1] = As[(mb + 8) * PA + kk + tg];
                af[mt][2] = As[mb * PA + kk + tg + 4];
                af[mt][3] = As[(mb + 8) * PA + kk + tg + 4];
            }
#pragma unroll
            for (int nt = 0; nt < 4; nt++) {
                int nb = wc * 32 + nt * 8 + g;
                bf[nt][0] = Bs[(kk + tg) * PB + nb];
                bf[nt][1] = Bs[(kk + tg + 4) * PB + nb];
            }
#pragma unroll
            for (int mt = 0; mt < 4; mt++)
#pragma unroll
                for (int nt = 0; nt < 4; nt++)
                    mma_tf32(acc[mt][nt], af[mt], bf[nt]);
        }
        __syncthreads();
        if (kb + 3 < nkb) issue(kb + 3);
        CP_COMMIT();
    }

#pragma unroll
    for (int mt = 0; mt < 4; mt++) {
#pragma unroll
        for (int nt = 0; nt < 4; nt++) {
            int row = m0 + wr * 64 + mt * 16 + g;
            int col = n0 + wc * 32 + nt * 8 + 2 * tg;
            float b0 = bias[col], b1 = bias[col + 1];
            float v0 = acc[mt][nt][0] + b0;
            float v1 = acc[mt][nt][1] + b1;
            float v2 = acc[mt][nt][2] + b0;
            float v3 = acc[mt][nt][3] + b1;
            if (op == 1) {
                v0 = 0.5f * v0 * (1.f + erff(v0 * 0.70710678118654752f));
                v1 = 0.5f * v1 * (1.f + erff(v1 * 0.70710678118654752f));
                v2 = 0.5f * v2 * (1.f + erff(v2 * 0.70710678118654752f));
                v3 = 0.5f * v3 * (1.f + erff(v3 * 0.70710678118654752f));
            } else if (op == 2) {
                const float* a0 = aux + (size_t)row * N + col;
                const float* a1 = aux + (size_t)(row + 8) * N + col;
                v0 *= a0[0]; v1 *= a0[1]; v2 *= a1[0]; v3 *= a1[1];
            }
            *(float2*)(C + (size_t)row * N + col)       = make_float2(v0, v1);
            *(float2*)(C + (size_t)(row + 8) * N + col) = make_float2(v2, v3);
        }
    }
}

__global__ void __launch_bounds__(256, 2) mma_gemm(
    const float* __restrict__ A, const float* __restrict__ W,
    const float* __restrict__ bias, float* __restrict__ C,
    const float* __restrict__ aux, int N, int Kd, int op)
{
    extern __shared__ float sm[];
    gemm_body(A, W, bias, C, aux, N, Kd, op, blockIdx.y * 128, blockIdx.x * 128, sm);
}

__global__ void __launch_bounds__(256, 2) mma_gemm_multi(
    const float* __restrict__ A, GemmSet s0, GemmSet s1, GemmSet s2, GemmSet s3,
    int N, int Kd)
{
    extern __shared__ float sm[];
    GemmSet s = (blockIdx.z == 0) ? s0 : (blockIdx.z == 1) ? s1 : (blockIdx.z == 2) ? s2 : s3;
    gemm_body(A, s.W, s.bias, s.C, nullptr, N, Kd, 0, blockIdx.y * 128, blockIdx.x * 128, sm);
}

// ============================================================================
// Fused flash attention (unchanged from R6)
// ============================================================================
#define FQP 100
#define FKP 132
#define FVP 104
#define FL_SMEM ((128*FQP + 128*FKP + 128*FVP + 2*128*4)*4)

__global__ void __launch_bounds__(256) flash_attn(
    const float* __restrict__ Q, const float* __restrict__ K,
    const float* __restrict__ V, float* __restrict__ C)
{
    extern __shared__ float sm[];
    float* Qs   = sm;
    float* Ks   = Qs + 128 * FQP;
    float* Vs   = Ks + 128 * FKP;
    float* redm = Vs + 128 * FVP;
    float* reds = redm + 128 * 4;

    const int tid = threadIdx.x;
    const int wid = tid >> 5, lane = tid & 31;
    const int wr = wid >> 2, wc = wid & 3;
    const int g = lane >> 2, tg = lane & 3;
    const int bz = blockIdx.y, b = bz >> 3, h = bz & 7;
    const int m0 = blockIdx.x * 128;

    const float* qg = Q + (size_t)b * SS * AHd + h * HD;
    const float* kg = K + (size_t)b * SS * AHd + h * HD;
    const float* vg = V + (size_t)b * SS * AHd + h * HD;

#pragma unroll
    for (int t = 0; t < 12; t++) {
        int s = tid + t * 256;
        int r = s / 24, cc = (s % 24) * 4;
        CP16(sptr(Qs + r * FQP + cc), qg + (size_t)(m0 + r) * AHd + cc);
    }
    CP_COMMIT();

    float m_i[4][2], l_i[4][2];
    float acc_o[4][3][4];
#pragma unroll
    for (int i = 0; i < 4; i++) {
        m_i[i][0] = m_i[i][1] = -1e30f;
        l_i[i][0] = l_i[i][1] = 0.f;
#pragma unroll
        for (int j = 0; j < 3; j++)
#pragma unroll
            for (int c = 0; c < 4; c++) acc_o[i][j][c] = 0.f;
    }

    for (int kt = 0; kt < 8; kt++) {
#pragma unroll
        for (int t = 0; t < 12; t++) {
            int s = tid + t * 256;
            int r = s / 24, cc = (s % 24) * 4;
            CP16(sptr(Ks + r * FKP + cc), kg + (size_t)(kt * 128 + r) * AHd + cc);
        }
        CP_COMMIT();
#pragma unroll
        for (int t = 0; t < 12; t++) {
            int s = tid + t * 256;
            int r = s / 24, cc = (s % 24) * 4;
            CP16(sptr(Vs + r * FVP + cc), vg + (size_t)(kt * 128 + r) * AHd + cc);
        }
        CP_COMMIT();
        CP_WAIT(1);
        __syncthreads();

        float sa[4][4][4];
#pragma unroll
        for (int i = 0; i < 4; i++)
#pragma unroll
            for (int j = 0; j < 4; j++)
#pragma unroll
                for (int c = 0; c < 4; c++) sa[i][j][c] = 0.f;

        const uint32_t* Qu = (const uint32_t*)Qs;
        const uint32_t* Ku = (const uint32_t*)Ks;
#pragma unroll
        for (int kk = 0; kk < 96; kk += 8) {
            uint32_t af[4][4], bf[4][2];
#pragma unroll
            for (int mt = 0; mt < 4; mt++) {
                int mb = wr * 64 + mt * 16 + g;
                af[mt][0] = Qu[mb * FQP + kk + tg];
                af[mt][1] = Qu[(mb + 8) * FQP + kk + tg];
                af[mt][2] = Qu[mb * FQP + kk + tg + 4];
                af[mt][3] = Qu[(mb + 8) * FQP + kk + tg + 4];
            }
#pragma unroll
            for (int nt = 0; nt < 4; nt++) {
                int nb = wc * 32 + nt * 8 + g;
                bf[nt][0] = Ku[nb * FKP + kk + tg];
                bf[nt][1] = Ku[nb * FKP + kk + tg + 4];
            }
#pragma unroll
            for (int mt = 0; mt < 4; mt++)
#pragma unroll
                for (int nt = 0; nt < 4; nt++)
                    mma_tf32(sa[mt][nt], af[mt], bf[nt]);
        }
        const float scale = 0.10206207261596576f;
#pragma unroll
        for (int mt = 0; mt < 4; mt++)
#pragma unroll
            for (int nt = 0; nt < 4; nt++)
#pragma unroll
                for (int c = 0; c < 4; c++) sa[mt][nt][c] *= scale;

        float rmax[4][2];
#pragma unroll
        for (int mt = 0; mt < 4; mt++) {
            float m0v = fmaxf(sa[mt][0][0], sa[mt][0][1]);
            float m1v = fmaxf(sa[mt][0][2], sa[mt][0][3]);
#pragma unroll
            for (int nt = 1; nt < 4; nt++) {
                m0v = fmaxf(m0v, fmaxf(sa[mt][nt][0], sa[mt][nt][1]));
                m1v = fmaxf(m1v, fmaxf(sa[mt][nt][2], sa[mt][nt][3]));
            }
            m0v = fmaxf(m0v, __shfl_xor_sync(0xffffffffu, m0v, 1));
            m0v = fmaxf(m0v, __shfl_xor_sync(0xffffffffu, m0v, 2));
            m1v = fmaxf(m1v, __shfl_xor_sync(0xffffffffu, m1v, 1));
            m1v = fmaxf(m1v, __shfl_xor_sync(0xffffffffu, m1v, 2));
            rmax[mt][0] = m0v; rmax[mt][1] = m1v;
        }
        if (tg == 0) {
#pragma unroll
            for (int mt = 0; mt < 4; mt++) {
                int r0 = wr * 64 + mt * 16 + g;
                redm[r0 * 4 + wc] = rmax[mt][0];
                redm[(r0 + 8) * 4 + wc] = rmax[mt][1];
            }
        }
        __syncthreads();

        float alpha[4][2], mnew[4][2];
#pragma unroll
        for (int mt = 0; mt < 4; mt++) {
#pragma unroll
            for (int hf = 0; hf < 2; hf++) {
                int row = wr * 64 + mt * 16 + g + hf * 8;
                float4 r4 = *(float4*)&redm[row * 4];
                float gm = fmaxf(fmaxf(r4.x, r4.y), fmaxf(r4.z, r4.w));
                float mn = fmaxf(m_i[mt][hf], gm);
                alpha[mt][hf] = __expf(m_i[mt][hf] - mn);
                mnew[mt][hf] = mn;
                m_i[mt][hf] = mn;
            }
        }

        float rsum[4][2];
#pragma unroll
        for (int mt = 0; mt < 4; mt++) { rsum[mt][0] = 0.f; rsum[mt][1] = 0.f; }
#pragma unroll
        for (int mt = 0; mt < 4; mt++)
#pragma unroll
            for (int nt = 0; nt < 4; nt++) {
                sa[mt][nt][0] = __expf(sa[mt][nt][0] - mnew[mt][0]);
                sa[mt][nt][1] = __expf(sa[mt][nt][1] - mnew[mt][0]);
                sa[mt][nt][2] = __expf(sa[mt][nt][2] - mnew[mt][1]);
                sa[mt][nt][3] = __expf(sa[mt][nt][3] - mnew[mt][1]);
                rsum[mt][0] += sa[mt][nt][0] + sa[mt][nt][1];
                rsum[mt][1] += sa[mt][nt][2] + sa[mt][nt][3];
            }
#pragma unroll
        for (int mt = 0; mt < 4; mt++) {
            rsum[mt][0] += __shfl_xor_sync(0xffffffffu, rsum[mt][0], 1);
            rsum[mt][0] += __shfl_xor_sync(0xffffffffu, rsum[mt][0], 2);
            rsum[mt][1] += __shfl_xor_sync(0xffffffffu, rsum[mt][1], 1);
            rsum[mt][1] += __shfl_xor_sync(0xffffffffu, rsum[mt][1], 2);
        }
        if (tg == 0) {
#pragma unroll
            for (int mt = 0; mt < 4; mt++) {
                int r0 = wr * 64 + mt * 16 + g;
                reds[r0 * 4 + wc] = rsum[mt][0];
                reds[(r0 + 8) * 4 + wc] = rsum[mt][1];
            }
        }
        __syncthreads();
#pragma unroll
        for (int mt = 0; mt < 4; mt++) {
#pragma unroll
            for (int hf = 0; hf < 2; hf++) {
                int row = wr * 64 + mt * 16 + g + hf * 8;
                float4 r4 = *(float4*)&reds[row * 4];
                float rs = r4.x + r4.y + r4.z + r4.w;
                l_i[mt][hf] = l_i[mt][hf] * alpha[mt][hf] + rs;
            }
#pragma unroll
            for (int nt = 0; nt < 3; nt++) {
                acc_o[mt][nt][0] *= alpha[mt][0];
                acc_o[mt][nt][1] *= alpha[mt][0];
                acc_o[mt][nt][2] *= alpha[mt][1];
                acc_o[mt][nt][3] *= alpha[mt][1];
            }
        }

#pragma unroll
        for (int mt = 0; mt < 4; mt++)
#pragma unroll
            for (int nt = 0; nt < 4; nt++) {
                int row = wr * 64 + mt * 16 + g;
                int col = wc * 32 + nt * 8 + 2 * tg;
                *(float2*)&Ks[row * FKP + col] = make_float2(sa[mt][nt][0], sa[mt][nt][1]);
                *(float2*)&Ks[(row + 8) * FKP + col] = make_float2(sa[mt][nt][2], sa[mt][nt][3]);
            }
        CP_WAIT(0);
        __syncthreads();

        const uint32_t* Pu = (const uint32_t*)Ks;
        const uint32_t* Vu = (const uint32_t*)Vs;
#pragma unroll
        for (int kk = 0; kk < 128; kk += 8) {
            uint32_t af[4][4], bf[3][2];
#pragma unroll
            for (int mt = 0; mt < 4; mt++) {
                int mb = wr * 64 + mt * 16 + g;
                af[mt][0] = Pu[mb * FKP + kk + tg];
                af[mt][1] = Pu[(mb + 8) * FKP + kk + tg];
                af[mt][2] = Pu[mb * FKP + kk + tg + 4];
                af[mt][3] = Pu[(mb + 8) * FKP + kk + tg + 4];
            }
#pragma unroll
            for (int nt = 0; nt < 3; nt++) {
                int nb = wc * 24 + nt * 8 + g;
                bf[nt][0] = Vu[(kk + tg) * FVP + nb];
                bf[nt][1] = Vu[(kk + tg + 4) * FVP + nb];
            }
#pragma unroll
            for (int mt = 0; mt < 4; mt++)
#pragma unroll
                for (int nt = 0; nt < 3; nt++)
                    mma_tf32(acc_o[mt][nt], af[mt], bf[nt]);
        }
        __syncthreads();
    }

#pragma unroll
    for (int mt = 0; mt < 4; mt++) {
        float inv0 = 1.f / l_i[mt][0];
        float inv1 = 1.f / l_i[mt][1];
#pragma unroll
        for (int nt = 0; nt < 3; nt++) {
            int row = m0 + wr * 64 + mt * 16 + g;
            int col = h * HD + wc * 24 + nt * 8 + 2 * tg;
            float* p0 = C + ((size_t)b * SS + row) * HH + col;
            float* p1 = C + ((size_t)b * SS + row + 8) * HH + col;
            *(float2*)p0 = make_float2(acc_o[mt][nt][0] * inv0, acc_o[mt][nt][1] * inv0);
            *(float2*)p1 = make_float2(acc_o[mt][nt][2] * inv1, acc_o[mt][nt][3] * inv1);
        }
    }
}

// ============================================================================
// ck GEMM: C[8192,56] = A[8192,768] @ W[768,56] + bias.  BM=32 -> 256 CTAs.
// ============================================================================
__global__ void __launch_bounds__(256) ck_gemm(
    const float* __restrict__ A, const float* __restrict__ W,
    const float* __restrict__ bias, float* __restrict__ C)
{
    __shared__ float As[32 * 68];
    __shared__ float Ws[64 * 60];
    const int tid = threadIdx.x;
    const int m0 = blockIdx.x * 32;
    const int rg = tid / 56, c = tid % 56;
    float acc[8];
#pragma unroll
    for (int r = 0; r < 8; r++) acc[r] = 0.f;

    for (int k0 = 0; k0 < AHd; k0 += 64) {
#pragma unroll
        for (int t = 0; t < 2; t++) {
            int f = tid + t * 256;
            int r = f >> 4, cc = (f & 15) << 2;
            *(float4*)&As[r * 68 + cc] = *(const float4*)(A + (size_t)(m0 + r) * AHd + k0 + cc);
        }
#pragma unroll
        for (int t = 0; t < 4; t++) {
            int f = tid + t * 256;
            if (f < 896) {
                int r = f / 14, cc = (f % 14) << 2;
                *(float4*)&Ws[r * 60 + cc] = *(const float4*)(W + (size_t)(k0 + r) * 56 + cc);
            }
        }
        __syncthreads();
        if (rg < 4) {
#pragma unroll
            for (int kk = 0; kk < 64; kk += 4) {
                float w0 = Ws[kk * 60 + c], w1 = Ws[(kk + 1) * 60 + c];
                float w2 = Ws[(kk + 2) * 60 + c], w3 = Ws[(kk + 3) * 60 + c];
#pragma unroll
                for (int r = 0; r < 8; r++) {
                    float4 a4 = *(const float4*)&As[(rg * 8 + r) * 68 + kk];
                    acc[r] += a4.x * w0 + a4.y * w1 + a4.z * w2 + a4.w * w3;
                }
            }
        }
        __syncthreads();
    }
    if (rg < 4) {
        float bb = bias[c];
#pragma unroll
        for (int r = 0; r < 8; r++)
            C[(size_t)(m0 + rg * 8 + r) * 56 + c] = acc[r] + bb;
    }
}

// ---------------- depthwise conv: 8 outputs per thread, register reuse ------
__global__ void depthwise_conv8(const float* __restrict__ X, const float* __restrict__ dw,
                                float* __restrict__ Y) {
    int idx = blockIdx.x * blockDim.x + threadIdx.x;
    if (idx >= (MROWS / 8) * HH) return;
    int c = idx % HH;
    int t = idx / HH;
    int sblk = t % (SS / 8);
    int b = t / (SS / 8);
    int s0 = sblk * 8;
    const float* xb = X + ((size_t)b * SS) * HH + c;
    float xv[14];
#pragma unroll
    for (int i = 0; i < 14; i++) {
        int ss = s0 - 3 + i;
        xv[i] = (ss >= 0 && ss < SS) ? xb[(size_t)ss * HH] : 0.f;
    }
    float w[7];
#pragma unroll
    for (int k = 0; k < 7; k++) w[k] = dw[c * 7 + k];
    float* yb = Y + ((size_t)b * SS + s0) * HH + c;
#pragma unroll
    for (int r = 0; r < 8; r++) {
        float acc = 0.f;
#pragma unroll
        for (int k = 0; k < 7; k++) acc += xv[r + k] * w[k];
        yb[(size_t)r * HH] = acc;
    }
}

__global__ void softmax7(float* __restrict__ ck) {
    int idx = blockIdx.x * blockDim.x + threadIdx.x;
    if (idx >= MROWS * NHh) return;
    int row = idx >> 3, h = idx & 7;
    float* p = ck + (size_t)row * 56 + h * 7;
    float m = p[0];
#pragma unroll
    for (int k = 1; k < 7; k++) m = fmaxf(m, p[k]);
    float e[7], s = 0.f;
#pragma unroll
    for (int k = 0; k < 7; k++) { e[k] = __expf(p[k] - m); s += e[k]; }
    float inv = 1.f / s;
#pragma unroll
    for (int k = 0; k < 7; k++) p[k] = e[k] * inv;
}

// ---------------- span conv: 4 outputs per thread, register reuse -----------
__global__ void span_conv4(const float* __restrict__ co, const float* __restrict__ ck,
                           float* __restrict__ ctx) {
    int idx = blockIdx.x * blockDim.x + threadIdx.x;
    if (idx >= (MROWS / 4) * AHd) return;
    int col = idx % AHd;
    int t = idx / AHd;
    int sblk = t % (SS / 4);
    int b = t / (SS / 4);
    int h = col / HD;
    int s0 = sblk * 4;
    const float* cb = co + ((size_t)b * SS) * AHd + col;
    float cv[10];
#pragma unroll
    for (int i = 0; i < 10; i++) {
        int ss = s0 - 3 + i;
        cv[i] = (ss >= 0 && ss < SS) ? cb[(size_t)ss * AHd] : 0.f;
    }
    size_t row0 = (size_t)b * SS + s0;
#pragma unroll
    for (int r = 0; r < 4; r++) {
        const float* w = ck + (row0 + r) * 56 + h * 7;
        float acc = 0.f;
#pragma unroll
        for (int k = 0; k < 7; k++) acc += cv[r + k] * w[k];
        ctx[(row0 + r) * HH + AHd + col] = acc;
    }
}

// ---------------- fused residual + LayerNorm ----------------
__global__ void ln_residual(const float* __restrict__ X, const float* __restrict__ R,
                            const float* __restrict__ gam, const float* __restrict__ bet,
                            float* __restrict__ O) {
    size_t row = blockIdx.x;
    int tid = threadIdx.x;
    const float* x = X + row * HH;
    const float* r = R + row * HH;
    __shared__ float red[256];
    float vals[6];
    float s = 0.f;
#pragma unroll
    for (int t = 0; t < 6; t++) {
        int c = tid + t * 256;
        vals[t] = x[c] + r[c];
        s += vals[t];
    }
    red[tid] = s;
    __syncthreads();
    for (int o = 128; o > 0; o >>= 1) {
        if (tid < o) red[tid] += red[tid + o];
        __syncthreads();
    }
    float mean = red[0] * (1.f / HH);
    __syncthreads();
    float s2 = 0.f;
#pragma unroll
    for (int t = 0; t < 6; t++) {
        float d = vals[t] - mean;
        s2 += d * d;
    }
    red[tid] = s2;
    __syncthreads();
    for (int o = 128; o > 0; o >>= 1) {
        if (tid < o) red[tid] += red[tid + o];
        __syncthreads();
    }
    float rstd = rsqrtf(red[0] * (1.f / HH) + 1e-12f);
#pragma unroll
    for (int t = 0; t < 6; t++) {
        int c = tid + t * 256;
        O[row * HH + c] = (vals[t] - mean) * rstd * gam[c] + bet[c];
    }
}

// ---------------- split max-pool + decoder ----------------
__global__ void maxpool_part(const float* __restrict__ L, float* __restrict__ pp) {
    int idx = blockIdx.x * blockDim.x + threadIdx.x;
    if (idx >= MB * 8 * HH) return;
    int c = idx % HH;
    int ch = (idx / HH) & 7;
    int b = idx / (HH * 8);
    const float* base = L + ((size_t)b * SS + ch * 128) * HH + c;
    float m = -3.4e38f;
    for (int s = 0; s < 128; s++) m = fmaxf(m, base[(size_t)s * HH]);
    pp[idx] = m;
}

__global__ void decode2(const float* __restrict__ pp, const float* __restrict__ wd,
                        const float* __restrict__ bd, float* __restrict__ out) {
    int b = blockIdx.x;
    int tid = threadIdx.x;
    __shared__ float red[256];
    float part = 0.f;
    for (int c = tid; c < HH; c += 256) {
        float m = pp[((size_t)b * 8) * HH + c];
#pragma unroll
        for (int ch = 1; ch < 8; ch++)
            m = fmaxf(m, pp[((size_t)b * 8 + ch) * HH + c]);
        part += m * wd[c];
    }
    red[tid] = part;
    __syncthreads();
    for (int o = 128; o > 0; o >>= 1) {
        if (tid < o) red[tid] += red[tid + o];
        __syncthreads();
    }
    if (tid == 0) out[b] = red[0] + bd[0];
}

// ============================================================================
// Host launcher
// ============================================================================
extern "C" void kernel_launch(void* const* d_in, const int* in_sizes, int n_in,
                              void* d_out, int out_size) {
    const float* embed = (const float*)d_in[0];
    const float* wq  = (const float*)d_in[1];  const float* bq  = (const float*)d_in[2];
    const float* wk  = (const float*)d_in[3];  const float* bk  = (const float*)d_in[4];
    const float* wv  = (const float*)d_in[5];  const float* bv  = (const float*)d_in[6];
    const float* dw  = (const float*)d_in[7];
    const float* pw  = (const float*)d_in[8];  const float* sep_b = (const float*)d_in[9];
    const float* wck = (const float*)d_in[10]; const float* bck = (const float*)d_in[11];
    const float* wco = (const float*)d_in[12]; const float* bco = (const float*)d_in[13];
    const float* wso = (const float*)d_in[14]; const float* bso = (const float*)d_in[15];
    const float* ln1_g = (const float*)d_in[16]; const float* ln1_b = (const float*)d_in[17];
    const float* wi  = (const float*)d_in[18]; const float* bi  = (const float*)d_in[19];
    const float* wo  = (const float*)d_in[20]; const float* bo  = (const float*)d_in[21];
    const float* ln2_g = (const float*)d_in[22]; const float* ln2_b = (const float*)d_in[23];
    const float* wd  = (const float*)d_in[24]; const float* bd  = (const float*)d_in[25];
    float* out = (float*)d_out;

    cudaFuncSetAttribute(mma_gemm, cudaFuncAttributeMaxDynamicSharedMemorySize, GEMM_SMEM);
    cudaFuncSetAttribute(mma_gemm_multi, cudaFuncAttributeMaxDynamicSharedMemorySize, GEMM_SMEM);
    cudaFuncSetAttribute(flash_attn, cudaFuncAttributeMaxDynamicSharedMemorySize, FL_SMEM);

    float *q, *k, *v, *co, *dconv, *sep, *ck, *ctx, *tmp, *inter, *attn, *layer, *poolp;
    cudaGetSymbolAddress((void**)&q, g_q);
    cudaGetSymbolAddress((void**)&k, g_k);
    cudaGetSymbolAddress((void**)&v, g_v);
    cudaGetSymbolAddress((void**)&co, g_co);
    cudaGetSymbolAddress((void**)&dconv, g_dconv);
    cudaGetSymbolAddress((void**)&sep, g_sep);
    cudaGetSymbolAddress((void**)&ck, g_ck);
    cudaGetSymbolAddress((void**)&ctx, g_ctx);
    cudaGetSymbolAddress((void**)&tmp, g_tmp);
    cudaGetSymbolAddress((void**)&inter, g_inter);
    cudaGetSymbolAddress((void**)&attn, g_attn);
    cudaGetSymbolAddress((void**)&layer, g_layer);
    cudaGetSymbolAddress((void**)&poolp, g_poolp);

    dim3 blk(256);

    // ---- fused q/k/v/co projections ----
    GemmSet sq = {wq, bq, q}, sk = {wk, bk, k}, sv = {wv, bv, v}, sc = {wco, bco, co};
    dim3 gm(AHd / 128, MROWS / 128, 4);
    mma_gemm_multi<<<gm, blk, GEMM_SMEM>>>(embed, sq, sk, sv, sc, AHd, HH);

    // ---- separable conv; pointwise gemm fuses conv_attn = sep*q ----
    depthwise_conv8<<<((MROWS / 8) * HH + 255) / 256, blk>>>(embed, dw, dconv);
    dim3 gproj(AHd / 128, MROWS / 128);
    mma_gemm<<<gproj, blk, GEMM_SMEM>>>(dconv, pw, sep_b, sep, q, AHd, HH, 2);

    // ---- span kernels ----
    ck_gemm<<<MROWS / 32, blk>>>(sep, wck, bck, ck);
    softmax7<<<(MROWS * NHh + 255) / 256, blk>>>(ck);
    span_conv4<<<((MROWS / 4) * AHd + 255) / 256, blk>>>(co, ck, ctx);

    // ---- fused flash attention -> ctx[:, 0:768] ----
    dim3 gfl(SS / 128, MB * NHh);
    flash_attn<<<gfl, blk, FL_SMEM>>>(q, k, v, ctx);

    // ---- self output + LN1 ----
    dim3 gso(HH / 128, MROWS / 128);
    mma_gemm<<<gso, blk, GEMM_SMEM>>>(ctx, wso, bso, tmp, nullptr, HH, HH, 0);
    ln_residual<<<MROWS, blk>>>(tmp, embed, ln1_g, ln1_b, attn);

    // ---- FFN ----
    dim3 gin(IM / 128, MROWS / 128);
    mma_gemm<<<gin, blk, GEMM_SMEM>>>(attn, wi, bi, inter, nullptr, IM, HH, 1);
    mma_gemm<<<gso, blk, GEMM_SMEM>>>(inter, wo, bo, tmp, nullptr, HH, IM, 0);
    ln_residual<<<MROWS, blk>>>(tmp, attn, ln2_g, ln2_b, layer);

    // ---- pool + decode ----
    maxpool_part<<<(MB * 8 * HH + 255) / 256, blk>>>(layer, poolp);
    decode2<<<MB, blk>>>(poolp, wd, bd, out);
}

// round 8
// speedup vs baseline: 4.4671x; 1.0321x over previous
#include <cuda_runtime.h>
#include <math.h>
#include <stdint.h>

// ---------------- problem dims ----------------
#define MB   8
#define SS   1024
#define HH   1536
#define NHh  8
#define HD   96
#define AHd  768
#define KK   7
#define IM   3072
#define MROWS (MB*SS)          // 8192

// ---------------- scratch ----------------
__device__ float g_q   [MROWS*AHd];
__device__ float g_k   [MROWS*AHd];
__device__ float g_v   [MROWS*AHd];
__device__ float g_co  [MROWS*AHd];
__device__ float g_dconv[MROWS*HH];
__device__ float g_sep [MROWS*AHd];
__device__ float g_ck  [MROWS*56];
__device__ float g_ctx [MROWS*HH];
__device__ float g_tmp [MROWS*HH];
__device__ float g_inter[MROWS*IM];
__device__ float g_attn[MROWS*HH];
__device__ float g_layer[MROWS*HH];
__device__ float g_poolp[MB*8*HH];

// ---------------- streams/events (created at load time, not in kernel_launch) ----
struct StreamInit {
    cudaStream_t s2;
    cudaEvent_t evF, evA, evB;
    StreamInit() {
        cudaStreamCreateWithFlags(&s2, cudaStreamNonBlocking);
        cudaEventCreateWithFlags(&evF, cudaEventDisableTiming);
        cudaEventCreateWithFlags(&evA, cudaEventDisableTiming);
        cudaEventCreateWithFlags(&evB, cudaEventDisableTiming);
    }
};
static StreamInit g_si;

// ---------------- PTX helpers ----------------
__device__ __forceinline__ uint32_t sptr(const void* p) {
    return (uint32_t)__cvta_generic_to_shared(p);
}
#define CP16(dst, src) \
    asm volatile("cp.async.cg.shared.global [%0], [%1], 16;" :: "r"(dst), "l"(src))
#define CP_COMMIT() asm volatile("cp.async.commit_group;" ::: "memory")
#define CP_WAIT(n)  asm volatile("cp.async.wait_group %0;" :: "n"(n) : "memory")

__device__ __forceinline__ void mma_tf32(float* d, const uint32_t* a, const uint32_t* b) {
    asm volatile(
        "mma.sync.aligned.m16n8k8.row.col.f32.tf32.tf32.f32 "
        "{%0,%1,%2,%3}, {%4,%5,%6,%7}, {%8,%9}, {%0,%1,%2,%3};"
        : "+f"(d[0]), "+f"(d[1]), "+f"(d[2]), "+f"(d[3])
        : "r"(a[0]), "r"(a[1]), "r"(a[2]), "r"(a[3]), "r"(b[0]), "r"(b[1]));
}

// ============================================================================
// tf32 mma GEMM, 3-stage cp.async pipeline, 2 CTAs/SM.
// op: 0 = bias, 1 = bias+gelu, 2 = (x+bias)*aux
// ============================================================================
#define PA   36
#define PB   136
#define ASZ  (128*PA)
#define BSZ  (32*PB)
#define NSTG 3
#define GEMM_SMEM (NSTG*(ASZ+BSZ)*4)

struct GemmSet { const float* W; const float* bias; float* C; };

__device__ __forceinline__ void gemm_body(
    const float* __restrict__ A, const float* __restrict__ W,
    const float* __restrict__ bias, float* __restrict__ C,
    const float* __restrict__ aux,
    int N, int Kd, int op, int m0, int n0, float* sm)
{
    float* Abase = sm;
    float* Bbase = sm + NSTG * ASZ;

    const int tid = threadIdx.x;
    const int wid = tid >> 5, lane = tid & 31;
    const int wr = wid >> 2, wc = wid & 3;
    const int g = lane >> 2, tg = lane & 3;
    const int nkb = Kd >> 5;

    float acc[4][4][4];
#pragma unroll
    for (int i = 0; i < 4; i++)
#pragma unroll
        for (int j = 0; j < 4; j++)
#pragma unroll
            for (int c = 0; c < 4; c++) acc[i][j][c] = 0.f;

    auto issue = [&](int kb) {
        int s = kb % NSTG;
        float* As = Abase + s * ASZ;
        float* Bs = Bbase + s * BSZ;
        const float* ag = A + (size_t)m0 * Kd + kb * 32;
        const float* bg = W + (size_t)(kb * 32) * N + n0;
#pragma unroll
        for (int t = 0; t < 4; t++) {
            int sA = tid + t * 256;
            int r  = sA >> 3,  c  = (sA & 7) << 2;
            CP16(sptr(As + r * PA + c), ag + (size_t)r * Kd + c);
            int rb = sA >> 5,  cb = (sA & 31) << 2;
            CP16(sptr(Bs + rb * PB + cb), bg + (size_t)rb * N + cb);
        }
    };

    issue(0); CP_COMMIT();
    issue(1); CP_COMMIT();
    issue(2); CP_COMMIT();

    for (int kb = 0; kb < nkb; kb++) {
        CP_WAIT(2);
        __syncthreads();
        int s = kb % NSTG;
        const uint32_t* As = (const uint32_t*)(Abase + s * ASZ);
        const uint32_t* Bs = (const uint32_t*)(Bbase + s * BSZ);
#pragma unroll
        for (int kk = 0; kk < 32; kk += 8) {
            uint32_t af[4][4], bf[4][2];
#pragma unroll
            for (int mt = 0; mt < 4; mt++) {
                int mb = wr * 64 + mt * 16 + g;
                af[mt][0] = As[mb * PA + kk + tg];
                af[mt][1] = As[(mb + 8) * PA + kk + tg];
                af[mt][2] = As[mb * PA + kk + tg + 4];
                af[mt][3] = As[(mb + 8) * PA + kk + tg + 4];
            }
#pragma unroll
            for (int nt = 0; nt < 4; nt++) {
                int nb = wc * 32 + nt * 8 + g;
                bf[nt][0] = Bs[(kk + tg) * PB + nb];
                bf[nt][1] = Bs[(kk + tg + 4) * PB + nb];
            }
#pragma unroll
            for (int mt = 0; mt < 4; mt++)
#pragma unroll
                for (int nt = 0; nt < 4; nt++)
                    mma_tf32(acc[mt][nt], af[mt], bf[nt]);
        }
        __syncthreads();
        if (kb + 3 < nkb) issue(kb + 3);
        CP_COMMIT();
    }

    float bb[4][2];
#pragma unroll
    for (int nt = 0; nt < 4; nt++) {
        int col = n0 + wc * 32 + nt * 8 + 2 * tg;
        bb[nt][0] = bias[col];
        bb[nt][1] = bias[col + 1];
    }
#pragma unroll
    for (int mt = 0; mt < 4; mt++) {
#pragma unroll
        for (int nt = 0; nt < 4; nt++) {
            int row = m0 + wr * 64 + mt * 16 + g;
            int col = n0 + wc * 32 + nt * 8 + 2 * tg;
            float v0 = acc[mt][nt][0] + bb[nt][0];
            float v1 = acc[mt][nt][1] + bb[nt][1];
            float v2 = acc[mt][nt][2] + bb[nt][0];
            float v3 = acc[mt][nt][3] + bb[nt][1];
            if (op == 1) {
                v0 = 0.5f * v0 * (1.f + erff(v0 * 0.70710678118654752f));
                v1 = 0.5f * v1 * (1.f + erff(v1 * 0.70710678118654752f));
                v2 = 0.5f * v2 * (1.f + erff(v2 * 0.70710678118654752f));
                v3 = 0.5f * v3 * (1.f + erff(v3 * 0.70710678118654752f));
            } else if (op == 2) {
                const float* a0 = aux + (size_t)row * N + col;
                const float* a1 = aux + (size_t)(row + 8) * N + col;
                v0 *= a0[0]; v1 *= a0[1]; v2 *= a1[0]; v3 *= a1[1];
            }
            *(float2*)(C + (size_t)row * N + col)       = make_float2(v0, v1);
            *(float2*)(C + (size_t)(row + 8) * N + col) = make_float2(v2, v3);
        }
    }
}

__global__ void __launch_bounds__(256, 2) mma_gemm(
    const float* __restrict__ A, const float* __restrict__ W,
    const float* __restrict__ bias, float* __restrict__ C,
    const float* __restrict__ aux, int N, int Kd, int op)
{
    extern __shared__ float sm[];
    gemm_body(A, W, bias, C, aux, N, Kd, op, blockIdx.y * 128, blockIdx.x * 128, sm);
}

__global__ void __launch_bounds__(256, 2) mma_gemm_multi(
    const float* __restrict__ A, GemmSet s0, GemmSet s1, GemmSet s2, GemmSet s3,
    int N, int Kd)
{
    extern __shared__ float sm[];
    GemmSet s = (blockIdx.z == 0) ? s0 : (blockIdx.z == 1) ? s1 : (blockIdx.z == 2) ? s2 : s3;
    gemm_body(A, s.W, s.bias, s.C, nullptr, N, Kd, 0, blockIdx.y * 128, blockIdx.x * 128, sm);
}

// ============================================================================
// Fused flash attention (unchanged)
// ============================================================================
#define FQP 100
#define FKP 132
#define FVP 104
#define FL_SMEM ((128*FQP + 128*FKP + 128*FVP + 2*128*4)*4)

__global__ void __launch_bounds__(256) flash_attn(
    const float* __restrict__ Q, const float* __restrict__ K,
    const float* __restrict__ V, float* __restrict__ C)
{
    extern __shared__ float sm[];
    float* Qs   = sm;
    float* Ks   = Qs + 128 * FQP;
    float* Vs   = Ks + 128 * FKP;
    float* redm = Vs + 128 * FVP;
    float* reds = redm + 128 * 4;

    const int tid = threadIdx.x;
    const int wid = tid >> 5, lane = tid & 31;
    const int wr = wid >> 2, wc = wid & 3;
    const int g = lane >> 2, tg = lane & 3;
    const int bz = blockIdx.y, b = bz >> 3, h = bz & 7;
    const int m0 = blockIdx.x * 128;

    const float* qg = Q + (size_t)b * SS * AHd + h * HD;
    const float* kg = K + (size_t)b * SS * AHd + h * HD;
    const float* vg = V + (size_t)b * SS * AHd + h * HD;

#pragma unroll
    for (int t = 0; t < 12; t++) {
        int s = tid + t * 256;
        int r = s / 24, cc = (s % 24) * 4;
        CP16(sptr(Qs + r * FQP + cc), qg + (size_t)(m0 + r) * AHd + cc);
    }
    CP_COMMIT();

    float m_i[4][2], l_i[4][2];
    float acc_o[4][3][4];
#pragma unroll
    for (int i = 0; i < 4; i++) {
        m_i[i][0] = m_i[i][1] = -1e30f;
        l_i[i][0] = l_i[i][1] = 0.f;
#pragma unroll
        for (int j = 0; j < 3; j++)
#pragma unroll
            for (int c = 0; c < 4; c++) acc_o[i][j][c] = 0.f;
    }

    for (int kt = 0; kt < 8; kt++) {
#pragma unroll
        for (int t = 0; t < 12; t++) {
            int s = tid + t * 256;
            int r = s / 24, cc = (s % 24) * 4;
            CP16(sptr(Ks + r * FKP + cc), kg + (size_t)(kt * 128 + r) * AHd + cc);
        }
        CP_COMMIT();
#pragma unroll
        for (int t = 0; t < 12; t++) {
            int s = tid + t * 256;
            int r = s / 24, cc = (s % 24) * 4;
            CP16(sptr(Vs + r * FVP + cc), vg + (size_t)(kt * 128 + r) * AHd + cc);
        }
        CP_COMMIT();
        CP_WAIT(1);
        __syncthreads();

        float sa[4][4][4];
#pragma unroll
        for (int i = 0; i < 4; i++)
#pragma unroll
            for (int j = 0; j < 4; j++)
#pragma unroll
                for (int c = 0; c < 4; c++) sa[i][j][c] = 0.f;

        const uint32_t* Qu = (const uint32_t*)Qs;
        const uint32_t* Ku = (const uint32_t*)Ks;
#pragma unroll
        for (int kk = 0; kk < 96; kk += 8) {
            uint32_t af[4][4], bf[4][2];
#pragma unroll
            for (int mt = 0; mt < 4; mt++) {
                int mb = wr * 64 + mt * 16 + g;
                af[mt][0] = Qu[mb * FQP + kk + tg];
                af[mt][1] = Qu[(mb + 8) * FQP + kk + tg];
                af[mt][2] = Qu[mb * FQP + kk + tg + 4];
                af[mt][3] = Qu[(mb + 8) * FQP + kk + tg + 4];
            }
#pragma unroll
            for (int nt = 0; nt < 4; nt++) {
                int nb = wc * 32 + nt * 8 + g;
                bf[nt][0] = Ku[nb * FKP + kk + tg];
                bf[nt][1] = Ku[nb * FKP + kk + tg + 4];
            }
#pragma unroll
            for (int mt = 0; mt < 4; mt++)
#pragma unroll
                for (int nt = 0; nt < 4; nt++)
                    mma_tf32(sa[mt][nt], af[mt], bf[nt]);
        }
        const float scale = 0.10206207261596576f;
#pragma unroll
        for (int mt = 0; mt < 4; mt++)
#pragma unroll
            for (int nt = 0; nt < 4; nt++)
#pragma unroll
                for (int c = 0; c < 4; c++) sa[mt][nt][c] *= scale;

        float rmax[4][2];
#pragma unroll
        for (int mt = 0; mt < 4; mt++) {
            float m0v = fmaxf(sa[mt][0][0], sa[mt][0][1]);
            float m1v = fmaxf(sa[mt][0][2], sa[mt][0][3]);
#pragma unroll
            for (int nt = 1; nt < 4; nt++) {
                m0v = fmaxf(m0v, fmaxf(sa[mt][nt][0], sa[mt][nt][1]));
                m1v = fmaxf(m1v, fmaxf(sa[mt][nt][2], sa[mt][nt][3]));
            }
            m0v = fmaxf(m0v, __shfl_xor_sync(0xffffffffu, m0v, 1));
            m0v = fmaxf(m0v, __shfl_xor_sync(0xffffffffu, m0v, 2));
            m1v = fmaxf(m1v, __shfl_xor_sync(0xffffffffu, m1v, 1));
            m1v = fmaxf(m1v, __shfl_xor_sync(0xffffffffu, m1v, 2));
            rmax[mt][0] = m0v; rmax[mt][1] = m1v;
        }
        if (tg == 0) {
#pragma unroll
            for (int mt = 0; mt < 4; mt++) {
                int r0 = wr * 64 + mt * 16 + g;
                redm[r0 * 4 + wc] = rmax[mt][0];
                redm[(r0 + 8) * 4 + wc] = rmax[mt][1];
            }
        }
        __syncthreads();

        float alpha[4][2], mnew[4][2];
#pragma unroll
        for (int mt = 0; mt < 4; mt++) {
#pragma unroll
            for (int hf = 0; hf < 2; hf++) {
                int row = wr * 64 + mt * 16 + g + hf * 8;
                float4 r4 = *(float4*)&redm[row * 4];
                float gm = fmaxf(fmaxf(r4.x, r4.y), fmaxf(r4.z, r4.w));
                float mn = fmaxf(m_i[mt][hf], gm);
                alpha[mt][hf] = __expf(m_i[mt][hf] - mn);
                mnew[mt][hf] = mn;
                m_i[mt][hf] = mn;
            }
        }

        float rsum[4][2];
#pragma unroll
        for (int mt = 0; mt < 4; mt++) { rsum[mt][0] = 0.f; rsum[mt][1] = 0.f; }
#pragma unroll
        for (int mt = 0; mt < 4; mt++)
#pragma unroll
            for (int nt = 0; nt < 4; nt++) {
                sa[mt][nt][0] = __expf(sa[mt][nt][0] - mnew[mt][0]);
                sa[mt][nt][1] = __expf(sa[mt][nt][1] - mnew[mt][0]);
                sa[mt][nt][2] = __expf(sa[mt][nt][2] - mnew[mt][1]);
                sa[mt][nt][3] = __expf(sa[mt][nt][3] - mnew[mt][1]);
                rsum[mt][0] += sa[mt][nt][0] + sa[mt][nt][1];
                rsum[mt][1] += sa[mt][nt][2] + sa[mt][nt][3];
            }
#pragma unroll
        for (int mt = 0; mt < 4; mt++) {
            rsum[mt][0] += __shfl_xor_sync(0xffffffffu, rsum[mt][0], 1);
            rsum[mt][0] += __shfl_xor_sync(0xffffffffu, rsum[mt][0], 2);
            rsum[mt][1] += __shfl_xor_sync(0xffffffffu, rsum[mt][1], 1);
            rsum[mt][1] += __shfl_xor_sync(0xffffffffu, rsum[mt][1], 2);
        }
        if (tg == 0) {
#pragma unroll
            for (int mt = 0; mt < 4; mt++) {
                int r0 = wr * 64 + mt * 16 + g;
                reds[r0 * 4 + wc] = rsum[mt][0];
                reds[(r0 + 8) * 4 + wc] = rsum[mt][1];
            }
        }
        __syncthreads();
#pragma unroll
        for (int mt = 0; mt < 4; mt++) {
#pragma unroll
            for (int hf = 0; hf < 2; hf++) {
                int row = wr * 64 + mt * 16 + g + hf * 8;
                float4 r4 = *(float4*)&reds[row * 4];
                float rs = r4.x + r4.y + r4.z + r4.w;
                l_i[mt][hf] = l_i[mt][hf] * alpha[mt][hf] + rs;
            }
#pragma unroll
            for (int nt = 0; nt < 3; nt++) {
                acc_o[mt][nt][0] *= alpha[mt][0];
                acc_o[mt][nt][1] *= alpha[mt][0];
                acc_o[mt][nt][2] *= alpha[mt][1];
                acc_o[mt][nt][3] *= alpha[mt][1];
            }
        }

#pragma unroll
        for (int mt = 0; mt < 4; mt++)
#pragma unroll
            for (int nt = 0; nt < 4; nt++) {
                int row = wr * 64 + mt * 16 + g;
                int col = wc * 32 + nt * 8 + 2 * tg;
                *(float2*)&Ks[row * FKP + col] = make_float2(sa[mt][nt][0], sa[mt][nt][1]);
                *(float2*)&Ks[(row + 8) * FKP + col] = make_float2(sa[mt][nt][2], sa[mt][nt][3]);
            }
        CP_WAIT(0);
        __syncthreads();

        const uint32_t* Pu = (const uint32_t*)Ks;
        const uint32_t* Vu = (const uint32_t*)Vs;
#pragma unroll
        for (int kk = 0; kk < 128; kk += 8) {
            uint32_t af[4][4], bf[3][2];
#pragma unroll
            for (int mt = 0; mt < 4; mt++) {
                int mb = wr * 64 + mt * 16 + g;
                af[mt][0] = Pu[mb * FKP + kk + tg];
                af[mt][1] = Pu[(mb + 8) * FKP + kk + tg];
                af[mt][2] = Pu[mb * FKP + kk + tg + 4];
                af[mt][3] = Pu[(mb + 8) * FKP + kk + tg + 4];
            }
#pragma unroll
            for (int nt = 0; nt < 3; nt++) {
                int nb = wc * 24 + nt * 8 + g;
                bf[nt][0] = Vu[(kk + tg) * FVP + nb];
                bf[nt][1] = Vu[(kk + tg + 4) * FVP + nb];
            }
#pragma unroll
            for (int mt = 0; mt < 4; mt++)
#pragma unroll
                for (int nt = 0; nt < 3; nt++)
                    mma_tf32(acc_o[mt][nt], af[mt], bf[nt]);
        }
        __syncthreads();
    }

#pragma unroll
    for (int mt = 0; mt < 4; mt++) {
        float inv0 = 1.f / l_i[mt][0];
        float inv1 = 1.f / l_i[mt][1];
#pragma unroll
        for (int nt = 0; nt < 3; nt++) {
            int row = m0 + wr * 64 + mt * 16 + g;
            int col = h * HD + wc * 24 + nt * 8 + 2 * tg;
            float* p0 = C + ((size_t)b * SS + row) * HH + col;
            float* p1 = C + ((size_t)b * SS + row + 8) * HH + col;
            *(float2*)p0 = make_float2(acc_o[mt][nt][0] * inv0, acc_o[mt][nt][1] * inv0);
            *(float2*)p1 = make_float2(acc_o[mt][nt][2] * inv1, acc_o[mt][nt][3] * inv1);
        }
    }
}

// ============================================================================
// ck GEMM + fused softmax over 7 taps.  BM=32 -> 256 CTAs.
// ============================================================================
__global__ void __launch_bounds__(256) ck_gemm_sm(
    const float* __restrict__ A, const float* __restrict__ W,
    const float* __restrict__ bias, float* __restrict__ C)
{
    __shared__ float As[32 * 68];
    __shared__ float Ws[64 * 60];
    __shared__ float S[32 * 57];
    const int tid = threadIdx.x;
    const int m0 = blockIdx.x * 32;
    const int rg = tid / 56, c = tid % 56;
    float acc[8];
#pragma unroll
    for (int r = 0; r < 8; r++) acc[r] = 0.f;

    for (int k0 = 0; k0 < AHd; k0 += 64) {
#pragma unroll
        for (int t = 0; t < 2; t++) {
            int f = tid + t * 256;
            int r = f >> 4, cc = (f & 15) << 2;
            *(float4*)&As[r * 68 + cc] = *(const float4*)(A + (size_t)(m0 + r) * AHd + k0 + cc);
        }
#pragma unroll
        for (int t = 0; t < 4; t++) {
            int f = tid + t * 256;
            if (f < 896) {
                int r = f / 14, cc = (f % 14) << 2;
                *(float4*)&Ws[r * 60 + cc] = *(const float4*)(W + (size_t)(k0 + r) * 56 + cc);
            }
        }
        __syncthreads();
        if (rg < 4) {
#pragma unroll
            for (int kk = 0; kk < 64; kk += 4) {
                float w0 = Ws[kk * 60 + c], w1 = Ws[(kk + 1) * 60 + c];
                float w2 = Ws[(kk + 2) * 60 + c], w3 = Ws[(kk + 3) * 60 + c];
#pragma unroll
                for (int r = 0; r < 8; r++) {
                    float4 a4 = *(const float4*)&As[(rg * 8 + r) * 68 + kk];
                    acc[r] += a4.x * w0 + a4.y * w1 + a4.z * w2 + a4.w * w3;
                }
            }
        }
        __syncthreads();
    }
    if (rg < 4) {
        float bb = bias[c];
#pragma unroll
        for (int r = 0; r < 8; r++)
            S[(rg * 8 + r) * 57 + c] = acc[r] + bb;
    }
    __syncthreads();
    // fused softmax over 7 taps: 256 threads = 32 rows x 8 heads
    {
        int row = tid >> 3, h = tid & 7;
        float* p = &S[row * 57 + h * 7];
        float m = p[0];
#pragma unroll
        for (int k = 1; k < 7; k++) m = fmaxf(m, p[k]);
        float e[7], s = 0.f;
#pragma unroll
        for (int k = 0; k < 7; k++) { e[k] = __expf(p[k] - m); s += e[k]; }
        float inv = 1.f / s;
        float* cp = C + (size_t)(m0 + row) * 56 + h * 7;
#pragma unroll
        for (int k = 0; k < 7; k++) cp[k] = e[k] * inv;
    }
}

// ---------------- depthwise conv: 8 outputs per thread ----------------
__global__ void depthwise_conv8(const float* __restrict__ X, const float* __restrict__ dw,
                                float* __restrict__ Y) {
    int idx = blockIdx.x * blockDim.x + threadIdx.x;
    if (idx >= (MROWS / 8) * HH) return;
    int c = idx % HH;
    int t = idx / HH;
    int sblk = t % (SS / 8);
    int b = t / (SS / 8);
    int s0 = sblk * 8;
    const float* xb = X + ((size_t)b * SS) * HH + c;
    float xv[14];
#pragma unroll
    for (int i = 0; i < 14; i++) {
        int ss = s0 - 3 + i;
        xv[i] = (ss >= 0 && ss < SS) ? xb[(size_t)ss * HH] : 0.f;
    }
    float w[7];
#pragma unroll
    for (int k = 0; k < 7; k++) w[k] = dw[c * 7 + k];
    float* yb = Y + ((size_t)b * SS + s0) * HH + c;
#pragma unroll
    for (int r = 0; r < 8; r++) {
        float acc = 0.f;
#pragma unroll
        for (int k = 0; k < 7; k++) acc += xv[r + k] * w[k];
        yb[(size_t)r * HH] = acc;
    }
}

// ---------------- span conv: 4 outputs per thread ----------------
__global__ void span_conv4(const float* __restrict__ co, const float* __restrict__ ck,
                           float* __restrict__ ctx) {
    int idx = blockIdx.x * blockDim.x + threadIdx.x;
    if (idx >= (MROWS / 4) * AHd) return;
    int col = idx % AHd;
    int t = idx / AHd;
    int sblk = t % (SS / 4);
    int b = t / (SS / 4);
    int h = col / HD;
    int s0 = sblk * 4;
    const float* cb = co + ((size_t)b * SS) * AHd + col;
    float cv[10];
#pragma unroll
    for (int i = 0; i < 10; i++) {
        int ss = s0 - 3 + i;
        cv[i] = (ss >= 0 && ss < SS) ? cb[(size_t)ss * AHd] : 0.f;
    }
    size_t row0 = (size_t)b * SS + s0;
#pragma unroll
    for (int r = 0; r < 4; r++) {
        const float* w = ck + (row0 + r) * 56 + h * 7;
        float acc = 0.f;
#pragma unroll
        for (int k = 0; k < 7; k++) acc += cv[r + k] * w[k];
        ctx[(row0 + r) * HH + AHd + col] = acc;
    }
}

// ---------------- fused residual + LayerNorm ----------------
__global__ void ln_residual(const float* __restrict__ X, const float* __restrict__ R,
                            const float* __restrict__ gam, const float* __restrict__ bet,
                            float* __restrict__ O) {
    size_t row = blockIdx.x;
    int tid = threadIdx.x;
    const float* x = X + row * HH;
    const float* r = R + row * HH;
    __shared__ float red[256];
    float vals[6];
    float s = 0.f;
#pragma unroll
    for (int t = 0; t < 6; t++) {
        int c = tid + t * 256;
        vals[t] = x[c] + r[c];
        s += vals[t];
    }
    red[tid] = s;
    __syncthreads();
    for (int o = 128; o > 0; o >>= 1) {
        if (tid < o) red[tid] += red[tid + o];
        __syncthreads();
    }
    float mean = red[0] * (1.f / HH);
    __syncthreads();
    float s2 = 0.f;
#pragma unroll
    for (int t = 0; t < 6; t++) {
        float d = vals[t] - mean;
        s2 += d * d;
    }
    red[tid] = s2;
    __syncthreads();
    for (int o = 128; o > 0; o >>= 1) {
        if (tid < o) red[tid] += red[tid + o];
        __syncthreads();
    }
    float rstd = rsqrtf(red[0] * (1.f / HH) + 1e-12f);
#pragma unroll
    for (int t = 0; t < 6; t++) {
        int c = tid + t * 256;
        O[row * HH + c] = (vals[t] - mean) * rstd * gam[c] + bet[c];
    }
}

// ---------------- split max-pool + decoder ----------------
__global__ void maxpool_part(const float* __restrict__ L, float* __restrict__ pp) {
    int idx = blockIdx.x * blockDim.x + threadIdx.x;
    if (idx >= MB * 8 * HH) return;
    int c = idx % HH;
    int ch = (idx / HH) & 7;
    int b = idx / (HH * 8);
    const float* base = L + ((size_t)b * SS + ch * 128) * HH + c;
    float m = -3.4e38f;
    for (int s = 0; s < 128; s++) m = fmaxf(m, base[(size_t)s * HH]);
    pp[idx] = m;
}

__global__ void decode2(const float* __restrict__ pp, const float* __restrict__ wd,
                        const float* __restrict__ bd, float* __restrict__ out) {
    int b = blockIdx.x;
    int tid = threadIdx.x;
    __shared__ float red[256];
    float part = 0.f;
    for (int c = tid; c < HH; c += 256) {
        float m = pp[((size_t)b * 8) * HH + c];
#pragma unroll
        for (int ch = 1; ch < 8; ch++)
            m = fmaxf(m, pp[((size_t)b * 8 + ch) * HH + c]);
        part += m * wd[c];
    }
    red[tid] = part;
    __syncthreads();
    for (int o = 128; o > 0; o >>= 1) {
        if (tid < o) red[tid] += red[tid + o];
        __syncthreads();
    }
    if (tid == 0) out[b] = red[0] + bd[0];
}

// ============================================================================
// Host launcher — two-stream overlap via event fork/join
// ============================================================================
extern "C" void kernel_launch(void* const* d_in, const int* in_sizes, int n_in,
                              void* d_out, int out_size) {
    const float* embed = (const float*)d_in[0];
    const float* wq  = (const float*)d_in[1];  const float* bq  = (const float*)d_in[2];
    const float* wk  = (const float*)d_in[3];  const float* bk  = (const float*)d_in[4];
    const float* wv  = (const float*)d_in[5];  const float* bv  = (const float*)d_in[6];
    const float* dw  = (const float*)d_in[7];
    const float* pw  = (const float*)d_in[8];  const float* sep_b = (const float*)d_in[9];
    const float* wck = (const float*)d_in[10]; const float* bck = (const float*)d_in[11];
    const float* wco = (const float*)d_in[12]; const float* bco = (const float*)d_in[13];
    const float* wso = (const float*)d_in[14]; const float* bso = (const float*)d_in[15];
    const float* ln1_g = (const float*)d_in[16]; const float* ln1_b = (const float*)d_in[17];
    const float* wi  = (const float*)d_in[18]; const float* bi  = (const float*)d_in[19];
    const float* wo  = (const float*)d_in[20]; const float* bo  = (const float*)d_in[21];
    const float* ln2_g = (const float*)d_in[22]; const float* ln2_b = (const float*)d_in[23];
    const float* wd  = (const float*)d_in[24]; const float* bd  = (const float*)d_in[25];
    float* out = (float*)d_out;

    cudaFuncSetAttribute(mma_gemm, cudaFuncAttributeMaxDynamicSharedMemorySize, GEMM_SMEM);
    cudaFuncSetAttribute(mma_gemm_multi, cudaFuncAttributeMaxDynamicSharedMemorySize, GEMM_SMEM);
    cudaFuncSetAttribute(flash_attn, cudaFuncAttributeMaxDynamicSharedMemorySize, FL_SMEM);

    float *q, *k, *v, *co, *dconv, *sep, *ck, *ctx, *tmp, *inter, *attn, *layer, *poolp;
    cudaGetSymbolAddress((void**)&q, g_q);
    cudaGetSymbolAddress((void**)&k, g_k);
    cudaGetSymbolAddress((void**)&v, g_v);
    cudaGetSymbolAddress((void**)&co, g_co);
    cudaGetSymbolAddress((void**)&dconv, g_dconv);
    cudaGetSymbolAddress((void**)&sep, g_sep);
    cudaGetSymbolAddress((void**)&ck, g_ck);
    cudaGetSymbolAddress((void**)&ctx, g_ctx);
    cudaGetSymbolAddress((void**)&tmp, g_tmp);
    cudaGetSymbolAddress((void**)&inter, g_inter);
    cudaGetSymbolAddress((void**)&attn, g_attn);
    cudaGetSymbolAddress((void**)&layer, g_layer);
    cudaGetSymbolAddress((void**)&poolp, g_poolp);

    dim3 blk(256);
    cudaStream_t s0 = 0;             // default (capture) stream
    cudaStream_t s2 = g_si.s2;       // helper stream

    // ---- fork: s2 joins the capture ----
    cudaEventRecord(g_si.evF, s0);
    cudaStreamWaitEvent(s2, g_si.evF, 0);

    // s2: depthwise conv (needs only embed) — overlaps projections
    depthwise_conv8<<<((MROWS / 8) * HH + 255) / 256, blk, 0, s2>>>(embed, dw, dconv);

    // s0: fused q/k/v/co projections
    GemmSet sq = {wq, bq, q}, sk = {wk, bk, k}, sv = {wv, bv, v}, sc = {wco, bco, co};
    dim3 gm(AHd / 128, MROWS / 128, 4);
    mma_gemm_multi<<<gm, blk, GEMM_SMEM, s0>>>(embed, sq, sk, sv, sc, AHd, HH);
    cudaEventRecord(g_si.evA, s0);   // q,k,v,co ready

    // s2: pw gemm (needs dconv + q) -> ck (+softmax) -> span (needs co + ck)
    cudaStreamWaitEvent(s2, g_si.evA, 0);
    dim3 gproj(AHd / 128, MROWS / 128);
    mma_gemm<<<gproj, blk, GEMM_SMEM, s2>>>(dconv, pw, sep_b, sep, q, AHd, HH, 2);
    ck_gemm_sm<<<MROWS / 32, blk, 0, s2>>>(sep, wck, bck, ck);
    span_conv4<<<((MROWS / 4) * AHd + 255) / 256, blk, 0, s2>>>(co, ck, ctx);
    cudaEventRecord(g_si.evB, s2);

    // s0: flash attention (needs q,k,v; ordered after proj on s0)
    dim3 gfl(SS / 128, MB * NHh);
    flash_attn<<<gfl, blk, FL_SMEM, s0>>>(q, k, v, ctx);

    // join: wso needs full ctx (flash on s0 + span on s2)
    cudaStreamWaitEvent(s0, g_si.evB, 0);

    // ---- self output + LN1 ----
    dim3 gso(HH / 128, MROWS / 128);
    mma_gemm<<<gso, blk, GEMM_SMEM, s0>>>(ctx, wso, bso, tmp, nullptr, HH, HH, 0);
    ln_residual<<<MROWS, blk, 0, s0>>>(tmp, embed, ln1_g, ln1_b, attn);

    // ---- FFN ----
    dim3 gin(IM / 128, MROWS / 128);
    mma_gemm<<<gin, blk, GEMM_SMEM, s0>>>(attn, wi, bi, inter, nullptr, IM, HH, 1);
    mma_gemm<<<gso, blk, GEMM_SMEM, s0>>>(inter, wo, bo, tmp, nullptr, HH, IM, 0);
    ln_residual<<<MROWS, blk, 0, s0>>>(tmp, attn, ln2_g, ln2_b, layer);

    // ---- pool + decode ----
    maxpool_part<<<(MB * 8 * HH + 255) / 256, blk, 0, s0>>>(layer, poolp);
    decode2<<<MB, blk, 0, s0>>>(poolp, wd, bd, out);
}